// round 8
// baseline (speedup 1.0000x reference)
#include <cuda_runtime.h>
#include <cuda_bf16.h>
#include <math.h>
#include <stdint.h>

#define TOLC   0.01f
#define ALPHAC 0.1f
#define SLOPEC 0.01f
#define EPSC   1e-10f

#define NMAX 500096
__device__ float g_gradV[2 * NMAX];
__device__ float g_V[NMAX];
__device__ float g_fh[2 * NMAX];

__device__ __forceinline__ float sr(float x)  { return x < 0.f ? 0.f : (x < 1.f ? 0.5f * x * x : x - 0.5f); }
__device__ __forceinline__ float srp(float x) { return x < 0.f ? 0.f : (x < 1.f ? x : 1.f); }
__device__ __forceinline__ float srp_out(float z) { return z <= 0.f ? 0.f : (z < 0.5f ? sqrtf(2.f * z) : 1.f); }
__device__ __forceinline__ float lrelu(float x) { return x >= 0.f ? x : SLOPEC * x; }

__device__ __forceinline__ uint32_t packbf(float v0, float v1) {
    uint32_t r; asm("cvt.rn.bf16x2.f32 %0, %1, %2;" : "=r"(r) : "f"(v1), "f"(v0)); return r;
}
__device__ __forceinline__ float bf16rt(float v) {
    return __bfloat162float(__float2bfloat16(v));
}
__device__ __forceinline__ uint32_t smem_u32(const void* p) {
    uint32_t a;
    asm("{ .reg .u64 t; cvta.to.shared.u64 t, %1; cvt.u32.u64 %0, t; }" : "=r"(a) : "l"(p));
    return a;
}
__device__ __forceinline__ void ldsm4(uint32_t* r, uint32_t addr) {
    asm volatile("ldmatrix.sync.aligned.m8n8.x4.shared.b16 {%0,%1,%2,%3}, [%4];"
                 : "=r"(r[0]), "=r"(r[1]), "=r"(r[2]), "=r"(r[3]) : "r"(addr));
}
__device__ __forceinline__ void mma_bf16(float* c,
                                         uint32_t a0, uint32_t a1, uint32_t a2, uint32_t a3,
                                         uint32_t b0, uint32_t b1) {
    asm volatile("mma.sync.aligned.m16n8k16.row.col.f32.bf16.bf16.f32 "
                 "{%0,%1,%2,%3}, {%4,%5,%6,%7}, {%8,%9}, {%0,%1,%2,%3};"
                 : "+f"(c[0]), "+f"(c[1]), "+f"(c[2]), "+f"(c[3])
                 : "r"(a0), "r"(a1), "r"(a2), "r"(a3), "r"(b0), "r"(b1));
}

// ============================================================================
// Combined kernel: CTA-type by wave parity.
//   even wave -> fhat MLP CTA (tensor pipe), writes g_fh
//   odd  wave -> vnet CTA (FMA pipe), writes g_gradV / g_V
// Each SM hosts one CTA of each type -> cross-pipe overlap without
// intra-CTA phase serialization.
// ============================================================================
constexpr int TB = 256;
constexpr int SMCOUNT = 148;
constexpr int ZS = 65;                         // vnet padded stride (floats)
constexpr int ST = 136;                        // fhat bf16 row stride
constexpr int TILE_A = 128 * ST * 2;           // 34816 B
constexpr int TILE_W = 64 * ST * 2;            // 17408 B
constexpr int U_BYTES = 2 * TILE_A + 2 * TILE_W;   // 104448 (vnet uses 66560+)
constexpr int MISC = U_BYTES;
// fhat misc floats: sx[256] sb[128] sff[258] = 642
// vnet misc floats (separate CTAs, overlay): sd[128] sgf[64]
constexpr int MF_TOT = 642;
constexpr int SMEM_BYTES = MISC + MF_TOT * 4;  // 107016 < 113664 -> 2 CTAs/SM

__global__ __launch_bounds__(TB, 2)
void icnn_combined(const float* __restrict__ X,   const float* __restrict__ Xs,
                   const float* __restrict__ Vl1, const float* __restrict__ V2x,
                   const float* __restrict__ V2z, const float* __restrict__ V3x,
                   const float* __restrict__ V3z, const float* __restrict__ Vfx,
                   const float* __restrict__ Vfz,
                   const float* __restrict__ f1w, const float* __restrict__ f1b,
                   const float* __restrict__ f2w, const float* __restrict__ f2b,
                   const float* __restrict__ f3w, const float* __restrict__ f3b,
                   const float* __restrict__ f4w, const float* __restrict__ f4b,
                   const float* __restrict__ f5w, const float* __restrict__ f5b,
                   const float* __restrict__ ffw, const float* __restrict__ ffb,
                   int n, int nblk)
{
    extern __shared__ __align__(16) char smb[];
    const int t    = threadIdx.x;
    const int w    = blockIdx.x / SMCOUNT;
    const int r    = blockIdx.x % SMCOUNT;
    const int idx  = (w >> 1) * SMCOUNT + r;
    if (idx >= nblk) return;

    const int ty = t >> 4;
    const int tx = t & 15;
    float* mf = (float*)(smb + MISC);

    if (w & 1) {
        // ====================================================================
        // vnet CTA: 128 points, two 64-point sub-passes (SIMT fp32)
        // ====================================================================
        float* sz1 = (float*)smb;
        float* sz2 = sz1 + 64 * ZS;
        float* sz3 = sz1 + 128 * ZS;
        float* sW  = sz1 + 192 * ZS;
        float* sd  = mf;          // 128
        float* sgf = mf + 128;    // 64

        for (int sub = 0; sub < 2; sub++) {
            const int base = idx * 128 + sub * 64;

            for (int i = t; i < 128; i += TB) {
                int gi = base + (i >> 1); if (gi >= n) gi = n - 1;
                sd[i] = X[gi * 2 + (i & 1)] - Xs[gi * 2 + (i & 1)];
            }
            __syncthreads();

            for (int i = t; i < 64 * 64; i += TB) {
                int p = i >> 6, j = i & 63;
                float a = sd[p * 2] * Vl1[j * 2] + sd[p * 2 + 1] * Vl1[j * 2 + 1];
                sz1[p * ZS + j] = sr(a);
            }
            for (int i = t; i < 64 * 64; i += TB) sW[(i >> 6) * ZS + (i & 63)] = V2z[i];
            __syncthreads();

            {   // z2
                float acc[4][4];
                #pragma unroll
                for (int pi = 0; pi < 4; pi++) {
                    int p = ty + 16 * pi;
                    #pragma unroll
                    for (int ji = 0; ji < 4; ji++) {
                        int j = tx + 16 * ji;
                        acc[pi][ji] = sd[p * 2] * V2x[j * 2] + sd[p * 2 + 1] * V2x[j * 2 + 1];
                    }
                }
                #pragma unroll 4
                for (int k = 0; k < 64; k++) {
                    float a[4], wv[4];
                    #pragma unroll
                    for (int pi = 0; pi < 4; pi++) a[pi] = sz1[(ty + 16 * pi) * ZS + k];
                    #pragma unroll
                    for (int ji = 0; ji < 4; ji++) wv[ji] = sW[(tx + 16 * ji) * ZS + k];
                    #pragma unroll
                    for (int pi = 0; pi < 4; pi++)
                        #pragma unroll
                        for (int ji = 0; ji < 4; ji++) acc[pi][ji] += a[pi] * wv[ji];
                }
                #pragma unroll
                for (int pi = 0; pi < 4; pi++)
                    #pragma unroll
                    for (int ji = 0; ji < 4; ji++)
                        sz2[(ty + 16 * pi) * ZS + tx + 16 * ji] = sr(acc[pi][ji]);
            }
            __syncthreads();
            for (int i = t; i < 64 * 64; i += TB) sW[(i >> 6) * ZS + (i & 63)] = V3z[i];
            __syncthreads();

            {   // z3
                float acc[4][4];
                #pragma unroll
                for (int pi = 0; pi < 4; pi++) {
                    int p = ty + 16 * pi;
                    #pragma unroll
                    for (int ji = 0; ji < 4; ji++) {
                        int j = tx + 16 * ji;
                        acc[pi][ji] = sd[p * 2] * V3x[j * 2] + sd[p * 2 + 1] * V3x[j * 2 + 1];
                    }
                }
                #pragma unroll 4
                for (int k = 0; k < 64; k++) {
                    float a[4], wv[4];
                    #pragma unroll
                    for (int pi = 0; pi < 4; pi++) a[pi] = sz2[(ty + 16 * pi) * ZS + k];
                    #pragma unroll
                    for (int ji = 0; ji < 4; ji++) wv[ji] = sW[(tx + 16 * ji) * ZS + k];
                    #pragma unroll
                    for (int pi = 0; pi < 4; pi++)
                        #pragma unroll
                        for (int ji = 0; ji < 4; ji++) acc[pi][ji] += a[pi] * wv[ji];
                }
                #pragma unroll
                for (int pi = 0; pi < 4; pi++)
                    #pragma unroll
                    for (int ji = 0; ji < 4; ji++)
                        sz3[(ty + 16 * pi) * ZS + tx + 16 * ji] = sr(acc[pi][ji]);
            }
            __syncthreads();

            if (t < 64) {
                int p = t;
                float af = sd[p * 2] * Vfx[0] + sd[p * 2 + 1] * Vfx[1];
                #pragma unroll 4
                for (int k = 0; k < 64; k++) af += Vfz[k] * sz3[p * ZS + k];
                float zf = sr(af);
                sgf[p] = srp(zf) * srp(af);
                int gi = base + p;
                if (gi < n)
                    g_V[gi] = sr(zf) + TOLC * (sd[p * 2] * sd[p * 2] + sd[p * 2 + 1] * sd[p * 2 + 1]);
            }
            __syncthreads();

            for (int i = t; i < 64 * 64; i += TB) {
                int p = i >> 6, j = i & 63;
                float z = sz3[p * ZS + j];
                sz3[p * ZS + j] = sgf[p] * Vfz[j] * srp_out(z);
            }
            __syncthreads();

            {   // g_a2 (sW holds V3z)
                float acc[4][4] = {};
                #pragma unroll 4
                for (int k = 0; k < 64; k++) {
                    float a[4], wv[4];
                    #pragma unroll
                    for (int pi = 0; pi < 4; pi++) a[pi] = sz3[(ty + 16 * pi) * ZS + k];
                    #pragma unroll
                    for (int ji = 0; ji < 4; ji++) wv[ji] = sW[k * ZS + tx + 16 * ji];
                    #pragma unroll
                    for (int pi = 0; pi < 4; pi++)
                        #pragma unroll
                        for (int ji = 0; ji < 4; ji++) acc[pi][ji] += a[pi] * wv[ji];
                }
                #pragma unroll
                for (int pi = 0; pi < 4; pi++)
                    #pragma unroll
                    for (int ji = 0; ji < 4; ji++) {
                        int p = ty + 16 * pi, j = tx + 16 * ji;
                        float z = sz2[p * ZS + j];
                        sz2[p * ZS + j] = acc[pi][ji] * srp_out(z);
                    }
            }
            __syncthreads();
            for (int i = t; i < 64 * 64; i += TB) sW[(i >> 6) * ZS + (i & 63)] = V2z[i];
            __syncthreads();

            {   // g_a1
                float acc[4][4] = {};
                #pragma unroll 4
                for (int k = 0; k < 64; k++) {
                    float a[4], wv[4];
                    #pragma unroll
                    for (int pi = 0; pi < 4; pi++) a[pi] = sz2[(ty + 16 * pi) * ZS + k];
                    #pragma unroll
                    for (int ji = 0; ji < 4; ji++) wv[ji] = sW[k * ZS + tx + 16 * ji];
                    #pragma unroll
                    for (int pi = 0; pi < 4; pi++)
                        #pragma unroll
                        for (int ji = 0; ji < 4; ji++) acc[pi][ji] += a[pi] * wv[ji];
                }
                #pragma unroll
                for (int pi = 0; pi < 4; pi++)
                    #pragma unroll
                    for (int ji = 0; ji < 4; ji++) {
                        int p = ty + 16 * pi, j = tx + 16 * ji;
                        float z = sz1[p * ZS + j];
                        sz1[p * ZS + j] = acc[pi][ji] * srp_out(z);
                    }
            }
            __syncthreads();

            if (t < 128) {
                int p = t >> 1, c = t & 1;
                float acc = sgf[p] * Vfx[c] + 2.f * TOLC * sd[p * 2 + c];
                #pragma unroll 4
                for (int k = 0; k < 64; k++) {
                    acc += sz3[p * ZS + k] * V3x[k * 2 + c];
                    acc += sz2[p * ZS + k] * V2x[k * 2 + c];
                    acc += sz1[p * ZS + k] * Vl1[k * 2 + c];
                }
                int gi = base + p;
                if (gi < n) g_gradV[gi * 2 + c] = acc;
            }
            __syncthreads();
        }
        return;
    }

    // ========================================================================
    // fhat CTA: 128 points, 2x-bf16 mma.sync MLP -> g_fh
    // ========================================================================
    __nv_bfloat16* Ahi = (__nv_bfloat16*)smb;
    __nv_bfloat16* Alo = (__nv_bfloat16*)(smb + TILE_A);
    __nv_bfloat16* Whi = (__nv_bfloat16*)(smb + 2 * TILE_A);
    __nv_bfloat16* Wlo = (__nv_bfloat16*)(smb + 2 * TILE_A + TILE_W);
    float* sx  = mf;            // 256
    float* sb  = mf + 256;      // 128
    float* sff = mf + 384;      // 258

    const int wid  = t >> 5;
    const int lane = t & 31;
    const int gid  = lane >> 2;
    const int tig  = lane & 3;
    const int r0   = wid * 16;
    const int base = idx * 128;

    const int aRow = r0 + (lane & 7) + ((lane >> 3) & 1) * 8;
    const int aCol = ((lane >> 4) & 1) * 8;
    const uint32_t aOff = (uint32_t)(aRow * ST + aCol) * 2;
    const int bRow = (lane & 7) + ((lane >> 4) & 1) * 8;
    const int bCol = ((lane >> 3) & 1) * 8;
    const uint32_t bOff = (uint32_t)(bRow * ST + bCol) * 2;

    const uint32_t aHiB = smem_u32(Ahi) + aOff;
    const uint32_t aLoB = smem_u32(Alo) + aOff;
    const uint32_t wHiB = smem_u32(Whi) + bOff;
    const uint32_t wLoB = smem_u32(Wlo) + bOff;

    {
        int p = t >> 1, c = t & 1;
        int gi = base + p; if (gi >= n) gi = n - 1;
        sx[t] = X[gi * 2 + c];
    }
    for (int i = t; i < 258; i += TB) sff[i] = (i < 256) ? ffw[i] : ffb[i - 256];
    __syncthreads();

    for (int i = t; i < 128 * 128; i += TB) {
        int p = i >> 7, j = i & 127;
        float v  = lrelu(sx[2 * p] * f1w[2 * j] + sx[2 * p + 1] * f1w[2 * j + 1] + f1b[j]);
        float h  = bf16rt(v);
        Ahi[p * ST + j] = __float2bfloat16(v);
        Alo[p * ST + j] = __float2bfloat16(v - h);
    }
    __syncthreads();

    const float* Ws[4] = { f2w, f3w, f4w, f5w };
    const float* Bs[4] = { f2b, f3b, f4b, f5b };

    for (int L = 0; L < 4; L++) {
        const float* Wg = Ws[L];
        float acc[16][4];
        #pragma unroll
        for (int q = 0; q < 16; q++)
            #pragma unroll
            for (int c = 0; c < 4; c++) acc[q][c] = 0.f;

        #pragma unroll 1
        for (int half = 0; half < 2; half++) {
            for (int i = t; i < 64 * 32; i += TB) {
                int j  = i >> 5;
                int k4 = (i & 31) << 2;
                float4 wv = *(const float4*)(Wg + (half * 64 + j) * 128 + k4);
                float h0 = bf16rt(wv.x), h1 = bf16rt(wv.y), h2 = bf16rt(wv.z), h3 = bf16rt(wv.w);
                *(uint2*)(Whi + j * ST + k4) = make_uint2(packbf(wv.x, wv.y), packbf(wv.z, wv.w));
                *(uint2*)(Wlo + j * ST + k4) =
                    make_uint2(packbf(wv.x - h0, wv.y - h1), packbf(wv.z - h2, wv.w - h3));
            }
            if (half == 0 && t < 128) sb[t] = Bs[L][t];
            __syncthreads();

            #pragma unroll
            for (int kt = 0; kt < 8; kt++) {
                const uint32_t kb = kt * 32;
                uint32_t ah[4], al[4];
                ldsm4(ah, aHiB + kb);
                ldsm4(al, aLoB + kb);
                #pragma unroll
                for (int p = 0; p < 4; p++) {
                    uint32_t bh[4], bl[4];
                    const uint32_t po = (uint32_t)(p * 16 * ST * 2) + kb;
                    ldsm4(bh, wHiB + po);
                    ldsm4(bl, wLoB + po);
                    float* c0 = acc[half * 8 + 2 * p];
                    float* c1 = acc[half * 8 + 2 * p + 1];
                    mma_bf16(c0, ah[0], ah[1], ah[2], ah[3], bh[0], bh[1]);
                    mma_bf16(c0, ah[0], ah[1], ah[2], ah[3], bl[0], bl[1]);
                    mma_bf16(c0, al[0], al[1], al[2], al[3], bh[0], bh[1]);
                    mma_bf16(c1, ah[0], ah[1], ah[2], ah[3], bh[2], bh[3]);
                    mma_bf16(c1, ah[0], ah[1], ah[2], ah[3], bl[2], bl[3]);
                    mma_bf16(c1, al[0], al[1], al[2], al[3], bh[2], bh[3]);
                }
            }
            __syncthreads();
        }

        if (L < 3) {
            #pragma unroll
            for (int q = 0; q < 16; q++) {
                int c = (q >> 3) * 64 + (q & 7) * 8 + 2 * tig;
                float v0 = lrelu(acc[q][0] + sb[c]);
                float v1 = lrelu(acc[q][1] + sb[c + 1]);
                float v2 = lrelu(acc[q][2] + sb[c]);
                float v3 = lrelu(acc[q][3] + sb[c + 1]);
                float h0 = bf16rt(v0), h1 = bf16rt(v1), h2 = bf16rt(v2), h3 = bf16rt(v3);
                *(uint32_t*)(Ahi + (r0 + gid) * ST + c)     = packbf(v0, v1);
                *(uint32_t*)(Ahi + (r0 + gid + 8) * ST + c) = packbf(v2, v3);
                *(uint32_t*)(Alo + (r0 + gid) * ST + c)     = packbf(v0 - h0, v1 - h1);
                *(uint32_t*)(Alo + (r0 + gid + 8) * ST + c) = packbf(v2 - h2, v3 - h3);
            }
            __syncthreads();
        } else {
            float p0 = 0.f, p1 = 0.f, q0 = 0.f, q1 = 0.f;
            #pragma unroll
            for (int q = 0; q < 16; q++) {
                int c = (q >> 3) * 64 + (q & 7) * 8 + 2 * tig;
                float v0 = lrelu(acc[q][0] + sb[c]);
                float v1 = lrelu(acc[q][1] + sb[c + 1]);
                float v2 = lrelu(acc[q][2] + sb[c]);
                float v3 = lrelu(acc[q][3] + sb[c + 1]);
                p0 = fmaf(v0, sff[c], fmaf(v1, sff[c + 1], p0));
                p1 = fmaf(v0, sff[128 + c], fmaf(v1, sff[129 + c], p1));
                q0 = fmaf(v2, sff[c], fmaf(v3, sff[c + 1], q0));
                q1 = fmaf(v2, sff[128 + c], fmaf(v3, sff[129 + c], q1));
            }
            #pragma unroll
            for (int m = 1; m < 4; m <<= 1) {
                p0 += __shfl_xor_sync(0xFFFFFFFFu, p0, m);
                p1 += __shfl_xor_sync(0xFFFFFFFFu, p1, m);
                q0 += __shfl_xor_sync(0xFFFFFFFFu, q0, m);
                q1 += __shfl_xor_sync(0xFFFFFFFFu, q1, m);
            }
            if (tig == 0) {
                int gi0 = base + r0 + gid;
                int gi1 = base + r0 + gid + 8;
                if (gi0 < n) { g_fh[2 * gi0] = sff[256] + p0; g_fh[2 * gi0 + 1] = sff[257] + p1; }
                if (gi1 < n) { g_fh[2 * gi1] = sff[256] + q0; g_fh[2 * gi1 + 1] = sff[257] + q1; }
            }
        }
    }
}

// ============================================================================
// Projection kernel: out = fh - gradV * relu(fh.g + alpha*V) / (|g|^2 + eps)
// ============================================================================
__global__ void proj_kernel(float* __restrict__ out, int n)
{
    int i = blockIdx.x * blockDim.x + threadIdx.x;
    if (i < n) {
        float fh0 = g_fh[2 * i], fh1 = g_fh[2 * i + 1];
        float g0 = g_gradV[2 * i], g1 = g_gradV[2 * i + 1];
        float V  = g_V[i];
        float vn  = g0 * g0 + g1 * g1;
        float num = fh0 * g0 + fh1 * g1 + ALPHAC * V;
        float fm  = (num > 0.f ? num : 0.f) / (vn + EPSC);
        out[2 * i]     = fh0 - g0 * fm;
        out[2 * i + 1] = fh1 - g1 * fm;
    }
}

// ============================================================================
extern "C" void kernel_launch(void* const* d_in, const int* in_sizes, int n_in,
                              void* d_out, int out_size)
{
    const float* X   = (const float*)d_in[0];
    const float* Xs  = (const float*)d_in[1];
    const float* Vl1 = (const float*)d_in[2];
    const float* V2x = (const float*)d_in[3];
    const float* V2z = (const float*)d_in[4];
    const float* V3x = (const float*)d_in[5];
    const float* V3z = (const float*)d_in[6];
    const float* Vfx = (const float*)d_in[7];
    const float* Vfz = (const float*)d_in[8];
    const float* f1w = (const float*)d_in[9];
    const float* f1b = (const float*)d_in[10];
    const float* f2w = (const float*)d_in[11];
    const float* f2b = (const float*)d_in[12];
    const float* f3w = (const float*)d_in[13];
    const float* f3b = (const float*)d_in[14];
    const float* f4w = (const float*)d_in[15];
    const float* f4b = (const float*)d_in[16];
    const float* f5w = (const float*)d_in[17];
    const float* f5b = (const float*)d_in[18];
    const float* ffw = (const float*)d_in[19];
    const float* ffb = (const float*)d_in[20];

    int n = in_sizes[0] / 2;
    int nblk = (n + 127) / 128;                          // CTAs per type
    int waves = (nblk + SMCOUNT - 1) / SMCOUNT;          // waves per type
    int grid = 2 * waves * SMCOUNT;

    cudaFuncSetAttribute(icnn_combined, cudaFuncAttributeMaxDynamicSharedMemorySize, SMEM_BYTES);

    icnn_combined<<<grid, TB, SMEM_BYTES>>>(
        X, Xs, Vl1, V2x, V2z, V3x, V3z, Vfx, Vfz,
        f1w, f1b, f2w, f2b, f3w, f3b, f4w, f4b, f5w, f5b, ffw, ffb,
        n, nblk);

    proj_kernel<<<(n + 255) / 256, 256>>>((float*)d_out, n);
}

// round 9
// speedup vs baseline: 1.5762x; 1.5762x over previous
#include <cuda_runtime.h>
#include <cuda_bf16.h>
#include <math.h>
#include <stdint.h>

#define TOLC   0.01f
#define ALPHAC 0.1f
#define SLOPEC 0.01f
#define EPSC   1e-10f

#define NMAX 500096
__device__ float g_gradV[2 * NMAX];
__device__ float g_V[NMAX];
__device__ __nv_bfloat16 g_fWh[4 * 16384], g_fWl[4 * 16384];   // f2..f5 hi/lo
__device__ __nv_bfloat16 g_vWh[8192],      g_vWl[8192];        // V2z,V3z hi/lo

__device__ __forceinline__ float sr(float x)  { return x < 0.f ? 0.f : (x < 1.f ? 0.5f * x * x : x - 0.5f); }
__device__ __forceinline__ float srp(float x) { return x < 0.f ? 0.f : (x < 1.f ? x : 1.f); }
__device__ __forceinline__ float srp_out(float z) { return z <= 0.f ? 0.f : (z < 0.5f ? sqrtf(2.f * z) : 1.f); }
__device__ __forceinline__ float lrelu(float x) { return x >= 0.f ? x : SLOPEC * x; }

__device__ __forceinline__ uint32_t packbf(float v0, float v1) {
    uint32_t r; asm("cvt.rn.bf16x2.f32 %0, %1, %2;" : "=r"(r) : "f"(v1), "f"(v0)); return r;
}
__device__ __forceinline__ float bf16rt(float v) {
    return __bfloat162float(__float2bfloat16(v));
}
__device__ __forceinline__ uint32_t smem_u32(const void* p) {
    uint32_t a;
    asm("{ .reg .u64 t; cvta.to.shared.u64 t, %1; cvt.u32.u64 %0, t; }" : "=r"(a) : "l"(p));
    return a;
}
__device__ __forceinline__ void ldsm4(uint32_t* r, uint32_t addr) {
    asm volatile("ldmatrix.sync.aligned.m8n8.x4.shared.b16 {%0,%1,%2,%3}, [%4];"
                 : "=r"(r[0]), "=r"(r[1]), "=r"(r[2]), "=r"(r[3]) : "r"(addr));
}
__device__ __forceinline__ void ldsm4t(uint32_t* r, uint32_t addr) {
    asm volatile("ldmatrix.sync.aligned.m8n8.x4.trans.shared.b16 {%0,%1,%2,%3}, [%4];"
                 : "=r"(r[0]), "=r"(r[1]), "=r"(r[2]), "=r"(r[3]) : "r"(addr));
}
__device__ __forceinline__ void mma_bf16(float* c,
                                         uint32_t a0, uint32_t a1, uint32_t a2, uint32_t a3,
                                         uint32_t b0, uint32_t b1) {
    asm volatile("mma.sync.aligned.m16n8k16.row.col.f32.bf16.bf16.f32 "
                 "{%0,%1,%2,%3}, {%4,%5,%6,%7}, {%8,%9}, {%0,%1,%2,%3};"
                 : "+f"(c[0]), "+f"(c[1]), "+f"(c[2]), "+f"(c[3])
                 : "r"(a0), "r"(a1), "r"(a2), "r"(a3), "r"(b0), "r"(b1));
}

// ============================================================================
// Setup: pre-split weights into bf16 hi/lo globals
// ============================================================================
__global__ void setup_w(const float* __restrict__ f2w, const float* __restrict__ f3w,
                        const float* __restrict__ f4w, const float* __restrict__ f5w,
                        const float* __restrict__ V2z, const float* __restrict__ V3z)
{
    int i = blockIdx.x * blockDim.x + threadIdx.x;
    if (i < 65536) {
        const float* W = (i < 32768) ? ((i < 16384) ? f2w : f3w)
                                     : ((i < 49152) ? f4w : f5w);
        float v = W[i & 16383];
        float h = bf16rt(v);
        g_fWh[i] = __float2bfloat16(v);
        g_fWl[i] = __float2bfloat16(v - h);
    } else if (i < 73728) {
        int j = i - 65536;
        float v = (j < 4096) ? V2z[j] : V3z[j - 4096];
        float h = bf16rt(v);
        g_vWh[j] = __float2bfloat16(v);
        g_vWl[j] = __float2bfloat16(v - h);
    }
}

// ============================================================================
// Kernel A: ICNN V network + VJP via 2x-bf16 mma.sync (fwd + trans-bwd GEMMs)
// ============================================================================
constexpr int SZB = 144;                 // row stride bytes (72 bf16)
constexpr int VT  = 128 * SZB;           // 18432 B per 128x64 tile
constexpr int VW  = 64 * SZB;            // 9216 B per 64x64 W tile
constexpr int V_AHI = 0, V_ALO = VT, V_BHI = 2 * VT, V_BLO = 3 * VT;
constexpr int V_W2H = 4 * VT, V_W2L = V_W2H + VW, V_W3H = V_W2H + 2 * VW, V_W3L = V_W2H + 3 * VW;
constexpr int V_MISC = V_W2H + 4 * VW;   // 110592
// misc floats: sd[256] sVfz[64] sV2x[128] sV3x[128] sVl1[128] = 704
constexpr int SMEMV_BYTES = V_MISC + 704 * 4;  // 113408

template<bool TR>
__device__ __forceinline__ void gemm64(float (&acc)[8][4], uint32_t aHi, uint32_t aLo,
                                       uint32_t wHi, uint32_t wLo)
{
    #pragma unroll
    for (int kt = 0; kt < 4; kt++) {
        uint32_t ah[4], al[4];
        ldsm4(ah, aHi + kt * 32);
        ldsm4(al, aLo + kt * 32);
        #pragma unroll
        for (int p = 0; p < 4; p++) {
            uint32_t off = TR ? (uint32_t)(kt * 16 * SZB + p * 32)
                              : (uint32_t)(p * 16 * SZB + kt * 32);
            uint32_t bh[4], bl[4];
            if (TR) { ldsm4t(bh, wHi + off); ldsm4t(bl, wLo + off); }
            else    { ldsm4 (bh, wHi + off); ldsm4 (bl, wLo + off); }
            float* c0 = acc[2 * p];
            float* c1 = acc[2 * p + 1];
            mma_bf16(c0, ah[0], ah[1], ah[2], ah[3], bh[0], bh[1]);
            mma_bf16(c0, ah[0], ah[1], ah[2], ah[3], bl[0], bl[1]);
            mma_bf16(c0, al[0], al[1], al[2], al[3], bh[0], bh[1]);
            mma_bf16(c1, ah[0], ah[1], ah[2], ah[3], bh[2], bh[3]);
            mma_bf16(c1, ah[0], ah[1], ah[2], ah[3], bl[2], bl[3]);
            mma_bf16(c1, al[0], al[1], al[2], al[3], bh[2], bh[3]);
        }
    }
}

__global__ __launch_bounds__(256, 2)
void vnet_mma(const float* __restrict__ X,   const float* __restrict__ Xs,
              const float* __restrict__ Vl1, const float* __restrict__ V2x,
              const float* __restrict__ V3x, const float* __restrict__ Vfx,
              const float* __restrict__ Vfz, int n)
{
    extern __shared__ __align__(16) char smb[];
    float* mf   = (float*)(smb + V_MISC);
    float* sd   = mf;
    float* sVfz = mf + 256;
    float* sV2x = mf + 320;
    float* sV3x = mf + 448;
    float* sVl1 = mf + 576;

    const int t    = threadIdx.x;
    const int wid  = t >> 5;
    const int lane = t & 31;
    const int gid  = lane >> 2;
    const int tig  = lane & 3;
    const int r0   = wid * 16;
    const int base = blockIdx.x * 128;
    const int rA = r0 + gid, rB = rA + 8;

    {   // stage d + small vectors
        int p = t >> 1, c = t & 1;
        int gi = base + p; if (gi >= n) gi = n - 1;
        sd[t] = X[gi * 2 + c] - Xs[gi * 2 + c];
    }
    if (t < 64)  sVfz[t] = Vfz[t];
    if (t < 128) { sV2x[t] = V2x[t]; sV3x[t] = V3x[t]; sVl1[t] = Vl1[t]; }
    // stage W tiles from pre-split globals (64 rows x 8 x 16B each)
    for (int i = t; i < 512; i += 256) {
        int row = i >> 3, ch = (i & 7) * 8;
        *(uint4*)(smb + V_W2H + row * SZB + ch * 2) = *(const uint4*)(g_vWh + row * 64 + ch);
        *(uint4*)(smb + V_W2L + row * SZB + ch * 2) = *(const uint4*)(g_vWl + row * 64 + ch);
        *(uint4*)(smb + V_W3H + row * SZB + ch * 2) = *(const uint4*)(g_vWh + 4096 + row * 64 + ch);
        *(uint4*)(smb + V_W3L + row * SZB + ch * 2) = *(const uint4*)(g_vWl + 4096 + row * 64 + ch);
    }
    __syncthreads();

    // z1 = sr(d @ Vl1^T) -> A tile (hi/lo)
    for (int i = t; i < 8192; i += 256) {
        int p = i >> 6, j = i & 63;
        float v = sr(sd[2 * p] * sVl1[2 * j] + sd[2 * p + 1] * sVl1[2 * j + 1]);
        float h = bf16rt(v);
        *(__nv_bfloat16*)(smb + V_AHI + p * SZB + 2 * j) = __float2bfloat16(v);
        *(__nv_bfloat16*)(smb + V_ALO + p * SZB + 2 * j) = __float2bfloat16(v - h);
    }
    __syncthreads();

    const uint32_t su   = smem_u32(smb);
    const uint32_t aoff = (uint32_t)((r0 + (lane & 7) + ((lane >> 3) & 1) * 8) * SZB
                                     + ((lane >> 4) & 1) * 16);
    const uint32_t wf   = (uint32_t)(((lane & 7) + ((lane >> 4) & 1) * 8) * SZB
                                     + ((lane >> 3) & 1) * 16);
    const uint32_t wt   = (uint32_t)(((lane & 7) + ((lane >> 3) & 1) * 8) * SZB
                                     + ((lane >> 4) & 1) * 16);

    const float dA0 = sd[2 * rA], dA1 = sd[2 * rA + 1];
    const float dB0 = sd[2 * rB], dB1 = sd[2 * rB + 1];
    float acc[8][4];

    // ---- z2 = sr(d@V2x^T + z1@V2z^T) -> B tile ----
    #pragma unroll
    for (int q = 0; q < 8; q++) { acc[q][0] = acc[q][1] = acc[q][2] = acc[q][3] = 0.f; }
    gemm64<false>(acc, su + V_AHI + aoff, su + V_ALO + aoff, su + V_W2H + wf, su + V_W2L + wf);
    #pragma unroll
    for (int q = 0; q < 8; q++) {
        int c = q * 8 + 2 * tig;
        float v0 = sr(acc[q][0] + dA0 * sV2x[2 * c]     + dA1 * sV2x[2 * c + 1]);
        float v1 = sr(acc[q][1] + dA0 * sV2x[2 * c + 2] + dA1 * sV2x[2 * c + 3]);
        float v2 = sr(acc[q][2] + dB0 * sV2x[2 * c]     + dB1 * sV2x[2 * c + 1]);
        float v3 = sr(acc[q][3] + dB0 * sV2x[2 * c + 2] + dB1 * sV2x[2 * c + 3]);
        *(uint32_t*)(smb + V_BHI + rA * SZB + 2 * c) = packbf(v0, v1);
        *(uint32_t*)(smb + V_BLO + rA * SZB + 2 * c) = packbf(v0 - bf16rt(v0), v1 - bf16rt(v1));
        *(uint32_t*)(smb + V_BHI + rB * SZB + 2 * c) = packbf(v2, v3);
        *(uint32_t*)(smb + V_BLO + rB * SZB + 2 * c) = packbf(v2 - bf16rt(v2), v3 - bf16rt(v3));
    }
    __syncthreads();

    // ---- z3 (regs) + zf/gf/V + g3 -> A tile ----
    #pragma unroll
    for (int q = 0; q < 8; q++) { acc[q][0] = acc[q][1] = acc[q][2] = acc[q][3] = 0.f; }
    gemm64<false>(acc, su + V_BHI + aoff, su + V_BLO + aoff, su + V_W3H + wf, su + V_W3L + wf);
    float zfA = 0.f, zfB = 0.f;
    #pragma unroll
    for (int q = 0; q < 8; q++) {
        int c = q * 8 + 2 * tig;
        acc[q][0] = sr(acc[q][0] + dA0 * sV3x[2 * c]     + dA1 * sV3x[2 * c + 1]);
        acc[q][1] = sr(acc[q][1] + dA0 * sV3x[2 * c + 2] + dA1 * sV3x[2 * c + 3]);
        acc[q][2] = sr(acc[q][2] + dB0 * sV3x[2 * c]     + dB1 * sV3x[2 * c + 1]);
        acc[q][3] = sr(acc[q][3] + dB0 * sV3x[2 * c + 2] + dB1 * sV3x[2 * c + 3]);
        zfA += sVfz[c] * acc[q][0] + sVfz[c + 1] * acc[q][1];
        zfB += sVfz[c] * acc[q][2] + sVfz[c + 1] * acc[q][3];
    }
    zfA += __shfl_xor_sync(0xFFFFFFFFu, zfA, 1);
    zfA += __shfl_xor_sync(0xFFFFFFFFu, zfA, 2);
    zfB += __shfl_xor_sync(0xFFFFFFFFu, zfB, 1);
    zfB += __shfl_xor_sync(0xFFFFFFFFu, zfB, 2);
    const float vfx0 = Vfx[0], vfx1 = Vfx[1];
    float afA = zfA + dA0 * vfx0 + dA1 * vfx1;
    float afB = zfB + dB0 * vfx0 + dB1 * vfx1;
    float zA = sr(afA), zB = sr(afB);
    float gfA = srp(zA) * srp(afA);
    float gfB = srp(zB) * srp(afB);
    if (tig == 0) {
        int gA = base + rA, gB = base + rB;
        if (gA < n) g_V[gA] = sr(zA) + TOLC * (dA0 * dA0 + dA1 * dA1);
        if (gB < n) g_V[gB] = sr(zB) + TOLC * (dB0 * dB0 + dB1 * dB1);
    }
    float gvA0 = 0.f, gvA1 = 0.f, gvB0 = 0.f, gvB1 = 0.f;
    #pragma unroll
    for (int q = 0; q < 8; q++) {
        int c = q * 8 + 2 * tig;
        float g0 = gfA * sVfz[c]     * srp_out(acc[q][0]);
        float g1 = gfA * sVfz[c + 1] * srp_out(acc[q][1]);
        float g2 = gfB * sVfz[c]     * srp_out(acc[q][2]);
        float g3 = gfB * sVfz[c + 1] * srp_out(acc[q][3]);
        gvA0 += g0 * sV3x[2 * c]     + g1 * sV3x[2 * c + 2];
        gvA1 += g0 * sV3x[2 * c + 1] + g1 * sV3x[2 * c + 3];
        gvB0 += g2 * sV3x[2 * c]     + g3 * sV3x[2 * c + 2];
        gvB1 += g2 * sV3x[2 * c + 1] + g3 * sV3x[2 * c + 3];
        *(uint32_t*)(smb + V_AHI + rA * SZB + 2 * c) = packbf(g0, g1);
        *(uint32_t*)(smb + V_ALO + rA * SZB + 2 * c) = packbf(g0 - bf16rt(g0), g1 - bf16rt(g1));
        *(uint32_t*)(smb + V_AHI + rB * SZB + 2 * c) = packbf(g2, g3);
        *(uint32_t*)(smb + V_ALO + rB * SZB + 2 * c) = packbf(g2 - bf16rt(g2), g3 - bf16rt(g3));
    }
    __syncthreads();

    // ---- g2 = (g3 @ V3z) * srp(z2) : A tile x trans(V3z); in-place over B ----
    #pragma unroll
    for (int q = 0; q < 8; q++) { acc[q][0] = acc[q][1] = acc[q][2] = acc[q][3] = 0.f; }
    gemm64<true>(acc, su + V_AHI + aoff, su + V_ALO + aoff, su + V_W3H + wt, su + V_W3L + wt);
    #pragma unroll
    for (int q = 0; q < 8; q++) {
        int c = q * 8 + 2 * tig;
        uint32_t hA = *(uint32_t*)(smb + V_BHI + rA * SZB + 2 * c);
        uint32_t lA = *(uint32_t*)(smb + V_BLO + rA * SZB + 2 * c);
        uint32_t hB = *(uint32_t*)(smb + V_BHI + rB * SZB + 2 * c);
        uint32_t lB = *(uint32_t*)(smb + V_BLO + rB * SZB + 2 * c);
        float z0 = __uint_as_float(hA << 16) + __uint_as_float(lA << 16);
        float z1v = __uint_as_float(hA & 0xFFFF0000u) + __uint_as_float(lA & 0xFFFF0000u);
        float z2v = __uint_as_float(hB << 16) + __uint_as_float(lB << 16);
        float z3v = __uint_as_float(hB & 0xFFFF0000u) + __uint_as_float(lB & 0xFFFF0000u);
        float v0 = acc[q][0] * srp_out(z0);
        float v1 = acc[q][1] * srp_out(z1v);
        float v2 = acc[q][2] * srp_out(z2v);
        float v3 = acc[q][3] * srp_out(z3v);
        gvA0 += v0 * sV2x[2 * c]     + v1 * sV2x[2 * c + 2];
        gvA1 += v0 * sV2x[2 * c + 1] + v1 * sV2x[2 * c + 3];
        gvB0 += v2 * sV2x[2 * c]     + v3 * sV2x[2 * c + 2];
        gvB1 += v2 * sV2x[2 * c + 1] + v3 * sV2x[2 * c + 3];
        *(uint32_t*)(smb + V_BHI + rA * SZB + 2 * c) = packbf(v0, v1);
        *(uint32_t*)(smb + V_BLO + rA * SZB + 2 * c) = packbf(v0 - bf16rt(v0), v1 - bf16rt(v1));
        *(uint32_t*)(smb + V_BHI + rB * SZB + 2 * c) = packbf(v2, v3);
        *(uint32_t*)(smb + V_BLO + rB * SZB + 2 * c) = packbf(v2 - bf16rt(v2), v3 - bf16rt(v3));
    }
    __syncthreads();

    // ---- g1 = (g2 @ V2z) * srp(a1); fold into gradV ----
    #pragma unroll
    for (int q = 0; q < 8; q++) { acc[q][0] = acc[q][1] = acc[q][2] = acc[q][3] = 0.f; }
    gemm64<true>(acc, su + V_BHI + aoff, su + V_BLO + aoff, su + V_W2H + wt, su + V_W2L + wt);
    #pragma unroll
    for (int q = 0; q < 8; q++) {
        int c = q * 8 + 2 * tig;
        float w00 = sVl1[2 * c],     w01 = sVl1[2 * c + 1];
        float w10 = sVl1[2 * c + 2], w11 = sVl1[2 * c + 3];
        float v0 = acc[q][0] * srp(dA0 * w00 + dA1 * w01);
        float v1 = acc[q][1] * srp(dA0 * w10 + dA1 * w11);
        float v2 = acc[q][2] * srp(dB0 * w00 + dB1 * w01);
        float v3 = acc[q][3] * srp(dB0 * w10 + dB1 * w11);
        gvA0 += v0 * w00 + v1 * w10;
        gvA1 += v0 * w01 + v1 * w11;
        gvB0 += v2 * w00 + v3 * w10;
        gvB1 += v2 * w01 + v3 * w11;
    }
    gvA0 += __shfl_xor_sync(0xFFFFFFFFu, gvA0, 1);
    gvA0 += __shfl_xor_sync(0xFFFFFFFFu, gvA0, 2);
    gvA1 += __shfl_xor_sync(0xFFFFFFFFu, gvA1, 1);
    gvA1 += __shfl_xor_sync(0xFFFFFFFFu, gvA1, 2);
    gvB0 += __shfl_xor_sync(0xFFFFFFFFu, gvB0, 1);
    gvB0 += __shfl_xor_sync(0xFFFFFFFFu, gvB0, 2);
    gvB1 += __shfl_xor_sync(0xFFFFFFFFu, gvB1, 1);
    gvB1 += __shfl_xor_sync(0xFFFFFFFFu, gvB1, 2);
    if (tig == 0) {
        int gA = base + rA, gB = base + rB;
        if (gA < n) {
            g_gradV[2 * gA]     = gvA0 + gfA * vfx0 + 2.f * TOLC * dA0;
            g_gradV[2 * gA + 1] = gvA1 + gfA * vfx1 + 2.f * TOLC * dA1;
        }
        if (gB < n) {
            g_gradV[2 * gB]     = gvB0 + gfB * vfx0 + 2.f * TOLC * dB0;
            g_gradV[2 * gB + 1] = gvB1 + gfB * vfx1 + 2.f * TOLC * dB1;
        }
    }
}

// ============================================================================
// Kernel B: f_hat MLP (2x-bf16 mma.sync, pre-split W copy staging) + projection
// ============================================================================
constexpr int TB = 256;
constexpr int ST = 136;
constexpr int TILE_A = 128 * ST * 2;
constexpr int TILE_W = 64 * ST * 2;
constexpr int B_AHI  = 0;
constexpr int B_ALO  = TILE_A;
constexpr int B_WHI  = 2 * TILE_A;
constexpr int B_WLO  = 2 * TILE_A + TILE_W;
constexpr int B_MISC = 2 * TILE_A + 2 * TILE_W;   // 104448
constexpr int SMEMB_BYTES = B_MISC + 4 * 898;     // 108040

__global__ __launch_bounds__(TB, 2)
void fhat_kernel(const float* __restrict__ X,
                 const float* __restrict__ f1w, const float* __restrict__ f1b,
                 const float* __restrict__ f2b, const float* __restrict__ f3b,
                 const float* __restrict__ f4b, const float* __restrict__ f5b,
                 const float* __restrict__ ffw, const float* __restrict__ ffb,
                 float* __restrict__ out, int n)
{
    extern __shared__ __align__(16) char smb[];
    __nv_bfloat16* Ahi = (__nv_bfloat16*)(smb + B_AHI);
    __nv_bfloat16* Alo = (__nv_bfloat16*)(smb + B_ALO);
    __nv_bfloat16* Whi = (__nv_bfloat16*)(smb + B_WHI);
    __nv_bfloat16* Wlo = (__nv_bfloat16*)(smb + B_WLO);
    float* mf  = (float*)(smb + B_MISC);
    float* sx  = mf;            // 256
    float* sb  = mf + 256;      // 128
    float* sff = mf + 384;      // 258
    float* sp0 = mf + 642;      // 128
    float* sp1 = mf + 770;      // 128

    const int t    = threadIdx.x;
    const int wid  = t >> 5;
    const int lane = t & 31;
    const int gid  = lane >> 2;
    const int tig  = lane & 3;
    const int r0   = wid * 16;
    const int base = blockIdx.x * 128;

    const int aRow = r0 + (lane & 7) + ((lane >> 3) & 1) * 8;
    const int aCol = ((lane >> 4) & 1) * 8;
    const uint32_t aOff = (uint32_t)(aRow * ST + aCol) * 2;
    const int bRow = (lane & 7) + ((lane >> 4) & 1) * 8;
    const int bCol = ((lane >> 3) & 1) * 8;
    const uint32_t bOff = (uint32_t)(bRow * ST + bCol) * 2;

    const uint32_t aHiB = smem_u32(Ahi) + aOff;
    const uint32_t aLoB = smem_u32(Alo) + aOff;
    const uint32_t wHiB = smem_u32(Whi) + bOff;
    const uint32_t wLoB = smem_u32(Wlo) + bOff;

    {
        int p = t >> 1, c = t & 1;
        int gi = base + p; if (gi >= n) gi = n - 1;
        sx[t] = X[gi * 2 + c];
    }
    for (int i = t; i < 258; i += TB) sff[i] = (i < 256) ? ffw[i] : ffb[i - 256];
    __syncthreads();

    // layer 1 (K=2, SIMT) -> A hi/lo
    for (int i = t; i < 128 * 128; i += TB) {
        int p = i >> 7, j = i & 127;
        float v  = lrelu(sx[2 * p] * f1w[2 * j] + sx[2 * p + 1] * f1w[2 * j + 1] + f1b[j]);
        float h  = bf16rt(v);
        Ahi[p * ST + j] = __float2bfloat16(v);
        Alo[p * ST + j] = __float2bfloat16(v - h);
    }
    __syncthreads();

    const float* Bs[4] = { f2b, f3b, f4b, f5b };

    for (int L = 0; L < 4; L++) {
        float acc[16][4];
        #pragma unroll
        for (int q = 0; q < 16; q++)
            #pragma unroll
            for (int c = 0; c < 4; c++) acc[q][c] = 0.f;

        #pragma unroll 1
        for (int half = 0; half < 2; half++) {
            // stage pre-split W half: pure 16B copies
            const __nv_bfloat16* WH = g_fWh + L * 16384 + half * 8192;
            const __nv_bfloat16* WL = g_fWl + L * 16384 + half * 8192;
            for (int i = t; i < 1024; i += TB) {
                int j = i >> 4, ch = (i & 15) * 8;
                *(uint4*)(Whi + j * ST + ch) = *(const uint4*)(WH + j * 128 + ch);
                *(uint4*)(Wlo + j * ST + ch) = *(const uint4*)(WL + j * 128 + ch);
            }
            if (half == 0 && t < 128) sb[t] = Bs[L][t];
            __syncthreads();

            #pragma unroll
            for (int kt = 0; kt < 8; kt++) {
                const uint32_t kb = kt * 32;
                uint32_t ah[4], al[4];
                ldsm4(ah, aHiB + kb);
                ldsm4(al, aLoB + kb);
                #pragma unroll
                for (int p = 0; p < 4; p++) {
                    uint32_t bh[4], bl[4];
                    const uint32_t po = (uint32_t)(p * 16 * ST * 2) + kb;
                    ldsm4(bh, wHiB + po);
                    ldsm4(bl, wLoB + po);
                    float* c0 = acc[half * 8 + 2 * p];
                    float* c1 = acc[half * 8 + 2 * p + 1];
                    mma_bf16(c0, ah[0], ah[1], ah[2], ah[3], bh[0], bh[1]);
                    mma_bf16(c0, ah[0], ah[1], ah[2], ah[3], bl[0], bl[1]);
                    mma_bf16(c0, al[0], al[1], al[2], al[3], bh[0], bh[1]);
                    mma_bf16(c1, ah[0], ah[1], ah[2], ah[3], bh[2], bh[3]);
                    mma_bf16(c1, ah[0], ah[1], ah[2], ah[3], bl[2], bl[3]);
                    mma_bf16(c1, al[0], al[1], al[2], al[3], bh[2], bh[3]);
                }
            }
            __syncthreads();
        }

        if (L < 3) {
            #pragma unroll
            for (int q = 0; q < 16; q++) {
                int c = (q >> 3) * 64 + (q & 7) * 8 + 2 * tig;
                float v0 = lrelu(acc[q][0] + sb[c]);
                float v1 = lrelu(acc[q][1] + sb[c + 1]);
                float v2 = lrelu(acc[q][2] + sb[c]);
                float v3 = lrelu(acc[q][3] + sb[c + 1]);
                float h0 = bf16rt(v0), h1 = bf16rt(v1), h2 = bf16rt(v2), h3 = bf16rt(v3);
                *(uint32_t*)(Ahi + (r0 + gid) * ST + c)     = packbf(v0, v1);
                *(uint32_t*)(Ahi + (r0 + gid + 8) * ST + c) = packbf(v2, v3);
                *(uint32_t*)(Alo + (r0 + gid) * ST + c)     = packbf(v0 - h0, v1 - h1);
                *(uint32_t*)(Alo + (r0 + gid + 8) * ST + c) = packbf(v2 - h2, v3 - h3);
            }
            __syncthreads();
        } else {
            float p0 = 0.f, p1 = 0.f, q0 = 0.f, q1 = 0.f;
            #pragma unroll
            for (int q = 0; q < 16; q++) {
                int c = (q >> 3) * 64 + (q & 7) * 8 + 2 * tig;
                float v0 = lrelu(acc[q][0] + sb[c]);
                float v1 = lrelu(acc[q][1] + sb[c + 1]);
                float v2 = lrelu(acc[q][2] + sb[c]);
                float v3 = lrelu(acc[q][3] + sb[c + 1]);
                p0 = fmaf(v0, sff[c], fmaf(v1, sff[c + 1], p0));
                p1 = fmaf(v0, sff[128 + c], fmaf(v1, sff[129 + c], p1));
                q0 = fmaf(v2, sff[c], fmaf(v3, sff[c + 1], q0));
                q1 = fmaf(v2, sff[128 + c], fmaf(v3, sff[129 + c], q1));
            }
            #pragma unroll
            for (int m = 1; m < 4; m <<= 1) {
                p0 += __shfl_xor_sync(0xFFFFFFFFu, p0, m);
                p1 += __shfl_xor_sync(0xFFFFFFFFu, p1, m);
                q0 += __shfl_xor_sync(0xFFFFFFFFu, q0, m);
                q1 += __shfl_xor_sync(0xFFFFFFFFu, q1, m);
            }
            if (tig == 0) {
                sp0[r0 + gid] = p0;  sp1[r0 + gid] = p1;
                sp0[r0 + gid + 8] = q0;  sp1[r0 + gid + 8] = q1;
            }
            __syncthreads();
        }
    }

    // final projection
    if (t < 128) {
        int gi = base + t;
        if (gi < n) {
            float fh0 = sff[256] + sp0[t];
            float fh1 = sff[257] + sp1[t];
            float g0 = g_gradV[2 * gi], g1 = g_gradV[2 * gi + 1];
            float V  = g_V[gi];
            float vn  = g0 * g0 + g1 * g1;
            float num = fh0 * g0 + fh1 * g1 + ALPHAC * V;
            float fm  = (num > 0.f ? num : 0.f) / (vn + EPSC);
            out[2 * gi]     = fh0 - g0 * fm;
            out[2 * gi + 1] = fh1 - g1 * fm;
        }
    }
}

// ============================================================================
extern "C" void kernel_launch(void* const* d_in, const int* in_sizes, int n_in,
                              void* d_out, int out_size)
{
    const float* X   = (const float*)d_in[0];
    const float* Xs  = (const float*)d_in[1];
    const float* Vl1 = (const float*)d_in[2];
    const float* V2x = (const float*)d_in[3];
    const float* V2z = (const float*)d_in[4];
    const float* V3x = (const float*)d_in[5];
    const float* V3z = (const float*)d_in[6];
    const float* Vfx = (const float*)d_in[7];
    const float* Vfz = (const float*)d_in[8];
    const float* f1w = (const float*)d_in[9];
    const float* f1b = (const float*)d_in[10];
    const float* f2w = (const float*)d_in[11];
    const float* f2b = (const float*)d_in[12];
    const float* f3w = (const float*)d_in[13];
    const float* f3b = (const float*)d_in[14];
    const float* f4w = (const float*)d_in[15];
    const float* f4b = (const float*)d_in[16];
    const float* f5w = (const float*)d_in[17];
    const float* f5b = (const float*)d_in[18];
    const float* ffw = (const float*)d_in[19];
    const float* ffb = (const float*)d_in[20];

    int n = in_sizes[0] / 2;
    int grid = (n + 127) / 128;

    cudaFuncSetAttribute(vnet_mma,   cudaFuncAttributeMaxDynamicSharedMemorySize, SMEMV_BYTES);
    cudaFuncSetAttribute(fhat_kernel, cudaFuncAttributeMaxDynamicSharedMemorySize, SMEMB_BYTES);

    setup_w<<<288, 256>>>(f2w, f3w, f4w, f5w, V2z, V3z);

    vnet_mma<<<grid, 256, SMEMV_BYTES>>>(X, Xs, Vl1, V2x, V3x, Vfx, Vfz, n);

    fhat_kernel<<<grid, TB, SMEMB_BYTES>>>(
        X, f1w, f1b, f2b, f3b, f4b, f5b, ffw, ffb, (float*)d_out, n);
}

// round 10
// speedup vs baseline: 2.0854x; 1.3231x over previous
#include <cuda_runtime.h>
#include <cuda_bf16.h>
#include <math.h>
#include <stdint.h>

#define TOLC   0.01f
#define ALPHAC 0.1f
#define SLOPEC 0.01f
#define EPSC   1e-10f

#define NMAX 500096
__device__ float g_gradV[2 * NMAX];
__device__ float g_V[NMAX];
__device__ __nv_bfloat16 g_fWh[4 * 16384], g_fWl[4 * 16384];   // f2..f5 hi/lo
__device__ __nv_bfloat16 g_vWh[8192],      g_vWl[8192];        // V2z,V3z hi/lo

__device__ __forceinline__ float sr(float x)  { return x < 0.f ? 0.f : (x < 1.f ? 0.5f * x * x : x - 0.5f); }
__device__ __forceinline__ float srp(float x) { return x < 0.f ? 0.f : (x < 1.f ? x : 1.f); }
__device__ __forceinline__ float srp_out(float z) { return z <= 0.f ? 0.f : (z < 0.5f ? sqrtf(2.f * z) : 1.f); }
__device__ __forceinline__ float lrelu(float x) { return x >= 0.f ? x : SLOPEC * x; }

__device__ __forceinline__ uint32_t packbf(float v0, float v1) {
    uint32_t r; asm("cvt.rn.bf16x2.f32 %0, %1, %2;" : "=r"(r) : "f"(v1), "f"(v0)); return r;
}
__device__ __forceinline__ float bf16rt(float v) {
    return __bfloat162float(__float2bfloat16(v));
}
__device__ __forceinline__ uint32_t smem_u32(const void* p) {
    uint32_t a;
    asm("{ .reg .u64 t; cvta.to.shared.u64 t, %1; cvt.u32.u64 %0, t; }" : "=r"(a) : "l"(p));
    return a;
}
__device__ __forceinline__ void ldsm4(uint32_t* r, uint32_t addr) {
    asm volatile("ldmatrix.sync.aligned.m8n8.x4.shared.b16 {%0,%1,%2,%3}, [%4];"
                 : "=r"(r[0]), "=r"(r[1]), "=r"(r[2]), "=r"(r[3]) : "r"(addr));
}
__device__ __forceinline__ void ldsm4t(uint32_t* r, uint32_t addr) {
    asm volatile("ldmatrix.sync.aligned.m8n8.x4.trans.shared.b16 {%0,%1,%2,%3}, [%4];"
                 : "=r"(r[0]), "=r"(r[1]), "=r"(r[2]), "=r"(r[3]) : "r"(addr));
}
__device__ __forceinline__ void mma_bf16(float* c,
                                         uint32_t a0, uint32_t a1, uint32_t a2, uint32_t a3,
                                         uint32_t b0, uint32_t b1) {
    asm volatile("mma.sync.aligned.m16n8k16.row.col.f32.bf16.bf16.f32 "
                 "{%0,%1,%2,%3}, {%4,%5,%6,%7}, {%8,%9}, {%0,%1,%2,%3};"
                 : "+f"(c[0]), "+f"(c[1]), "+f"(c[2]), "+f"(c[3])
                 : "r"(a0), "r"(a1), "r"(a2), "r"(a3), "r"(b0), "r"(b1));
}

// ============================================================================
// Setup: pre-split weights into bf16 hi/lo globals
// ============================================================================
__global__ void setup_w(const float* __restrict__ f2w, const float* __restrict__ f3w,
                        const float* __restrict__ f4w, const float* __restrict__ f5w,
                        const float* __restrict__ V2z, const float* __restrict__ V3z)
{
    int i = blockIdx.x * blockDim.x + threadIdx.x;
    if (i < 65536) {
        const float* W = (i < 32768) ? ((i < 16384) ? f2w : f3w)
                                     : ((i < 49152) ? f4w : f5w);
        float v = W[i & 16383];
        float h = bf16rt(v);
        g_fWh[i] = __float2bfloat16(v);
        g_fWl[i] = __float2bfloat16(v - h);
    } else if (i < 73728) {
        int j = i - 65536;
        float v = (j < 4096) ? V2z[j] : V3z[j - 4096];
        float h = bf16rt(v);
        g_vWh[j] = __float2bfloat16(v);
        g_vWl[j] = __float2bfloat16(v - h);
    }
}

// ============================================================================
// Kernel A: ICNN V network + VJP via 2x-bf16 mma.sync (proven round-9 code)
// ============================================================================
constexpr int SZB = 144;
constexpr int VT  = 128 * SZB;
constexpr int VW  = 64 * SZB;
constexpr int V_AHI = 0, V_ALO = VT, V_BHI = 2 * VT, V_BLO = 3 * VT;
constexpr int V_W2H = 4 * VT, V_W2L = V_W2H + VW, V_W3H = V_W2H + 2 * VW, V_W3L = V_W2H + 3 * VW;
constexpr int V_MISC = V_W2H + 4 * VW;
constexpr int SMEMV_BYTES = V_MISC + 704 * 4;

template<bool TR>
__device__ __forceinline__ void gemm64(float (&acc)[8][4], uint32_t aHi, uint32_t aLo,
                                       uint32_t wHi, uint32_t wLo)
{
    #pragma unroll
    for (int kt = 0; kt < 4; kt++) {
        uint32_t ah[4], al[4];
        ldsm4(ah, aHi + kt * 32);
        ldsm4(al, aLo + kt * 32);
        #pragma unroll
        for (int p = 0; p < 4; p++) {
            uint32_t off = TR ? (uint32_t)(kt * 16 * SZB + p * 32)
                              : (uint32_t)(p * 16 * SZB + kt * 32);
            uint32_t bh[4], bl[4];
            if (TR) { ldsm4t(bh, wHi + off); ldsm4t(bl, wLo + off); }
            else    { ldsm4 (bh, wHi + off); ldsm4 (bl, wLo + off); }
            float* c0 = acc[2 * p];
            float* c1 = acc[2 * p + 1];
            mma_bf16(c0, ah[0], ah[1], ah[2], ah[3], bh[0], bh[1]);
            mma_bf16(c0, ah[0], ah[1], ah[2], ah[3], bl[0], bl[1]);
            mma_bf16(c0, al[0], al[1], al[2], al[3], bh[0], bh[1]);
            mma_bf16(c1, ah[0], ah[1], ah[2], ah[3], bh[2], bh[3]);
            mma_bf16(c1, ah[0], ah[1], ah[2], ah[3], bl[2], bl[3]);
            mma_bf16(c1, al[0], al[1], al[2], al[3], bh[2], bh[3]);
        }
    }
}

__global__ __launch_bounds__(256, 2)
void vnet_mma(const float* __restrict__ X,   const float* __restrict__ Xs,
              const float* __restrict__ Vl1, const float* __restrict__ V2x,
              const float* __restrict__ V3x, const float* __restrict__ Vfx,
              const float* __restrict__ Vfz, int n)
{
    extern __shared__ __align__(16) char smb[];
    float* mf   = (float*)(smb + V_MISC);
    float* sd   = mf;
    float* sVfz = mf + 256;
    float* sV2x = mf + 320;
    float* sV3x = mf + 448;
    float* sVl1 = mf + 576;

    const int t    = threadIdx.x;
    const int wid  = t >> 5;
    const int lane = t & 31;
    const int gid  = lane >> 2;
    const int tig  = lane & 3;
    const int r0   = wid * 16;
    const int base = blockIdx.x * 128;
    const int rA = r0 + gid, rB = rA + 8;

    {
        int p = t >> 1, c = t & 1;
        int gi = base + p; if (gi >= n) gi = n - 1;
        sd[t] = X[gi * 2 + c] - Xs[gi * 2 + c];
    }
    if (t < 64)  sVfz[t] = Vfz[t];
    if (t < 128) { sV2x[t] = V2x[t]; sV3x[t] = V3x[t]; sVl1[t] = Vl1[t]; }
    for (int i = t; i < 512; i += 256) {
        int row = i >> 3, ch = (i & 7) * 8;
        *(uint4*)(smb + V_W2H + row * SZB + ch * 2) = *(const uint4*)(g_vWh + row * 64 + ch);
        *(uint4*)(smb + V_W2L + row * SZB + ch * 2) = *(const uint4*)(g_vWl + row * 64 + ch);
        *(uint4*)(smb + V_W3H + row * SZB + ch * 2) = *(const uint4*)(g_vWh + 4096 + row * 64 + ch);
        *(uint4*)(smb + V_W3L + row * SZB + ch * 2) = *(const uint4*)(g_vWl + 4096 + row * 64 + ch);
    }
    __syncthreads();

    for (int i = t; i < 8192; i += 256) {
        int p = i >> 6, j = i & 63;
        float v = sr(sd[2 * p] * sVl1[2 * j] + sd[2 * p + 1] * sVl1[2 * j + 1]);
        float h = bf16rt(v);
        *(__nv_bfloat16*)(smb + V_AHI + p * SZB + 2 * j) = __float2bfloat16(v);
        *(__nv_bfloat16*)(smb + V_ALO + p * SZB + 2 * j) = __float2bfloat16(v - h);
    }
    __syncthreads();

    const uint32_t su   = smem_u32(smb);
    const uint32_t aoff = (uint32_t)((r0 + (lane & 7) + ((lane >> 3) & 1) * 8) * SZB
                                     + ((lane >> 4) & 1) * 16);
    const uint32_t wf   = (uint32_t)(((lane & 7) + ((lane >> 4) & 1) * 8) * SZB
                                     + ((lane >> 3) & 1) * 16);
    const uint32_t wt   = (uint32_t)(((lane & 7) + ((lane >> 3) & 1) * 8) * SZB
                                     + ((lane >> 4) & 1) * 16);

    const float dA0 = sd[2 * rA], dA1 = sd[2 * rA + 1];
    const float dB0 = sd[2 * rB], dB1 = sd[2 * rB + 1];
    float acc[8][4];

    #pragma unroll
    for (int q = 0; q < 8; q++) { acc[q][0] = acc[q][1] = acc[q][2] = acc[q][3] = 0.f; }
    gemm64<false>(acc, su + V_AHI + aoff, su + V_ALO + aoff, su + V_W2H + wf, su + V_W2L + wf);
    #pragma unroll
    for (int q = 0; q < 8; q++) {
        int c = q * 8 + 2 * tig;
        float v0 = sr(acc[q][0] + dA0 * sV2x[2 * c]     + dA1 * sV2x[2 * c + 1]);
        float v1 = sr(acc[q][1] + dA0 * sV2x[2 * c + 2] + dA1 * sV2x[2 * c + 3]);
        float v2 = sr(acc[q][2] + dB0 * sV2x[2 * c]     + dB1 * sV2x[2 * c + 1]);
        float v3 = sr(acc[q][3] + dB0 * sV2x[2 * c + 2] + dB1 * sV2x[2 * c + 3]);
        *(uint32_t*)(smb + V_BHI + rA * SZB + 2 * c) = packbf(v0, v1);
        *(uint32_t*)(smb + V_BLO + rA * SZB + 2 * c) = packbf(v0 - bf16rt(v0), v1 - bf16rt(v1));
        *(uint32_t*)(smb + V_BHI + rB * SZB + 2 * c) = packbf(v2, v3);
        *(uint32_t*)(smb + V_BLO + rB * SZB + 2 * c) = packbf(v2 - bf16rt(v2), v3 - bf16rt(v3));
    }
    __syncthreads();

    #pragma unroll
    for (int q = 0; q < 8; q++) { acc[q][0] = acc[q][1] = acc[q][2] = acc[q][3] = 0.f; }
    gemm64<false>(acc, su + V_BHI + aoff, su + V_BLO + aoff, su + V_W3H + wf, su + V_W3L + wf);
    float zfA = 0.f, zfB = 0.f;
    #pragma unroll
    for (int q = 0; q < 8; q++) {
        int c = q * 8 + 2 * tig;
        acc[q][0] = sr(acc[q][0] + dA0 * sV3x[2 * c]     + dA1 * sV3x[2 * c + 1]);
        acc[q][1] = sr(acc[q][1] + dA0 * sV3x[2 * c + 2] + dA1 * sV3x[2 * c + 3]);
        acc[q][2] = sr(acc[q][2] + dB0 * sV3x[2 * c]     + dB1 * sV3x[2 * c + 1]);
        acc[q][3] = sr(acc[q][3] + dB0 * sV3x[2 * c + 2] + dB1 * sV3x[2 * c + 3]);
        zfA += sVfz[c] * acc[q][0] + sVfz[c + 1] * acc[q][1];
        zfB += sVfz[c] * acc[q][2] + sVfz[c + 1] * acc[q][3];
    }
    zfA += __shfl_xor_sync(0xFFFFFFFFu, zfA, 1);
    zfA += __shfl_xor_sync(0xFFFFFFFFu, zfA, 2);
    zfB += __shfl_xor_sync(0xFFFFFFFFu, zfB, 1);
    zfB += __shfl_xor_sync(0xFFFFFFFFu, zfB, 2);
    const float vfx0 = Vfx[0], vfx1 = Vfx[1];
    float afA = zfA + dA0 * vfx0 + dA1 * vfx1;
    float afB = zfB + dB0 * vfx0 + dB1 * vfx1;
    float zA = sr(afA), zB = sr(afB);
    float gfA = srp(zA) * srp(afA);
    float gfB = srp(zB) * srp(afB);
    if (tig == 0) {
        int gA = base + rA, gB = base + rB;
        if (gA < n) g_V[gA] = sr(zA) + TOLC * (dA0 * dA0 + dA1 * dA1);
        if (gB < n) g_V[gB] = sr(zB) + TOLC * (dB0 * dB0 + dB1 * dB1);
    }
    float gvA0 = 0.f, gvA1 = 0.f, gvB0 = 0.f, gvB1 = 0.f;
    #pragma unroll
    for (int q = 0; q < 8; q++) {
        int c = q * 8 + 2 * tig;
        float g0 = gfA * sVfz[c]     * srp_out(acc[q][0]);
        float g1 = gfA * sVfz[c + 1] * srp_out(acc[q][1]);
        float g2 = gfB * sVfz[c]     * srp_out(acc[q][2]);
        float g3 = gfB * sVfz[c + 1] * srp_out(acc[q][3]);
        gvA0 += g0 * sV3x[2 * c]     + g1 * sV3x[2 * c + 2];
        gvA1 += g0 * sV3x[2 * c + 1] + g1 * sV3x[2 * c + 3];
        gvB0 += g2 * sV3x[2 * c]     + g3 * sV3x[2 * c + 2];
        gvB1 += g2 * sV3x[2 * c + 1] + g3 * sV3x[2 * c + 3];
        *(uint32_t*)(smb + V_AHI + rA * SZB + 2 * c) = packbf(g0, g1);
        *(uint32_t*)(smb + V_ALO + rA * SZB + 2 * c) = packbf(g0 - bf16rt(g0), g1 - bf16rt(g1));
        *(uint32_t*)(smb + V_AHI + rB * SZB + 2 * c) = packbf(g2, g3);
        *(uint32_t*)(smb + V_ALO + rB * SZB + 2 * c) = packbf(g2 - bf16rt(g2), g3 - bf16rt(g3));
    }
    __syncthreads();

    #pragma unroll
    for (int q = 0; q < 8; q++) { acc[q][0] = acc[q][1] = acc[q][2] = acc[q][3] = 0.f; }
    gemm64<true>(acc, su + V_AHI + aoff, su + V_ALO + aoff, su + V_W3H + wt, su + V_W3L + wt);
    #pragma unroll
    for (int q = 0; q < 8; q++) {
        int c = q * 8 + 2 * tig;
        uint32_t hA = *(uint32_t*)(smb + V_BHI + rA * SZB + 2 * c);
        uint32_t lA = *(uint32_t*)(smb + V_BLO + rA * SZB + 2 * c);
        uint32_t hB = *(uint32_t*)(smb + V_BHI + rB * SZB + 2 * c);
        uint32_t lB = *(uint32_t*)(smb + V_BLO + rB * SZB + 2 * c);
        float z0 = __uint_as_float(hA << 16) + __uint_as_float(lA << 16);
        float z1v = __uint_as_float(hA & 0xFFFF0000u) + __uint_as_float(lA & 0xFFFF0000u);
        float z2v = __uint_as_float(hB << 16) + __uint_as_float(lB << 16);
        float z3v = __uint_as_float(hB & 0xFFFF0000u) + __uint_as_float(lB & 0xFFFF0000u);
        float v0 = acc[q][0] * srp_out(z0);
        float v1 = acc[q][1] * srp_out(z1v);
        float v2 = acc[q][2] * srp_out(z2v);
        float v3 = acc[q][3] * srp_out(z3v);
        gvA0 += v0 * sV2x[2 * c]     + v1 * sV2x[2 * c + 2];
        gvA1 += v0 * sV2x[2 * c + 1] + v1 * sV2x[2 * c + 3];
        gvB0 += v2 * sV2x[2 * c]     + v3 * sV2x[2 * c + 2];
        gvB1 += v2 * sV2x[2 * c + 1] + v3 * sV2x[2 * c + 3];
        *(uint32_t*)(smb + V_BHI + rA * SZB + 2 * c) = packbf(v0, v1);
        *(uint32_t*)(smb + V_BLO + rA * SZB + 2 * c) = packbf(v0 - bf16rt(v0), v1 - bf16rt(v1));
        *(uint32_t*)(smb + V_BHI + rB * SZB + 2 * c) = packbf(v2, v3);
        *(uint32_t*)(smb + V_BLO + rB * SZB + 2 * c) = packbf(v2 - bf16rt(v2), v3 - bf16rt(v3));
    }
    __syncthreads();

    #pragma unroll
    for (int q = 0; q < 8; q++) { acc[q][0] = acc[q][1] = acc[q][2] = acc[q][3] = 0.f; }
    gemm64<true>(acc, su + V_BHI + aoff, su + V_BLO + aoff, su + V_W2H + wt, su + V_W2L + wt);
    #pragma unroll
    for (int q = 0; q < 8; q++) {
        int c = q * 8 + 2 * tig;
        float w00 = sVl1[2 * c],     w01 = sVl1[2 * c + 1];
        float w10 = sVl1[2 * c + 2], w11 = sVl1[2 * c + 3];
        float v0 = acc[q][0] * srp(dA0 * w00 + dA1 * w01);
        float v1 = acc[q][1] * srp(dA0 * w10 + dA1 * w11);
        float v2 = acc[q][2] * srp(dB0 * w00 + dB1 * w01);
        float v3 = acc[q][3] * srp(dB0 * w10 + dB1 * w11);
        gvA0 += v0 * w00 + v1 * w10;
        gvA1 += v0 * w01 + v1 * w11;
        gvB0 += v2 * w00 + v3 * w10;
        gvB1 += v2 * w01 + v3 * w11;
    }
    gvA0 += __shfl_xor_sync(0xFFFFFFFFu, gvA0, 1);
    gvA0 += __shfl_xor_sync(0xFFFFFFFFu, gvA0, 2);
    gvA1 += __shfl_xor_sync(0xFFFFFFFFu, gvA1, 1);
    gvA1 += __shfl_xor_sync(0xFFFFFFFFu, gvA1, 2);
    gvB0 += __shfl_xor_sync(0xFFFFFFFFu, gvB0, 1);
    gvB0 += __shfl_xor_sync(0xFFFFFFFFu, gvB0, 2);
    gvB1 += __shfl_xor_sync(0xFFFFFFFFu, gvB1, 1);
    gvB1 += __shfl_xor_sync(0xFFFFFFFFu, gvB1, 2);
    if (tig == 0) {
        int gA = base + rA, gB = base + rB;
        if (gA < n) {
            g_gradV[2 * gA]     = gvA0 + gfA * vfx0 + 2.f * TOLC * dA0;
            g_gradV[2 * gA + 1] = gvA1 + gfA * vfx1 + 2.f * TOLC * dA1;
        }
        if (gB < n) {
            g_gradV[2 * gB]     = gvB0 + gfB * vfx0 + 2.f * TOLC * dB0;
            g_gradV[2 * gB + 1] = gvB1 + gfB * vfx1 + 2.f * TOLC * dB1;
        }
    }
}

// ============================================================================
// Kernel B: f_hat MLP — A-hi fragments live in REGISTERS (acc->frag repack),
// only A-lo goes through smem; W staged in quarters. + projection
// ============================================================================
constexpr int TB = 256;
constexpr int ST = 136;                       // bf16 row stride (272 B)
constexpr int ALO_OFF = 0;                    // 128 x 272 = 34816
constexpr int WQ_HI   = 34816;                // 32 x 272 = 8704
constexpr int WQ_LO   = 34816 + 8704;
constexpr int B_MISC  = 34816 + 17408;        // 52224
// misc floats: sx[256] sb[128] sff[258] u[384] (u = f1 stage, later sp0/sp1)
constexpr int SMEMB_BYTES = B_MISC + (256 + 128 + 258 + 384) * 4;   // 56328

__global__ __launch_bounds__(TB, 2)
void fhat_kernel(const float* __restrict__ X,
                 const float* __restrict__ f1w, const float* __restrict__ f1b,
                 const float* __restrict__ f2b, const float* __restrict__ f3b,
                 const float* __restrict__ f4b, const float* __restrict__ f5b,
                 const float* __restrict__ ffw, const float* __restrict__ ffb,
                 float* __restrict__ out, int n)
{
    extern __shared__ __align__(16) char smb[];
    float* mf  = (float*)(smb + B_MISC);
    float* sx  = mf;            // 256
    float* sb  = mf + 256;      // 128
    float* sff = mf + 384;      // 258
    float* su_ = mf + 642;      // 384: f1 staging, later sp0/sp1
    float* sp0 = su_;           // 128
    float* sp1 = su_ + 128;     // 128

    const int t    = threadIdx.x;
    const int wid  = t >> 5;
    const int lane = t & 31;
    const int gid  = lane >> 2;
    const int tig  = lane & 3;
    const int r0   = wid * 16;
    const int base = blockIdx.x * 128;
    const int rA = r0 + gid, rB = rA + 8;

    // ldsm per-lane offsets (A-lo tile; W quarter)
    const uint32_t aOff = (uint32_t)((r0 + (lane & 7) + ((lane >> 3) & 1) * 8) * ST
                                     + ((lane >> 4) & 1) * 8) * 2;
    const uint32_t bOff = (uint32_t)(((lane & 7) + ((lane >> 4) & 1) * 8) * ST
                                     + ((lane >> 3) & 1) * 8) * 2;
    const uint32_t aloB = smem_u32(smb + ALO_OFF) + aOff;
    const uint32_t wHiB = smem_u32(smb + WQ_HI) + bOff;
    const uint32_t wLoB = smem_u32(smb + WQ_LO) + bOff;

    {   // stage X, ff weights, f1 weights
        int p = t >> 1, c = t & 1;
        int gi = base + p; if (gi >= n) gi = n - 1;
        sx[t] = X[gi * 2 + c];
    }
    for (int i = t; i < 258; i += TB) sff[i] = (i < 256) ? ffw[i] : ffb[i - 256];
    for (int i = t; i < 384; i += TB) su_[i] = (i < 256) ? f1w[i] : f1b[i - 256];
    __syncthreads();

    const float xA0 = sx[2 * rA], xA1 = sx[2 * rA + 1];
    const float xB0 = sx[2 * rB], xB1 = sx[2 * rB + 1];

    uint32_t AH[8][4];   // A-hi fragments (registers), rebuilt each layer

    // ---- layer 1 in registers -> AH + A-lo smem tile ----
    #pragma unroll
    for (int q = 0; q < 16; q++) {
        int c = 8 * q + 2 * tig;
        float w0 = su_[2 * c],     w1 = su_[2 * c + 1], b0 = su_[256 + c];
        float w2 = su_[2 * c + 2], w3 = su_[2 * c + 3], b1 = su_[256 + c + 1];
        float v0 = lrelu(xA0 * w0 + xA1 * w1 + b0);
        float v1 = lrelu(xA0 * w2 + xA1 * w3 + b1);
        float v2 = lrelu(xB0 * w0 + xB1 * w1 + b0);
        float v3 = lrelu(xB0 * w2 + xB1 * w3 + b1);
        int kt = q >> 1, s = (q & 1) * 2;
        AH[kt][s]     = packbf(v0, v1);
        AH[kt][s + 1] = packbf(v2, v3);
        *(uint32_t*)(smb + ALO_OFF + rA * ST * 2 + 2 * c) =
            packbf(v0 - bf16rt(v0), v1 - bf16rt(v1));
        *(uint32_t*)(smb + ALO_OFF + rB * ST * 2 + 2 * c) =
            packbf(v2 - bf16rt(v2), v3 - bf16rt(v3));
    }
    __syncthreads();   // f1 staging (su_) reads done; alo visible (own-warp reads anyway)

    const float* Bs[4] = { f2b, f3b, f4b, f5b };

    for (int L = 0; L < 4; L++) {
        float acc[16][4];
        #pragma unroll
        for (int q = 0; q < 16; q++)
            #pragma unroll
            for (int c = 0; c < 4; c++) acc[q][c] = 0.f;

        #pragma unroll
        for (int qt = 0; qt < 4; qt++) {
            // stage W quarter (32 out-rows x 128 k) hi/lo: pure 16B copies
            const __nv_bfloat16* WH = g_fWh + L * 16384 + qt * 4096;
            const __nv_bfloat16* WL = g_fWl + L * 16384 + qt * 4096;
            for (int i = t; i < 512; i += TB) {
                int j = i >> 4, ch = (i & 15) * 8;
                *(uint4*)(smb + WQ_HI + j * ST * 2 + ch * 2) = *(const uint4*)(WH + j * 128 + ch);
                *(uint4*)(smb + WQ_LO + j * ST * 2 + ch * 2) = *(const uint4*)(WL + j * 128 + ch);
            }
            if (qt == 0 && t < 128) sb[t] = Bs[L][t];
            __syncthreads();

            #pragma unroll
            for (int kt = 0; kt < 8; kt++) {
                uint32_t al[4];
                ldsm4(al, aloB + kt * 32);
                #pragma unroll
                for (int p = 0; p < 2; p++) {
                    uint32_t bh[4], bl[4];
                    const uint32_t po = (uint32_t)(p * 16 * ST * 2) + kt * 32;
                    ldsm4(bh, wHiB + po);
                    ldsm4(bl, wLoB + po);
                    float* c0 = acc[4 * qt + 2 * p];
                    float* c1 = acc[4 * qt + 2 * p + 1];
                    mma_bf16(c0, AH[kt][0], AH[kt][1], AH[kt][2], AH[kt][3], bh[0], bh[1]);
                    mma_bf16(c0, AH[kt][0], AH[kt][1], AH[kt][2], AH[kt][3], bl[0], bl[1]);
                    mma_bf16(c0, al[0], al[1], al[2], al[3], bh[0], bh[1]);
                    mma_bf16(c1, AH[kt][0], AH[kt][1], AH[kt][2], AH[kt][3], bh[2], bh[3]);
                    mma_bf16(c1, AH[kt][0], AH[kt][1], AH[kt][2], AH[kt][3], bl[2], bl[3]);
                    mma_bf16(c1, al[0], al[1], al[2], al[3], bh[2], bh[3]);
                }
            }
            __syncthreads();   // W quarter fully consumed before restage
        }

        if (L < 3) {
            // ---- epilogue: bias + lrelu -> new AH (regs) + A-lo smem ----
            #pragma unroll
            for (int q = 0; q < 16; q++) {
                int c = 8 * q + 2 * tig;
                float v0 = lrelu(acc[q][0] + sb[c]);
                float v1 = lrelu(acc[q][1] + sb[c + 1]);
                float v2 = lrelu(acc[q][2] + sb[c]);
                float v3 = lrelu(acc[q][3] + sb[c + 1]);
                int kt = q >> 1, s = (q & 1) * 2;
                AH[kt][s]     = packbf(v0, v1);
                AH[kt][s + 1] = packbf(v2, v3);
                *(uint32_t*)(smb + ALO_OFF + rA * ST * 2 + 2 * c) =
                    packbf(v0 - bf16rt(v0), v1 - bf16rt(v1));
                *(uint32_t*)(smb + ALO_OFF + rB * ST * 2 + 2 * c) =
                    packbf(v2 - bf16rt(v2), v3 - bf16rt(v3));
            }
            __syncthreads();   // sb consumed before next layer's restage
        } else {
            // ---- last hidden layer: fold into ff dot products ----
            float p0 = 0.f, p1 = 0.f, q0 = 0.f, q1 = 0.f;
            #pragma unroll
            for (int q = 0; q < 16; q++) {
                int c = 8 * q + 2 * tig;
                float v0 = lrelu(acc[q][0] + sb[c]);
                float v1 = lrelu(acc[q][1] + sb[c + 1]);
                float v2 = lrelu(acc[q][2] + sb[c]);
                float v3 = lrelu(acc[q][3] + sb[c + 1]);
                p0 = fmaf(v0, sff[c], fmaf(v1, sff[c + 1], p0));
                p1 = fmaf(v0, sff[128 + c], fmaf(v1, sff[129 + c], p1));
                q0 = fmaf(v2, sff[c], fmaf(v3, sff[c + 1], q0));
                q1 = fmaf(v2, sff[128 + c], fmaf(v3, sff[129 + c], q1));
            }
            #pragma unroll
            for (int m = 1; m < 4; m <<= 1) {
                p0 += __shfl_xor_sync(0xFFFFFFFFu, p0, m);
                p1 += __shfl_xor_sync(0xFFFFFFFFu, p1, m);
                q0 += __shfl_xor_sync(0xFFFFFFFFu, q0, m);
                q1 += __shfl_xor_sync(0xFFFFFFFFu, q1, m);
            }
            __syncthreads();   // su_ region free (f1 stage long dead) -> sp0/sp1
            if (tig == 0) {
                sp0[rA] = p0;  sp1[rA] = p1;
                sp0[rB] = q0;  sp1[rB] = q1;
            }
            __syncthreads();
        }
    }

    // ---- final projection ----
    if (t < 128) {
        int gi = base + t;
        if (gi < n) {
            float fh0 = sff[256] + sp0[t];
            float fh1 = sff[257] + sp1[t];
            float g0 = g_gradV[2 * gi], g1 = g_gradV[2 * gi + 1];
            float V  = g_V[gi];
            float vn  = g0 * g0 + g1 * g1;
            float num = fh0 * g0 + fh1 * g1 + ALPHAC * V;
            float fm  = (num > 0.f ? num : 0.f) / (vn + EPSC);
            out[2 * gi]     = fh0 - g0 * fm;
            out[2 * gi + 1] = fh1 - g1 * fm;
        }
    }
}

// ============================================================================
extern "C" void kernel_launch(void* const* d_in, const int* in_sizes, int n_in,
                              void* d_out, int out_size)
{
    const float* X   = (const float*)d_in[0];
    const float* Xs  = (const float*)d_in[1];
    const float* Vl1 = (const float*)d_in[2];
    const float* V2x = (const float*)d_in[3];
    const float* V2z = (const float*)d_in[4];
    const float* V3x = (const float*)d_in[5];
    const float* V3z = (const float*)d_in[6];
    const float* Vfx = (const float*)d_in[7];
    const float* Vfz = (const float*)d_in[8];
    const float* f1w = (const float*)d_in[9];
    const float* f1b = (const float*)d_in[10];
    const float* f2w = (const float*)d_in[11];
    const float* f2b = (const float*)d_in[12];
    const float* f3w = (const float*)d_in[13];
    const float* f3b = (const float*)d_in[14];
    const float* f4w = (const float*)d_in[15];
    const float* f4b = (const float*)d_in[16];
    const float* f5w = (const float*)d_in[17];
    const float* f5b = (const float*)d_in[18];
    const float* ffw = (const float*)d_in[19];
    const float* ffb = (const float*)d_in[20];

    int n = in_sizes[0] / 2;
    int grid = (n + 127) / 128;

    cudaFuncSetAttribute(vnet_mma,    cudaFuncAttributeMaxDynamicSharedMemorySize, SMEMV_BYTES);
    cudaFuncSetAttribute(fhat_kernel, cudaFuncAttributeMaxDynamicSharedMemorySize, SMEMB_BYTES);

    setup_w<<<288, 256>>>(f2w, f3w, f4w, f5w, V2z, V3z);

    vnet_mma<<<grid, 256, SMEMV_BYTES>>>(X, Xs, Vl1, V2x, V3x, Vfx, Vfz, n);

    fhat_kernel<<<grid, TB, SMEMB_BYTES>>>(
        X, f1w, f1b, f2b, f3b, f4b, f5b, ffw, ffb, (float*)d_out, n);
}

// round 11
// speedup vs baseline: 2.1928x; 1.0515x over previous
#include <cuda_runtime.h>
#include <cuda_bf16.h>
#include <math.h>
#include <stdint.h>

#define TOLC   0.01f
#define ALPHAC 0.1f
#define SLOPEC 0.01f
#define EPSC   1e-10f

#define NMAX 500096
__device__ float g_gradV[2 * NMAX];
__device__ float g_V[NMAX];
__device__ __nv_bfloat16 g_fWh[4 * 16384], g_fWl[4 * 16384];   // f2..f5 hi/lo
__device__ __nv_bfloat16 g_vWh[8192],      g_vWl[8192];        // V2z,V3z hi/lo

__device__ __forceinline__ float sr(float x)  { return x < 0.f ? 0.f : (x < 1.f ? 0.5f * x * x : x - 0.5f); }
__device__ __forceinline__ float srp(float x) { return x < 0.f ? 0.f : (x < 1.f ? x : 1.f); }
__device__ __forceinline__ float srp_out(float z) { return z <= 0.f ? 0.f : (z < 0.5f ? sqrtf(2.f * z) : 1.f); }
__device__ __forceinline__ float lrelu(float x) { return x >= 0.f ? x : SLOPEC * x; }

__device__ __forceinline__ uint32_t packbf(float v0, float v1) {
    uint32_t r; asm("cvt.rn.bf16x2.f32 %0, %1, %2;" : "=r"(r) : "f"(v1), "f"(v0)); return r;
}
__device__ __forceinline__ float bf16rt(float v) {
    return __bfloat162float(__float2bfloat16(v));
}
__device__ __forceinline__ uint32_t smem_u32(const void* p) {
    uint32_t a;
    asm("{ .reg .u64 t; cvta.to.shared.u64 t, %1; cvt.u32.u64 %0, t; }" : "=r"(a) : "l"(p));
    return a;
}
__device__ __forceinline__ void cpa16(uint32_t s, const void* g) {
    asm volatile("cp.async.cg.shared.global [%0], [%1], 16;" :: "r"(s), "l"(g));
}
__device__ __forceinline__ void ldsm4(uint32_t* r, uint32_t addr) {
    asm volatile("ldmatrix.sync.aligned.m8n8.x4.shared.b16 {%0,%1,%2,%3}, [%4];"
                 : "=r"(r[0]), "=r"(r[1]), "=r"(r[2]), "=r"(r[3]) : "r"(addr));
}
__device__ __forceinline__ void ldsm4t(uint32_t* r, uint32_t addr) {
    asm volatile("ldmatrix.sync.aligned.m8n8.x4.trans.shared.b16 {%0,%1,%2,%3}, [%4];"
                 : "=r"(r[0]), "=r"(r[1]), "=r"(r[2]), "=r"(r[3]) : "r"(addr));
}
__device__ __forceinline__ void mma_bf16(float* c,
                                         uint32_t a0, uint32_t a1, uint32_t a2, uint32_t a3,
                                         uint32_t b0, uint32_t b1) {
    asm volatile("mma.sync.aligned.m16n8k16.row.col.f32.bf16.bf16.f32 "
                 "{%0,%1,%2,%3}, {%4,%5,%6,%7}, {%8,%9}, {%0,%1,%2,%3};"
                 : "+f"(c[0]), "+f"(c[1]), "+f"(c[2]), "+f"(c[3])
                 : "r"(a0), "r"(a1), "r"(a2), "r"(a3), "r"(b0), "r"(b1));
}

// ============================================================================
// Setup: pre-split weights into bf16 hi/lo globals
// ============================================================================
__global__ void setup_w(const float* __restrict__ f2w, const float* __restrict__ f3w,
                        const float* __restrict__ f4w, const float* __restrict__ f5w,
                        const float* __restrict__ V2z, const float* __restrict__ V3z)
{
    int i = blockIdx.x * blockDim.x + threadIdx.x;
    if (i < 65536) {
        const float* W = (i < 32768) ? ((i < 16384) ? f2w : f3w)
                                     : ((i < 49152) ? f4w : f5w);
        float v = W[i & 16383];
        float h = bf16rt(v);
        g_fWh[i] = __float2bfloat16(v);
        g_fWl[i] = __float2bfloat16(v - h);
    } else if (i < 73728) {
        int j = i - 65536;
        float v = (j < 4096) ? V2z[j] : V3z[j - 4096];
        float h = bf16rt(v);
        g_vWh[j] = __float2bfloat16(v);
        g_vWl[j] = __float2bfloat16(v - h);
    }
}

// ============================================================================
// Kernel A: ICNN V network + VJP via 2x-bf16 mma.sync (proven round-9 code)
// ============================================================================
constexpr int SZB = 144;
constexpr int VT  = 128 * SZB;
constexpr int VW  = 64 * SZB;
constexpr int V_AHI = 0, V_ALO = VT, V_BHI = 2 * VT, V_BLO = 3 * VT;
constexpr int V_W2H = 4 * VT, V_W2L = V_W2H + VW, V_W3H = V_W2H + 2 * VW, V_W3L = V_W2H + 3 * VW;
constexpr int V_MISC = V_W2H + 4 * VW;
constexpr int SMEMV_BYTES = V_MISC + 704 * 4;

template<bool TR>
__device__ __forceinline__ void gemm64(float (&acc)[8][4], uint32_t aHi, uint32_t aLo,
                                       uint32_t wHi, uint32_t wLo)
{
    #pragma unroll
    for (int kt = 0; kt < 4; kt++) {
        uint32_t ah[4], al[4];
        ldsm4(ah, aHi + kt * 32);
        ldsm4(al, aLo + kt * 32);
        #pragma unroll
        for (int p = 0; p < 4; p++) {
            uint32_t off = TR ? (uint32_t)(kt * 16 * SZB + p * 32)
                              : (uint32_t)(p * 16 * SZB + kt * 32);
            uint32_t bh[4], bl[4];
            if (TR) { ldsm4t(bh, wHi + off); ldsm4t(bl, wLo + off); }
            else    { ldsm4 (bh, wHi + off); ldsm4 (bl, wLo + off); }
            float* c0 = acc[2 * p];
            float* c1 = acc[2 * p + 1];
            mma_bf16(c0, ah[0], ah[1], ah[2], ah[3], bh[0], bh[1]);
            mma_bf16(c0, ah[0], ah[1], ah[2], ah[3], bl[0], bl[1]);
            mma_bf16(c0, al[0], al[1], al[2], al[3], bh[0], bh[1]);
            mma_bf16(c1, ah[0], ah[1], ah[2], ah[3], bh[2], bh[3]);
            mma_bf16(c1, ah[0], ah[1], ah[2], ah[3], bl[2], bl[3]);
            mma_bf16(c1, al[0], al[1], al[2], al[3], bh[2], bh[3]);
        }
    }
}

__global__ __launch_bounds__(256, 2)
void vnet_mma(const float* __restrict__ X,   const float* __restrict__ Xs,
              const float* __restrict__ Vl1, const float* __restrict__ V2x,
              const float* __restrict__ V3x, const float* __restrict__ Vfx,
              const float* __restrict__ Vfz, int n)
{
    extern __shared__ __align__(16) char smb[];
    float* mf   = (float*)(smb + V_MISC);
    float* sd   = mf;
    float* sVfz = mf + 256;
    float* sV2x = mf + 320;
    float* sV3x = mf + 448;
    float* sVl1 = mf + 576;

    const int t    = threadIdx.x;
    const int wid  = t >> 5;
    const int lane = t & 31;
    const int gid  = lane >> 2;
    const int tig  = lane & 3;
    const int r0   = wid * 16;
    const int base = blockIdx.x * 128;
    const int rA = r0 + gid, rB = rA + 8;

    {
        int p = t >> 1, c = t & 1;
        int gi = base + p; if (gi >= n) gi = n - 1;
        sd[t] = X[gi * 2 + c] - Xs[gi * 2 + c];
    }
    if (t < 64)  sVfz[t] = Vfz[t];
    if (t < 128) { sV2x[t] = V2x[t]; sV3x[t] = V3x[t]; sVl1[t] = Vl1[t]; }
    for (int i = t; i < 512; i += 256) {
        int row = i >> 3, ch = (i & 7) * 8;
        *(uint4*)(smb + V_W2H + row * SZB + ch * 2) = *(const uint4*)(g_vWh + row * 64 + ch);
        *(uint4*)(smb + V_W2L + row * SZB + ch * 2) = *(const uint4*)(g_vWl + row * 64 + ch);
        *(uint4*)(smb + V_W3H + row * SZB + ch * 2) = *(const uint4*)(g_vWh + 4096 + row * 64 + ch);
        *(uint4*)(smb + V_W3L + row * SZB + ch * 2) = *(const uint4*)(g_vWl + 4096 + row * 64 + ch);
    }
    __syncthreads();

    for (int i = t; i < 8192; i += 256) {
        int p = i >> 6, j = i & 63;
        float v = sr(sd[2 * p] * sVl1[2 * j] + sd[2 * p + 1] * sVl1[2 * j + 1]);
        float h = bf16rt(v);
        *(__nv_bfloat16*)(smb + V_AHI + p * SZB + 2 * j) = __float2bfloat16(v);
        *(__nv_bfloat16*)(smb + V_ALO + p * SZB + 2 * j) = __float2bfloat16(v - h);
    }
    __syncthreads();

    const uint32_t su   = smem_u32(smb);
    const uint32_t aoff = (uint32_t)((r0 + (lane & 7) + ((lane >> 3) & 1) * 8) * SZB
                                     + ((lane >> 4) & 1) * 16);
    const uint32_t wf   = (uint32_t)(((lane & 7) + ((lane >> 4) & 1) * 8) * SZB
                                     + ((lane >> 3) & 1) * 16);
    const uint32_t wt   = (uint32_t)(((lane & 7) + ((lane >> 3) & 1) * 8) * SZB
                                     + ((lane >> 4) & 1) * 16);

    const float dA0 = sd[2 * rA], dA1 = sd[2 * rA + 1];
    const float dB0 = sd[2 * rB], dB1 = sd[2 * rB + 1];
    float acc[8][4];

    #pragma unroll
    for (int q = 0; q < 8; q++) { acc[q][0] = acc[q][1] = acc[q][2] = acc[q][3] = 0.f; }
    gemm64<false>(acc, su + V_AHI + aoff, su + V_ALO + aoff, su + V_W2H + wf, su + V_W2L + wf);
    #pragma unroll
    for (int q = 0; q < 8; q++) {
        int c = q * 8 + 2 * tig;
        float v0 = sr(acc[q][0] + dA0 * sV2x[2 * c]     + dA1 * sV2x[2 * c + 1]);
        float v1 = sr(acc[q][1] + dA0 * sV2x[2 * c + 2] + dA1 * sV2x[2 * c + 3]);
        float v2 = sr(acc[q][2] + dB0 * sV2x[2 * c]     + dB1 * sV2x[2 * c + 1]);
        float v3 = sr(acc[q][3] + dB0 * sV2x[2 * c + 2] + dB1 * sV2x[2 * c + 3]);
        *(uint32_t*)(smb + V_BHI + rA * SZB + 2 * c) = packbf(v0, v1);
        *(uint32_t*)(smb + V_BLO + rA * SZB + 2 * c) = packbf(v0 - bf16rt(v0), v1 - bf16rt(v1));
        *(uint32_t*)(smb + V_BHI + rB * SZB + 2 * c) = packbf(v2, v3);
        *(uint32_t*)(smb + V_BLO + rB * SZB + 2 * c) = packbf(v2 - bf16rt(v2), v3 - bf16rt(v3));
    }
    __syncthreads();

    #pragma unroll
    for (int q = 0; q < 8; q++) { acc[q][0] = acc[q][1] = acc[q][2] = acc[q][3] = 0.f; }
    gemm64<false>(acc, su + V_BHI + aoff, su + V_BLO + aoff, su + V_W3H + wf, su + V_W3L + wf);
    float zfA = 0.f, zfB = 0.f;
    #pragma unroll
    for (int q = 0; q < 8; q++) {
        int c = q * 8 + 2 * tig;
        acc[q][0] = sr(acc[q][0] + dA0 * sV3x[2 * c]     + dA1 * sV3x[2 * c + 1]);
        acc[q][1] = sr(acc[q][1] + dA0 * sV3x[2 * c + 2] + dA1 * sV3x[2 * c + 3]);
        acc[q][2] = sr(acc[q][2] + dB0 * sV3x[2 * c]     + dB1 * sV3x[2 * c + 1]);
        acc[q][3] = sr(acc[q][3] + dB0 * sV3x[2 * c + 2] + dB1 * sV3x[2 * c + 3]);
        zfA += sVfz[c] * acc[q][0] + sVfz[c + 1] * acc[q][1];
        zfB += sVfz[c] * acc[q][2] + sVfz[c + 1] * acc[q][3];
    }
    zfA += __shfl_xor_sync(0xFFFFFFFFu, zfA, 1);
    zfA += __shfl_xor_sync(0xFFFFFFFFu, zfA, 2);
    zfB += __shfl_xor_sync(0xFFFFFFFFu, zfB, 1);
    zfB += __shfl_xor_sync(0xFFFFFFFFu, zfB, 2);
    const float vfx0 = Vfx[0], vfx1 = Vfx[1];
    float afA = zfA + dA0 * vfx0 + dA1 * vfx1;
    float afB = zfB + dB0 * vfx0 + dB1 * vfx1;
    float zA = sr(afA), zB = sr(afB);
    float gfA = srp(zA) * srp(afA);
    float gfB = srp(zB) * srp(afB);
    if (tig == 0) {
        int gA = base + rA, gB = base + rB;
        if (gA < n) g_V[gA] = sr(zA) + TOLC * (dA0 * dA0 + dA1 * dA1);
        if (gB < n) g_V[gB] = sr(zB) + TOLC * (dB0 * dB0 + dB1 * dB1);
    }
    float gvA0 = 0.f, gvA1 = 0.f, gvB0 = 0.f, gvB1 = 0.f;
    #pragma unroll
    for (int q = 0; q < 8; q++) {
        int c = q * 8 + 2 * tig;
        float g0 = gfA * sVfz[c]     * srp_out(acc[q][0]);
        float g1 = gfA * sVfz[c + 1] * srp_out(acc[q][1]);
        float g2 = gfB * sVfz[c]     * srp_out(acc[q][2]);
        float g3 = gfB * sVfz[c + 1] * srp_out(acc[q][3]);
        gvA0 += g0 * sV3x[2 * c]     + g1 * sV3x[2 * c + 2];
        gvA1 += g0 * sV3x[2 * c + 1] + g1 * sV3x[2 * c + 3];
        gvB0 += g2 * sV3x[2 * c]     + g3 * sV3x[2 * c + 2];
        gvB1 += g2 * sV3x[2 * c + 1] + g3 * sV3x[2 * c + 3];
        *(uint32_t*)(smb + V_AHI + rA * SZB + 2 * c) = packbf(g0, g1);
        *(uint32_t*)(smb + V_ALO + rA * SZB + 2 * c) = packbf(g0 - bf16rt(g0), g1 - bf16rt(g1));
        *(uint32_t*)(smb + V_AHI + rB * SZB + 2 * c) = packbf(g2, g3);
        *(uint32_t*)(smb + V_ALO + rB * SZB + 2 * c) = packbf(g2 - bf16rt(g2), g3 - bf16rt(g3));
    }
    __syncthreads();

    #pragma unroll
    for (int q = 0; q < 8; q++) { acc[q][0] = acc[q][1] = acc[q][2] = acc[q][3] = 0.f; }
    gemm64<true>(acc, su + V_AHI + aoff, su + V_ALO + aoff, su + V_W3H + wt, su + V_W3L + wt);
    #pragma unroll
    for (int q = 0; q < 8; q++) {
        int c = q * 8 + 2 * tig;
        uint32_t hA = *(uint32_t*)(smb + V_BHI + rA * SZB + 2 * c);
        uint32_t lA = *(uint32_t*)(smb + V_BLO + rA * SZB + 2 * c);
        uint32_t hB = *(uint32_t*)(smb + V_BHI + rB * SZB + 2 * c);
        uint32_t lB = *(uint32_t*)(smb + V_BLO + rB * SZB + 2 * c);
        float z0 = __uint_as_float(hA << 16) + __uint_as_float(lA << 16);
        float z1v = __uint_as_float(hA & 0xFFFF0000u) + __uint_as_float(lA & 0xFFFF0000u);
        float z2v = __uint_as_float(hB << 16) + __uint_as_float(lB << 16);
        float z3v = __uint_as_float(hB & 0xFFFF0000u) + __uint_as_float(lB & 0xFFFF0000u);
        float v0 = acc[q][0] * srp_out(z0);
        float v1 = acc[q][1] * srp_out(z1v);
        float v2 = acc[q][2] * srp_out(z2v);
        float v3 = acc[q][3] * srp_out(z3v);
        gvA0 += v0 * sV2x[2 * c]     + v1 * sV2x[2 * c + 2];
        gvA1 += v0 * sV2x[2 * c + 1] + v1 * sV2x[2 * c + 3];
        gvB0 += v2 * sV2x[2 * c]     + v3 * sV2x[2 * c + 2];
        gvB1 += v2 * sV2x[2 * c + 1] + v3 * sV2x[2 * c + 3];
        *(uint32_t*)(smb + V_BHI + rA * SZB + 2 * c) = packbf(v0, v1);
        *(uint32_t*)(smb + V_BLO + rA * SZB + 2 * c) = packbf(v0 - bf16rt(v0), v1 - bf16rt(v1));
        *(uint32_t*)(smb + V_BHI + rB * SZB + 2 * c) = packbf(v2, v3);
        *(uint32_t*)(smb + V_BLO + rB * SZB + 2 * c) = packbf(v2 - bf16rt(v2), v3 - bf16rt(v3));
    }
    __syncthreads();

    #pragma unroll
    for (int q = 0; q < 8; q++) { acc[q][0] = acc[q][1] = acc[q][2] = acc[q][3] = 0.f; }
    gemm64<true>(acc, su + V_BHI + aoff, su + V_BLO + aoff, su + V_W2H + wt, su + V_W2L + wt);
    #pragma unroll
    for (int q = 0; q < 8; q++) {
        int c = q * 8 + 2 * tig;
        float w00 = sVl1[2 * c],     w01 = sVl1[2 * c + 1];
        float w10 = sVl1[2 * c + 2], w11 = sVl1[2 * c + 3];
        float v0 = acc[q][0] * srp(dA0 * w00 + dA1 * w01);
        float v1 = acc[q][1] * srp(dA0 * w10 + dA1 * w11);
        float v2 = acc[q][2] * srp(dB0 * w00 + dB1 * w01);
        float v3 = acc[q][3] * srp(dB0 * w10 + dB1 * w11);
        gvA0 += v0 * w00 + v1 * w10;
        gvA1 += v0 * w01 + v1 * w11;
        gvB0 += v2 * w00 + v3 * w10;
        gvB1 += v2 * w01 + v3 * w11;
    }
    gvA0 += __shfl_xor_sync(0xFFFFFFFFu, gvA0, 1);
    gvA0 += __shfl_xor_sync(0xFFFFFFFFu, gvA0, 2);
    gvA1 += __shfl_xor_sync(0xFFFFFFFFu, gvA1, 1);
    gvA1 += __shfl_xor_sync(0xFFFFFFFFu, gvA1, 2);
    gvB0 += __shfl_xor_sync(0xFFFFFFFFu, gvB0, 1);
    gvB0 += __shfl_xor_sync(0xFFFFFFFFu, gvB0, 2);
    gvB1 += __shfl_xor_sync(0xFFFFFFFFu, gvB1, 1);
    gvB1 += __shfl_xor_sync(0xFFFFFFFFu, gvB1, 2);
    if (tig == 0) {
        int gA = base + rA, gB = base + rB;
        if (gA < n) {
            g_gradV[2 * gA]     = gvA0 + gfA * vfx0 + 2.f * TOLC * dA0;
            g_gradV[2 * gA + 1] = gvA1 + gfA * vfx1 + 2.f * TOLC * dA1;
        }
        if (gB < n) {
            g_gradV[2 * gB]     = gvB0 + gfB * vfx0 + 2.f * TOLC * dB0;
            g_gradV[2 * gB + 1] = gvB1 + gfB * vfx1 + 2.f * TOLC * dB1;
        }
    }
}

// ============================================================================
// Kernel B: f_hat MLP — register A-hi fragments + FULL-W single-sync staging
// via cp.async. + projection
// ============================================================================
constexpr int TB = 256;
constexpr int ST = 136;                       // bf16 row stride (272 B)
constexpr int ALO_OFF = 0;                    // 128 x 272 = 34816
constexpr int WHI_OFF = 34816;                // 128 x 272 = 34816
constexpr int WLO_OFF = 69632;
constexpr int B_MISC  = 104448;
// misc floats: sx[256] sb4[512] sff[258] su_[384]
constexpr int SMEMB_BYTES = B_MISC + (256 + 512 + 258 + 384) * 4;   // 110088

__global__ __launch_bounds__(TB, 2)
void fhat_kernel(const float* __restrict__ X,
                 const float* __restrict__ f1w, const float* __restrict__ f1b,
                 const float* __restrict__ f2b, const float* __restrict__ f3b,
                 const float* __restrict__ f4b, const float* __restrict__ f5b,
                 const float* __restrict__ ffw, const float* __restrict__ ffb,
                 float* __restrict__ out, int n)
{
    extern __shared__ __align__(16) char smb[];
    float* mf  = (float*)(smb + B_MISC);
    float* sx  = mf;            // 256
    float* sb4 = mf + 256;      // 512 (biases f2..f5)
    float* sff = mf + 768;      // 258
    float* su_ = mf + 1026;     // 384: f1 staging, later sp0/sp1
    float* sp0 = su_;           // 128
    float* sp1 = su_ + 128;     // 128

    const int t    = threadIdx.x;
    const int wid  = t >> 5;
    const int lane = t & 31;
    const int gid  = lane >> 2;
    const int tig  = lane & 3;
    const int r0   = wid * 16;
    const int base = blockIdx.x * 128;
    const int rA = r0 + gid, rB = rA + 8;

    const uint32_t suB  = smem_u32(smb);
    const uint32_t aOff = (uint32_t)((r0 + (lane & 7) + ((lane >> 3) & 1) * 8) * ST
                                     + ((lane >> 4) & 1) * 8) * 2;
    const uint32_t bOff = (uint32_t)(((lane & 7) + ((lane >> 4) & 1) * 8) * ST
                                     + ((lane >> 3) & 1) * 8) * 2;
    const uint32_t aloB = suB + ALO_OFF + aOff;
    const uint32_t wHiB = suB + WHI_OFF + bOff;
    const uint32_t wLoB = suB + WLO_OFF + bOff;

    {   // stage X, ff weights, f1 weights, all biases
        int p = t >> 1, c = t & 1;
        int gi = base + p; if (gi >= n) gi = n - 1;
        sx[t] = X[gi * 2 + c];
    }
    for (int i = t; i < 258; i += TB) sff[i] = (i < 256) ? ffw[i] : ffb[i - 256];
    for (int i = t; i < 384; i += TB) su_[i] = (i < 256) ? f1w[i] : f1b[i - 256];
    {
        const float* Bs[4] = { f2b, f3b, f4b, f5b };
        for (int i = t; i < 512; i += TB) sb4[i] = Bs[i >> 7][i & 127];
    }
    __syncthreads();

    const float xA0 = sx[2 * rA], xA1 = sx[2 * rA + 1];
    const float xB0 = sx[2 * rB], xB1 = sx[2 * rB + 1];

    uint32_t AH[8][4];   // A-hi fragments in registers

    // ---- layer 1 in registers -> AH + A-lo smem ----
    #pragma unroll
    for (int q = 0; q < 16; q++) {
        int c = 8 * q + 2 * tig;
        float w0 = su_[2 * c],     w1 = su_[2 * c + 1], b0 = su_[256 + c];
        float w2 = su_[2 * c + 2], w3 = su_[2 * c + 3], b1 = su_[256 + c + 1];
        float v0 = lrelu(xA0 * w0 + xA1 * w1 + b0);
        float v1 = lrelu(xA0 * w2 + xA1 * w3 + b1);
        float v2 = lrelu(xB0 * w0 + xB1 * w1 + b0);
        float v3 = lrelu(xB0 * w2 + xB1 * w3 + b1);
        int kt = q >> 1, s = (q & 1) * 2;
        uint32_t hA = packbf(v0, v1);
        uint32_t hB = packbf(v2, v3);
        AH[kt][s]     = hA;
        AH[kt][s + 1] = hB;
        *(uint32_t*)(smb + ALO_OFF + rA * ST * 2 + 2 * c) =
            packbf(v0 - __uint_as_float(hA << 16), v1 - __uint_as_float(hA & 0xFFFF0000u));
        *(uint32_t*)(smb + ALO_OFF + rB * ST * 2 + 2 * c) =
            packbf(v2 - __uint_as_float(hB << 16), v3 - __uint_as_float(hB & 0xFFFF0000u));
    }
    __syncthreads();   // f1 staging reads done before su_ reuse later

    for (int L = 0; L < 4; L++) {
        // ---- stage full W (hi+lo) via cp.async: 2048 x 16B each ----
        const __nv_bfloat16* WH = g_fWh + L * 16384;
        const __nv_bfloat16* WL = g_fWl + L * 16384;
        for (int i = t; i < 2048; i += TB) {
            int j = i >> 4, ch = (i & 15) * 8;
            uint32_t so = (uint32_t)(j * ST * 2 + ch * 2);
            cpa16(suB + WHI_OFF + so, WH + j * 128 + ch);
            cpa16(suB + WLO_OFF + so, WL + j * 128 + ch);
        }
        asm volatile("cp.async.commit_group;" ::: "memory");
        asm volatile("cp.async.wait_group 0;" ::: "memory");
        __syncthreads();

        float acc[16][4];
        #pragma unroll
        for (int q = 0; q < 16; q++)
            #pragma unroll
            for (int c = 0; c < 4; c++) acc[q][c] = 0.f;

        // ---- mainloop: 8 kt x 8 p, uninterrupted ----
        #pragma unroll
        for (int kt = 0; kt < 8; kt++) {
            uint32_t al[4];
            ldsm4(al, aloB + kt * 32);
            #pragma unroll
            for (int p = 0; p < 8; p++) {
                uint32_t bh[4], bl[4];
                const uint32_t po = (uint32_t)(p * 16 * ST * 2) + kt * 32;
                ldsm4(bh, wHiB + po);
                ldsm4(bl, wLoB + po);
                float* c0 = acc[2 * p];
                float* c1 = acc[2 * p + 1];
                mma_bf16(c0, AH[kt][0], AH[kt][1], AH[kt][2], AH[kt][3], bh[0], bh[1]);
                mma_bf16(c0, AH[kt][0], AH[kt][1], AH[kt][2], AH[kt][3], bl[0], bl[1]);
                mma_bf16(c0, al[0], al[1], al[2], al[3], bh[0], bh[1]);
                mma_bf16(c1, AH[kt][0], AH[kt][1], AH[kt][2], AH[kt][3], bh[2], bh[3]);
                mma_bf16(c1, AH[kt][0], AH[kt][1], AH[kt][2], AH[kt][3], bl[2], bl[3]);
                mma_bf16(c1, al[0], al[1], al[2], al[3], bh[2], bh[3]);
            }
        }

        const float* sb = sb4 + L * 128;
        if (L < 3) {
            // ---- epilogue: bias + lrelu -> new AH + A-lo ----
            #pragma unroll
            for (int q = 0; q < 16; q++) {
                int c = 8 * q + 2 * tig;
                float v0 = lrelu(acc[q][0] + sb[c]);
                float v1 = lrelu(acc[q][1] + sb[c + 1]);
                float v2 = lrelu(acc[q][2] + sb[c]);
                float v3 = lrelu(acc[q][3] + sb[c + 1]);
                int kt = q >> 1, s = (q & 1) * 2;
                uint32_t hA = packbf(v0, v1);
                uint32_t hB = packbf(v2, v3);
                AH[kt][s]     = hA;
                AH[kt][s + 1] = hB;
                *(uint32_t*)(smb + ALO_OFF + rA * ST * 2 + 2 * c) =
                    packbf(v0 - __uint_as_float(hA << 16), v1 - __uint_as_float(hA & 0xFFFF0000u));
                *(uint32_t*)(smb + ALO_OFF + rB * ST * 2 + 2 * c) =
                    packbf(v2 - __uint_as_float(hB << 16), v3 - __uint_as_float(hB & 0xFFFF0000u));
            }
            __syncthreads();   // all W reads done before next-layer restage
        } else {
            // ---- last hidden layer: fold into ff dot products ----
            float p0 = 0.f, p1 = 0.f, q0 = 0.f, q1 = 0.f;
            #pragma unroll
            for (int q = 0; q < 16; q++) {
                int c = 8 * q + 2 * tig;
                float v0 = lrelu(acc[q][0] + sb[c]);
                float v1 = lrelu(acc[q][1] + sb[c + 1]);
                float v2 = lrelu(acc[q][2] + sb[c]);
                float v3 = lrelu(acc[q][3] + sb[c + 1]);
                p0 = fmaf(v0, sff[c], fmaf(v1, sff[c + 1], p0));
                p1 = fmaf(v0, sff[128 + c], fmaf(v1, sff[129 + c], p1));
                q0 = fmaf(v2, sff[c], fmaf(v3, sff[c + 1], q0));
                q1 = fmaf(v2, sff[128 + c], fmaf(v3, sff[129 + c], q1));
            }
            #pragma unroll
            for (int m = 1; m < 4; m <<= 1) {
                p0 += __shfl_xor_sync(0xFFFFFFFFu, p0, m);
                p1 += __shfl_xor_sync(0xFFFFFFFFu, p1, m);
                q0 += __shfl_xor_sync(0xFFFFFFFFu, q0, m);
                q1 += __shfl_xor_sync(0xFFFFFFFFu, q1, m);
            }
            __syncthreads();   // su_ region free -> sp0/sp1
            if (tig == 0) {
                sp0[rA] = p0;  sp1[rA] = p1;
                sp0[rB] = q0;  sp1[rB] = q1;
            }
            __syncthreads();
        }
    }

    // ---- final projection ----
    if (t < 128) {
        int gi = base + t;
        if (gi < n) {
            float fh0 = sff[256] + sp0[t];
            float fh1 = sff[257] + sp1[t];
            float g0 = g_gradV[2 * gi], g1 = g_gradV[2 * gi + 1];
            float V  = g_V[gi];
            float vn  = g0 * g0 + g1 * g1;
            float num = fh0 * g0 + fh1 * g1 + ALPHAC * V;
            float fm  = (num > 0.f ? num : 0.f) / (vn + EPSC);
            out[2 * gi]     = fh0 - g0 * fm;
            out[2 * gi + 1] = fh1 - g1 * fm;
        }
    }
}

// ============================================================================
extern "C" void kernel_launch(void* const* d_in, const int* in_sizes, int n_in,
                              void* d_out, int out_size)
{
    const float* X   = (const float*)d_in[0];
    const float* Xs  = (const float*)d_in[1];
    const float* Vl1 = (const float*)d_in[2];
    const float* V2x = (const float*)d_in[3];
    const float* V2z = (const float*)d_in[4];
    const float* V3x = (const float*)d_in[5];
    const float* V3z = (const float*)d_in[6];
    const float* Vfx = (const float*)d_in[7];
    const float* Vfz = (const float*)d_in[8];
    const float* f1w = (const float*)d_in[9];
    const float* f1b = (const float*)d_in[10];
    const float* f2w = (const float*)d_in[11];
    const float* f2b = (const float*)d_in[12];
    const float* f3w = (const float*)d_in[13];
    const float* f3b = (const float*)d_in[14];
    const float* f4w = (const float*)d_in[15];
    const float* f4b = (const float*)d_in[16];
    const float* f5w = (const float*)d_in[17];
    const float* f5b = (const float*)d_in[18];
    const float* ffw = (const float*)d_in[19];
    const float* ffb = (const float*)d_in[20];

    int n = in_sizes[0] / 2;
    int grid = (n + 127) / 128;

    cudaFuncSetAttribute(vnet_mma,    cudaFuncAttributeMaxDynamicSharedMemorySize, SMEMV_BYTES);
    cudaFuncSetAttribute(fhat_kernel, cudaFuncAttributeMaxDynamicSharedMemorySize, SMEMB_BYTES);

    setup_w<<<288, 256>>>(f2w, f3w, f4w, f5w, V2z, V3z);

    vnet_mma<<<grid, 256, SMEMV_BYTES>>>(X, Xs, Vl1, V2x, V3x, Vfx, Vfz, n);

    fhat_kernel<<<grid, TB, SMEMB_BYTES>>>(
        X, f1w, f1b, f2b, f3b, f4b, f5b, ffw, ffb, (float*)d_out, n);
}

// round 13
// speedup vs baseline: 2.9151x; 1.3294x over previous
#include <cuda_runtime.h>
#include <cuda_fp16.h>
#include <math.h>
#include <stdint.h>

#define TOLC   0.01f
#define ALPHAC 0.1f
#define SLOPEC 0.01f
#define EPSC   1e-10f

#define NMAX 500096
__device__ float g_gradV[2 * NMAX];
__device__ float g_V[NMAX];
__device__ __half g_fWh[4 * 16384];   // f2..f5 fp16
__device__ __half g_vWh[8192];        // V2z,V3z fp16

__device__ __forceinline__ float sr(float x)  { return x < 0.f ? 0.f : (x < 1.f ? 0.5f * x * x : x - 0.5f); }
__device__ __forceinline__ float srp(float x) { return x < 0.f ? 0.f : (x < 1.f ? x : 1.f); }
__device__ __forceinline__ float srp_out(float z) { return z <= 0.f ? 0.f : (z < 0.5f ? sqrtf(2.f * z) : 1.f); }
__device__ __forceinline__ float lrelu(float x) { return x >= 0.f ? x : SLOPEC * x; }

__device__ __forceinline__ uint32_t packhf(float v0, float v1) {
    uint32_t r; asm("cvt.rn.f16x2.f32 %0, %1, %2;" : "=r"(r) : "f"(v1), "f"(v0)); return r;
}
__device__ __forceinline__ float hfrt(float v) { return __half2float(__float2half_rn(v)); }
__device__ __forceinline__ float2 unpackhf(uint32_t u) {
    __half2 h = *reinterpret_cast<__half2*>(&u);
    return __half22float2(h);
}
__device__ __forceinline__ uint32_t smem_u32(const void* p) {
    uint32_t a;
    asm("{ .reg .u64 t; cvta.to.shared.u64 t, %1; cvt.u32.u64 %0, t; }" : "=r"(a) : "l"(p));
    return a;
}
__device__ __forceinline__ void cpa16(uint32_t s, const void* g) {
    asm volatile("cp.async.cg.shared.global [%0], [%1], 16;" :: "r"(s), "l"(g));
}
__device__ __forceinline__ void ldsm4(uint32_t* r, uint32_t addr) {
    asm volatile("ldmatrix.sync.aligned.m8n8.x4.shared.b16 {%0,%1,%2,%3}, [%4];"
                 : "=r"(r[0]), "=r"(r[1]), "=r"(r[2]), "=r"(r[3]) : "r"(addr));
}
__device__ __forceinline__ void ldsm4t(uint32_t* r, uint32_t addr) {
    asm volatile("ldmatrix.sync.aligned.m8n8.x4.trans.shared.b16 {%0,%1,%2,%3}, [%4];"
                 : "=r"(r[0]), "=r"(r[1]), "=r"(r[2]), "=r"(r[3]) : "r"(addr));
}
__device__ __forceinline__ void mma_hf(float* c,
                                       uint32_t a0, uint32_t a1, uint32_t a2, uint32_t a3,
                                       uint32_t b0, uint32_t b1) {
    asm volatile("mma.sync.aligned.m16n8k16.row.col.f32.f16.f16.f32 "
                 "{%0,%1,%2,%3}, {%4,%5,%6,%7}, {%8,%9}, {%0,%1,%2,%3};"
                 : "+f"(c[0]), "+f"(c[1]), "+f"(c[2]), "+f"(c[3])
                 : "r"(a0), "r"(a1), "r"(a2), "r"(a3), "r"(b0), "r"(b1));
}

// ============================================================================
// Setup: convert weights to fp16 globals
// ============================================================================
__global__ void setup_w(const float* __restrict__ f2w, const float* __restrict__ f3w,
                        const float* __restrict__ f4w, const float* __restrict__ f5w,
                        const float* __restrict__ V2z, const float* __restrict__ V3z)
{
    int i = blockIdx.x * blockDim.x + threadIdx.x;
    if (i < 65536) {
        const float* W = (i < 32768) ? ((i < 16384) ? f2w : f3w)
                                     : ((i < 49152) ? f4w : f5w);
        g_fWh[i] = __float2half_rn(W[i & 16383]);
    } else if (i < 73728) {
        int j = i - 65536;
        g_vWh[j] = __float2half_rn((j < 4096) ? V2z[j] : V3z[j - 4096]);
    }
}

// ============================================================================
// Kernel A: ICNN V network + VJP (exact-A fp16-split x fp16-W mma.sync)
// ============================================================================
constexpr int SZB = 144;
constexpr int VT  = 128 * SZB;
constexpr int VW  = 64 * SZB;
constexpr int V_AHI = 0, V_ALO = VT, V_BHI = 2 * VT, V_BLO = 3 * VT;
constexpr int V_W2H = 4 * VT, V_W3H = 4 * VT + VW;
constexpr int V_MISC = 4 * VT + 2 * VW;          // 92160
constexpr int SMEMV_BYTES = V_MISC + 704 * 4;    // 94976 -> 2 CTAs/SM

template<bool TR>
__device__ __forceinline__ void gemm64(float (&acc)[8][4], uint32_t aHi, uint32_t aLo,
                                       uint32_t wHi)
{
    #pragma unroll
    for (int kt = 0; kt < 4; kt++) {
        uint32_t ah[4], al[4];
        ldsm4(ah, aHi + kt * 32);
        ldsm4(al, aLo + kt * 32);
        #pragma unroll
        for (int p = 0; p < 4; p++) {
            uint32_t off = TR ? (uint32_t)(kt * 16 * SZB + p * 32)
                              : (uint32_t)(p * 16 * SZB + kt * 32);
            uint32_t bh[4];
            if (TR) ldsm4t(bh, wHi + off);
            else    ldsm4 (bh, wHi + off);
            float* c0 = acc[2 * p];
            float* c1 = acc[2 * p + 1];
            mma_hf(c0, ah[0], ah[1], ah[2], ah[3], bh[0], bh[1]);
            mma_hf(c0, al[0], al[1], al[2], al[3], bh[0], bh[1]);
            mma_hf(c1, ah[0], ah[1], ah[2], ah[3], bh[2], bh[3]);
            mma_hf(c1, al[0], al[1], al[2], al[3], bh[2], bh[3]);
        }
    }
}

__global__ __launch_bounds__(256, 2)
void vnet_mma(const float* __restrict__ X,   const float* __restrict__ Xs,
              const float* __restrict__ Vl1, const float* __restrict__ V2x,
              const float* __restrict__ V3x, const float* __restrict__ Vfx,
              const float* __restrict__ Vfz, int n)
{
    extern __shared__ __align__(16) char smb[];
    float* mf   = (float*)(smb + V_MISC);
    float* sd   = mf;
    float* sVfz = mf + 256;
    float* sV2x = mf + 320;
    float* sV3x = mf + 448;
    float* sVl1 = mf + 576;

    const int t    = threadIdx.x;
    const int wid  = t >> 5;
    const int lane = t & 31;
    const int gid  = lane >> 2;
    const int tig  = lane & 3;
    const int r0   = wid * 16;
    const int base = blockIdx.x * 128;
    const int rA = r0 + gid, rB = rA + 8;

    {
        int p = t >> 1, c = t & 1;
        int gi = base + p; if (gi >= n) gi = n - 1;
        sd[t] = X[gi * 2 + c] - Xs[gi * 2 + c];
    }
    if (t < 64)  sVfz[t] = Vfz[t];
    if (t < 128) { sV2x[t] = V2x[t]; sV3x[t] = V3x[t]; sVl1[t] = Vl1[t]; }
    // stage W2h / W3h (each 64 rows x 64 halves = 128 B/row)
    for (int i = t; i < 512; i += 256) {
        int row = i >> 3, ch = (i & 7) * 8;
        *(uint4*)(smb + V_W2H + row * SZB + ch * 2) = *(const uint4*)(g_vWh + row * 64 + ch);
        *(uint4*)(smb + V_W3H + row * SZB + ch * 2) = *(const uint4*)(g_vWh + 4096 + row * 64 + ch);
    }
    __syncthreads();

    // z1 = sr(d @ Vl1^T) -> A tile hi/lo (fp16 split: hi+lo == exact)
    for (int i = t; i < 8192; i += 256) {
        int p = i >> 6, j = i & 63;
        float v = sr(sd[2 * p] * sVl1[2 * j] + sd[2 * p + 1] * sVl1[2 * j + 1]);
        float h = hfrt(v);
        *(__half*)(smb + V_AHI + p * SZB + 2 * j) = __float2half_rn(v);
        *(__half*)(smb + V_ALO + p * SZB + 2 * j) = __float2half_rn(v - h);
    }
    __syncthreads();

    const uint32_t su   = smem_u32(smb);
    const uint32_t aoff = (uint32_t)((r0 + (lane & 7) + ((lane >> 3) & 1) * 8) * SZB
                                     + ((lane >> 4) & 1) * 16);
    const uint32_t wf   = (uint32_t)(((lane & 7) + ((lane >> 4) & 1) * 8) * SZB
                                     + ((lane >> 3) & 1) * 16);
    const uint32_t wt   = (uint32_t)(((lane & 7) + ((lane >> 3) & 1) * 8) * SZB
                                     + ((lane >> 4) & 1) * 16);

    const float dA0 = sd[2 * rA], dA1 = sd[2 * rA + 1];
    const float dB0 = sd[2 * rB], dB1 = sd[2 * rB + 1];
    float acc[8][4];

    // ---- z2 = sr(d@V2x^T + z1@V2z^T) -> B tile ----
    #pragma unroll
    for (int q = 0; q < 8; q++) { acc[q][0] = acc[q][1] = acc[q][2] = acc[q][3] = 0.f; }
    gemm64<false>(acc, su + V_AHI + aoff, su + V_ALO + aoff, su + V_W2H + wf);
    #pragma unroll
    for (int q = 0; q < 8; q++) {
        int c = q * 8 + 2 * tig;
        float v0 = sr(acc[q][0] + dA0 * sV2x[2 * c]     + dA1 * sV2x[2 * c + 1]);
        float v1 = sr(acc[q][1] + dA0 * sV2x[2 * c + 2] + dA1 * sV2x[2 * c + 3]);
        float v2 = sr(acc[q][2] + dB0 * sV2x[2 * c]     + dB1 * sV2x[2 * c + 1]);
        float v3 = sr(acc[q][3] + dB0 * sV2x[2 * c + 2] + dB1 * sV2x[2 * c + 3]);
        uint32_t hA = packhf(v0, v1), hB = packhf(v2, v3);
        float2 ha = unpackhf(hA), hb = unpackhf(hB);
        *(uint32_t*)(smb + V_BHI + rA * SZB + 2 * c) = hA;
        *(uint32_t*)(smb + V_BLO + rA * SZB + 2 * c) = packhf(v0 - ha.x, v1 - ha.y);
        *(uint32_t*)(smb + V_BHI + rB * SZB + 2 * c) = hB;
        *(uint32_t*)(smb + V_BLO + rB * SZB + 2 * c) = packhf(v2 - hb.x, v3 - hb.y);
    }
    __syncthreads();

    // ---- z3 (regs) + zf/gf/V + g3 -> A tile ----
    #pragma unroll
    for (int q = 0; q < 8; q++) { acc[q][0] = acc[q][1] = acc[q][2] = acc[q][3] = 0.f; }
    gemm64<false>(acc, su + V_BHI + aoff, su + V_BLO + aoff, su + V_W3H + wf);
    float zfA = 0.f, zfB = 0.f;
    #pragma unroll
    for (int q = 0; q < 8; q++) {
        int c = q * 8 + 2 * tig;
        acc[q][0] = sr(acc[q][0] + dA0 * sV3x[2 * c]     + dA1 * sV3x[2 * c + 1]);
        acc[q][1] = sr(acc[q][1] + dA0 * sV3x[2 * c + 2] + dA1 * sV3x[2 * c + 3]);
        acc[q][2] = sr(acc[q][2] + dB0 * sV3x[2 * c]     + dB1 * sV3x[2 * c + 1]);
        acc[q][3] = sr(acc[q][3] + dB0 * sV3x[2 * c + 2] + dB1 * sV3x[2 * c + 3]);
        zfA += sVfz[c] * acc[q][0] + sVfz[c + 1] * acc[q][1];
        zfB += sVfz[c] * acc[q][2] + sVfz[c + 1] * acc[q][3];
    }
    zfA += __shfl_xor_sync(0xFFFFFFFFu, zfA, 1);
    zfA += __shfl_xor_sync(0xFFFFFFFFu, zfA, 2);
    zfB += __shfl_xor_sync(0xFFFFFFFFu, zfB, 1);
    zfB += __shfl_xor_sync(0xFFFFFFFFu, zfB, 2);
    const float vfx0 = Vfx[0], vfx1 = Vfx[1];
    float afA = zfA + dA0 * vfx0 + dA1 * vfx1;
    float afB = zfB + dB0 * vfx0 + dB1 * vfx1;
    float zA = sr(afA), zB = sr(afB);
    float gfA = srp(zA) * srp(afA);
    float gfB = srp(zB) * srp(afB);
    if (tig == 0) {
        int gA = base + rA, gB = base + rB;
        if (gA < n) g_V[gA] = sr(zA) + TOLC * (dA0 * dA0 + dA1 * dA1);
        if (gB < n) g_V[gB] = sr(zB) + TOLC * (dB0 * dB0 + dB1 * dB1);
    }
    float gvA0 = 0.f, gvA1 = 0.f, gvB0 = 0.f, gvB1 = 0.f;
    #pragma unroll
    for (int q = 0; q < 8; q++) {
        int c = q * 8 + 2 * tig;
        float g0 = gfA * sVfz[c]     * srp_out(acc[q][0]);
        float g1 = gfA * sVfz[c + 1] * srp_out(acc[q][1]);
        float g2 = gfB * sVfz[c]     * srp_out(acc[q][2]);
        float g3 = gfB * sVfz[c + 1] * srp_out(acc[q][3]);
        gvA0 += g0 * sV3x[2 * c]     + g1 * sV3x[2 * c + 2];
        gvA1 += g0 * sV3x[2 * c + 1] + g1 * sV3x[2 * c + 3];
        gvB0 += g2 * sV3x[2 * c]     + g3 * sV3x[2 * c + 2];
        gvB1 += g2 * sV3x[2 * c + 1] + g3 * sV3x[2 * c + 3];
        uint32_t hA = packhf(g0, g1), hB = packhf(g2, g3);
        float2 ha = unpackhf(hA), hb = unpackhf(hB);
        *(uint32_t*)(smb + V_AHI + rA * SZB + 2 * c) = hA;
        *(uint32_t*)(smb + V_ALO + rA * SZB + 2 * c) = packhf(g0 - ha.x, g1 - ha.y);
        *(uint32_t*)(smb + V_AHI + rB * SZB + 2 * c) = hB;
        *(uint32_t*)(smb + V_ALO + rB * SZB + 2 * c) = packhf(g2 - hb.x, g3 - hb.y);
    }
    __syncthreads();

    // ---- g2 = (g3 @ V3z) * srp(z2) ----
    #pragma unroll
    for (int q = 0; q < 8; q++) { acc[q][0] = acc[q][1] = acc[q][2] = acc[q][3] = 0.f; }
    gemm64<true>(acc, su + V_AHI + aoff, su + V_ALO + aoff, su + V_W3H + wt);
    #pragma unroll
    for (int q = 0; q < 8; q++) {
        int c = q * 8 + 2 * tig;
        float2 hA = unpackhf(*(uint32_t*)(smb + V_BHI + rA * SZB + 2 * c));
        float2 lA = unpackhf(*(uint32_t*)(smb + V_BLO + rA * SZB + 2 * c));
        float2 hB = unpackhf(*(uint32_t*)(smb + V_BHI + rB * SZB + 2 * c));
        float2 lB = unpackhf(*(uint32_t*)(smb + V_BLO + rB * SZB + 2 * c));
        float v0 = acc[q][0] * srp_out(hA.x + lA.x);
        float v1 = acc[q][1] * srp_out(hA.y + lA.y);
        float v2 = acc[q][2] * srp_out(hB.x + lB.x);
        float v3 = acc[q][3] * srp_out(hB.y + lB.y);
        gvA0 += v0 * sV2x[2 * c]     + v1 * sV2x[2 * c + 2];
        gvA1 += v0 * sV2x[2 * c + 1] + v1 * sV2x[2 * c + 3];
        gvB0 += v2 * sV2x[2 * c]     + v3 * sV2x[2 * c + 2];
        gvB1 += v2 * sV2x[2 * c + 1] + v3 * sV2x[2 * c + 3];
        uint32_t nhA = packhf(v0, v1), nhB = packhf(v2, v3);
        float2 na = unpackhf(nhA), nb = unpackhf(nhB);
        *(uint32_t*)(smb + V_BHI + rA * SZB + 2 * c) = nhA;
        *(uint32_t*)(smb + V_BLO + rA * SZB + 2 * c) = packhf(v0 - na.x, v1 - na.y);
        *(uint32_t*)(smb + V_BHI + rB * SZB + 2 * c) = nhB;
        *(uint32_t*)(smb + V_BLO + rB * SZB + 2 * c) = packhf(v2 - nb.x, v3 - nb.y);
    }
    __syncthreads();

    // ---- g1 = (g2 @ V2z) * srp(a1); fold into gradV ----
    #pragma unroll
    for (int q = 0; q < 8; q++) { acc[q][0] = acc[q][1] = acc[q][2] = acc[q][3] = 0.f; }
    gemm64<true>(acc, su + V_BHI + aoff, su + V_BLO + aoff, su + V_W2H + wt);
    #pragma unroll
    for (int q = 0; q < 8; q++) {
        int c = q * 8 + 2 * tig;
        float w00 = sVl1[2 * c],     w01 = sVl1[2 * c + 1];
        float w10 = sVl1[2 * c + 2], w11 = sVl1[2 * c + 3];
        float v0 = acc[q][0] * srp(dA0 * w00 + dA1 * w01);
        float v1 = acc[q][1] * srp(dA0 * w10 + dA1 * w11);
        float v2 = acc[q][2] * srp(dB0 * w00 + dB1 * w01);
        float v3 = acc[q][3] * srp(dB0 * w10 + dB1 * w11);
        gvA0 += v0 * w00 + v1 * w10;
        gvA1 += v0 * w01 + v1 * w11;
        gvB0 += v2 * w00 + v3 * w10;
        gvB1 += v2 * w01 + v3 * w11;
    }
    gvA0 += __shfl_xor_sync(0xFFFFFFFFu, gvA0, 1);
    gvA0 += __shfl_xor_sync(0xFFFFFFFFu, gvA0, 2);
    gvA1 += __shfl_xor_sync(0xFFFFFFFFu, gvA1, 1);
    gvA1 += __shfl_xor_sync(0xFFFFFFFFu, gvA1, 2);
    gvB0 += __shfl_xor_sync(0xFFFFFFFFu, gvB0, 1);
    gvB0 += __shfl_xor_sync(0xFFFFFFFFu, gvB0, 2);
    gvB1 += __shfl_xor_sync(0xFFFFFFFFu, gvB1, 1);
    gvB1 += __shfl_xor_sync(0xFFFFFFFFu, gvB1, 2);
    if (tig == 0) {
        int gA = base + rA, gB = base + rB;
        if (gA < n) {
            g_gradV[2 * gA]     = gvA0 + gfA * vfx0 + 2.f * TOLC * dA0;
            g_gradV[2 * gA + 1] = gvA1 + gfA * vfx1 + 2.f * TOLC * dA1;
        }
        if (gB < n) {
            g_gradV[2 * gB]     = gvB0 + gfB * vfx0 + 2.f * TOLC * dB0;
            g_gradV[2 * gB + 1] = gvB1 + gfB * vfx1 + 2.f * TOLC * dB1;
        }
    }
}

// ============================================================================
// Kernel B: f_hat MLP — register A-hi + smem A-lo (exact A), fp16 W (no lo)
// ============================================================================
constexpr int TB = 256;
constexpr int ST = 136;                       // fp16 row stride (272 B)
constexpr int ALO_OFF = 0;                    // 128 x 272 = 34816
constexpr int WHI_OFF = 34816;                // 128 x 272 = 34816
constexpr int B_MISC  = 69632;
// misc floats: sx[256] sb4[512] sff[258] su_[384]
constexpr int SMEMB_BYTES = B_MISC + (256 + 512 + 258 + 384) * 4;   // 75272

__global__ __launch_bounds__(TB, 2)
void fhat_kernel(const float* __restrict__ X,
                 const float* __restrict__ f1w, const float* __restrict__ f1b,
                 const float* __restrict__ f2b, const float* __restrict__ f3b,
                 const float* __restrict__ f4b, const float* __restrict__ f5b,
                 const float* __restrict__ ffw, const float* __restrict__ ffb,
                 float* __restrict__ out, int n)
{
    extern __shared__ __align__(16) char smb[];
    float* mf  = (float*)(smb + B_MISC);
    float* sx  = mf;            // 256
    float* sb4 = mf + 256;      // 512
    float* sff = mf + 768;      // 258
    float* su_ = mf + 1026;     // 384: f1 staging, later sp0/sp1
    float* sp0 = su_;
    float* sp1 = su_ + 128;

    const int t    = threadIdx.x;
    const int wid  = t >> 5;
    const int lane = t & 31;
    const int gid  = lane >> 2;
    const int tig  = lane & 3;
    const int r0   = wid * 16;
    const int base = blockIdx.x * 128;
    const int rA = r0 + gid, rB = rA + 8;

    const uint32_t suB  = smem_u32(smb);
    const uint32_t aOff = (uint32_t)((r0 + (lane & 7) + ((lane >> 3) & 1) * 8) * ST
                                     + ((lane >> 4) & 1) * 8) * 2;
    const uint32_t bOff = (uint32_t)(((lane & 7) + ((lane >> 4) & 1) * 8) * ST
                                     + ((lane >> 3) & 1) * 8) * 2;
    const uint32_t aloB = suB + ALO_OFF + aOff;
    const uint32_t wHiB = suB + WHI_OFF + bOff;

    {
        int p = t >> 1, c = t & 1;
        int gi = base + p; if (gi >= n) gi = n - 1;
        sx[t] = X[gi * 2 + c];
    }
    for (int i = t; i < 258; i += TB) sff[i] = (i < 256) ? ffw[i] : ffb[i - 256];
    for (int i = t; i < 384; i += TB) su_[i] = (i < 256) ? f1w[i] : f1b[i - 256];
    {
        const float* Bs[4] = { f2b, f3b, f4b, f5b };
        for (int i = t; i < 512; i += TB) sb4[i] = Bs[i >> 7][i & 127];
    }
    __syncthreads();

    const float xA0 = sx[2 * rA], xA1 = sx[2 * rA + 1];
    const float xB0 = sx[2 * rB], xB1 = sx[2 * rB + 1];

    uint32_t AH[8][4];   // A-hi fp16x2 fragments in registers

    // ---- layer 1 in registers -> AH + A-lo smem ----
    #pragma unroll
    for (int q = 0; q < 16; q++) {
        int c = 8 * q + 2 * tig;
        float w0 = su_[2 * c],     w1 = su_[2 * c + 1], b0 = su_[256 + c];
        float w2 = su_[2 * c + 2], w3 = su_[2 * c + 3], b1 = su_[256 + c + 1];
        float v0 = lrelu(xA0 * w0 + xA1 * w1 + b0);
        float v1 = lrelu(xA0 * w2 + xA1 * w3 + b1);
        float v2 = lrelu(xB0 * w0 + xB1 * w1 + b0);
        float v3 = lrelu(xB0 * w2 + xB1 * w3 + b1);
        int kt = q >> 1, s = (q & 1) * 2;
        uint32_t hA = packhf(v0, v1);
        uint32_t hB = packhf(v2, v3);
        AH[kt][s]     = hA;
        AH[kt][s + 1] = hB;
        float2 ha = unpackhf(hA), hb = unpackhf(hB);
        *(uint32_t*)(smb + ALO_OFF + rA * ST * 2 + 2 * c) = packhf(v0 - ha.x, v1 - ha.y);
        *(uint32_t*)(smb + ALO_OFF + rB * ST * 2 + 2 * c) = packhf(v2 - hb.x, v3 - hb.y);
    }
    __syncthreads();

    for (int L = 0; L < 4; L++) {
        // ---- stage full W-hi via cp.async: 2048 x 16B (FULL 256B rows) ----
        const __half* WH = g_fWh + L * 16384;
        for (int i = t; i < 2048; i += TB) {
            int j = i >> 4, ch = (i & 15) * 8;
            cpa16(suB + WHI_OFF + (uint32_t)(j * ST * 2 + ch * 2), WH + j * 128 + ch);
        }
        asm volatile("cp.async.commit_group;" ::: "memory");
        asm volatile("cp.async.wait_group 0;" ::: "memory");
        __syncthreads();

        float acc[16][4];
        #pragma unroll
        for (int q = 0; q < 16; q++)
            #pragma unroll
            for (int c = 0; c < 4; c++) acc[q][c] = 0.f;

        // ---- mainloop: 8 kt x 8 p ----
        #pragma unroll
        for (int kt = 0; kt < 8; kt++) {
            uint32_t al[4];
            ldsm4(al, aloB + kt * 32);
            #pragma unroll
            for (int p = 0; p < 8; p++) {
                uint32_t bh[4];
                ldsm4(bh, wHiB + (uint32_t)(p * 16 * ST * 2) + kt * 32);
                float* c0 = acc[2 * p];
                float* c1 = acc[2 * p + 1];
                mma_hf(c0, AH[kt][0], AH[kt][1], AH[kt][2], AH[kt][3], bh[0], bh[1]);
                mma_hf(c0, al[0], al[1], al[2], al[3], bh[0], bh[1]);
                mma_hf(c1, AH[kt][0], AH[kt][1], AH[kt][2], AH[kt][3], bh[2], bh[3]);
                mma_hf(c1, al[0], al[1], al[2], al[3], bh[2], bh[3]);
            }
        }

        const float* sb = sb4 + L * 128;
        if (L < 3) {
            #pragma unroll
            for (int q = 0; q < 16; q++) {
                int c = 8 * q + 2 * tig;
                float v0 = lrelu(acc[q][0] + sb[c]);
                float v1 = lrelu(acc[q][1] + sb[c + 1]);
                float v2 = lrelu(acc[q][2] + sb[c]);
                float v3 = lrelu(acc[q][3] + sb[c + 1]);
                int kt = q >> 1, s = (q & 1) * 2;
                uint32_t hA = packhf(v0, v1);
                uint32_t hB = packhf(v2, v3);
                AH[kt][s]     = hA;
                AH[kt][s + 1] = hB;
                float2 ha = unpackhf(hA), hb = unpackhf(hB);
                *(uint32_t*)(smb + ALO_OFF + rA * ST * 2 + 2 * c) = packhf(v0 - ha.x, v1 - ha.y);
                *(uint32_t*)(smb + ALO_OFF + rB * ST * 2 + 2 * c) = packhf(v2 - hb.x, v3 - hb.y);
            }
            __syncthreads();
        } else {
            float p0 = 0.f, p1 = 0.f, q0 = 0.f, q1 = 0.f;
            #pragma unroll
            for (int q = 0; q < 16; q++) {
                int c = 8 * q + 2 * tig;
                float v0 = lrelu(acc[q][0] + sb[c]);
                float v1 = lrelu(acc[q][1] + sb[c + 1]);
                float v2 = lrelu(acc[q][2] + sb[c]);
                float v3 = lrelu(acc[q][3] + sb[c + 1]);
                p0 = fmaf(v0, sff[c], fmaf(v1, sff[c + 1], p0));
                p1 = fmaf(v0, sff[128 + c], fmaf(v1, sff[129 + c], p1));
                q0 = fmaf(v2, sff[c], fmaf(v3, sff[c + 1], q0));
                q1 = fmaf(v2, sff[128 + c], fmaf(v3, sff[129 + c], q1));
            }
            #pragma unroll
            for (int m = 1; m < 4; m <<= 1) {
                p0 += __shfl_xor_sync(0xFFFFFFFFu, p0, m);
                p1 += __shfl_xor_sync(0xFFFFFFFFu, p1, m);
                q0 += __shfl_xor_sync(0xFFFFFFFFu, q0, m);
                q1 += __shfl_xor_sync(0xFFFFFFFFu, q1, m);
            }
            __syncthreads();   // su_ free -> sp0/sp1
            if (tig == 0) {
                sp0[rA] = p0;  sp1[rA] = p1;
                sp0[rB] = q0;  sp1[rB] = q1;
            }
            __syncthreads();
        }
    }

    // ---- final projection ----
    if (t < 128) {
        int gi = base + t;
        if (gi < n) {
            float fh0 = sff[256] + sp0[t];
            float fh1 = sff[257] + sp1[t];
            float g0 = g_gradV[2 * gi], g1 = g_gradV[2 * gi + 1];
            float V  = g_V[gi];
            float vn  = g0 * g0 + g1 * g1;
            float num = fh0 * g0 + fh1 * g1 + ALPHAC * V;
            float fm  = (num > 0.f ? num : 0.f) / (vn + EPSC);
            out[2 * gi]     = fh0 - g0 * fm;
            out[2 * gi + 1] = fh1 - g1 * fm;
        }
    }
}

// ============================================================================
extern "C" void kernel_launch(void* const* d_in, const int* in_sizes, int n_in,
                              void* d_out, int out_size)
{
    const float* X   = (const float*)d_in[0];
    const float* Xs  = (const float*)d_in[1];
    const float* Vl1 = (const float*)d_in[2];
    const float* V2x = (const float*)d_in[3];
    const float* V2z = (const float*)d_in[4];
    const float* V3x = (const float*)d_in[5];
    const float* V3z = (const float*)d_in[6];
    const float* Vfx = (const float*)d_in[7];
    const float* Vfz = (const float*)d_in[8];
    const float* f1w = (const float*)d_in[9];
    const float* f1b = (const float*)d_in[10];
    const float* f2w = (const float*)d_in[11];
    const float* f2b = (const float*)d_in[12];
    const float* f3w = (const float*)d_in[13];
    const float* f3b = (const float*)d_in[14];
    const float* f4w = (const float*)d_in[15];
    const float* f4b = (const float*)d_in[16];
    const float* f5w = (const float*)d_in[17];
    const float* f5b = (const float*)d_in[18];
    const float* ffw = (const float*)d_in[19];
    const float* ffb = (const float*)d_in[20];

    int n = in_sizes[0] / 2;
    int grid = (n + 127) / 128;

    cudaFuncSetAttribute(vnet_mma,    cudaFuncAttributeMaxDynamicSharedMemorySize, SMEMV_BYTES);
    cudaFuncSetAttribute(fhat_kernel, cudaFuncAttributeMaxDynamicSharedMemorySize, SMEMB_BYTES);

    setup_w<<<288, 256>>>(f2w, f3w, f4w, f5w, V2z, V3z);

    vnet_mma<<<grid, 256, SMEMV_BYTES>>>(X, Xs, Vl1, V2x, V3x, Vfx, Vfz, n);

    fhat_kernel<<<grid, TB, SMEMB_BYTES>>>(
        X, f1w, f1b, f2b, f3b, f4b, f5b, ffw, ffb, (float*)d_out, n);
}

// round 14
// speedup vs baseline: 2.9370x; 1.0075x over previous
#include <cuda_runtime.h>
#include <cuda_fp16.h>
#include <math.h>
#include <stdint.h>

#define TOLC   0.01f
#define ALPHAC 0.1f
#define SLOPEC 0.01f
#define EPSC   1e-10f

#define NMAX 500096
__device__ float g_gradV[2 * NMAX];
__device__ float g_V[NMAX];
__device__ __half g_fWh[4 * 16384];   // f2..f5 fp16
__device__ __half g_vWh[8192];        // V2z,V3z fp16

__device__ __forceinline__ float sr(float x)  { return x < 0.f ? 0.f : (x < 1.f ? 0.5f * x * x : x - 0.5f); }
__device__ __forceinline__ float srp(float x) { return x < 0.f ? 0.f : (x < 1.f ? x : 1.f); }
__device__ __forceinline__ float srp_out(float z) { return z <= 0.f ? 0.f : (z < 0.5f ? sqrtf(2.f * z) : 1.f); }
__device__ __forceinline__ float lrelu(float x) { return x >= 0.f ? x : SLOPEC * x; }

__device__ __forceinline__ uint32_t packhf(float v0, float v1) {
    uint32_t r; asm("cvt.rn.f16x2.f32 %0, %1, %2;" : "=r"(r) : "f"(v1), "f"(v0)); return r;
}
__device__ __forceinline__ float hfrt(float v) { return __half2float(__float2half_rn(v)); }
__device__ __forceinline__ float2 unpackhf(uint32_t u) {
    __half2 h = *reinterpret_cast<__half2*>(&u);
    return __half22float2(h);
}
__device__ __forceinline__ uint32_t smem_u32(const void* p) {
    uint32_t a;
    asm("{ .reg .u64 t; cvta.to.shared.u64 t, %1; cvt.u32.u64 %0, t; }" : "=r"(a) : "l"(p));
    return a;
}
__device__ __forceinline__ void cpa16(uint32_t s, const void* g) {
    asm volatile("cp.async.cg.shared.global [%0], [%1], 16;" :: "r"(s), "l"(g));
}
__device__ __forceinline__ void ldsm4(uint32_t* r, uint32_t addr) {
    asm volatile("ldmatrix.sync.aligned.m8n8.x4.shared.b16 {%0,%1,%2,%3}, [%4];"
                 : "=r"(r[0]), "=r"(r[1]), "=r"(r[2]), "=r"(r[3]) : "r"(addr));
}
__device__ __forceinline__ void ldsm4t(uint32_t* r, uint32_t addr) {
    asm volatile("ldmatrix.sync.aligned.m8n8.x4.trans.shared.b16 {%0,%1,%2,%3}, [%4];"
                 : "=r"(r[0]), "=r"(r[1]), "=r"(r[2]), "=r"(r[3]) : "r"(addr));
}
__device__ __forceinline__ void mma_hf(float* c,
                                       uint32_t a0, uint32_t a1, uint32_t a2, uint32_t a3,
                                       uint32_t b0, uint32_t b1) {
    asm volatile("mma.sync.aligned.m16n8k16.row.col.f32.f16.f16.f32 "
                 "{%0,%1,%2,%3}, {%4,%5,%6,%7}, {%8,%9}, {%0,%1,%2,%3};"
                 : "+f"(c[0]), "+f"(c[1]), "+f"(c[2]), "+f"(c[3])
                 : "r"(a0), "r"(a1), "r"(a2), "r"(a3), "r"(b0), "r"(b1));
}

// ============================================================================
// Setup: convert weights to fp16 globals
// ============================================================================
__global__ void setup_w(const float* __restrict__ f2w, const float* __restrict__ f3w,
                        const float* __restrict__ f4w, const float* __restrict__ f5w,
                        const float* __restrict__ V2z, const float* __restrict__ V3z)
{
    int i = blockIdx.x * blockDim.x + threadIdx.x;
    if (i < 65536) {
        const float* W = (i < 32768) ? ((i < 16384) ? f2w : f3w)
                                     : ((i < 49152) ? f4w : f5w);
        g_fWh[i] = __float2half_rn(W[i & 16383]);
    } else if (i < 73728) {
        int j = i - 65536;
        g_vWh[j] = __float2half_rn((j < 4096) ? V2z[j] : V3z[j - 4096]);
    }
}

// ============================================================================
// Kernel A: ICNN V + VJP — fully warp-local after one staging barrier
// ============================================================================
constexpr int SZB = 144;
constexpr int VT  = 128 * SZB;
constexpr int VW  = 64 * SZB;
constexpr int V_AHI = 0, V_ALO = VT, V_BHI = 2 * VT, V_BLO = 3 * VT;
constexpr int V_W2H = 4 * VT, V_W3H = 4 * VT + VW;
constexpr int V_MISC = 4 * VT + 2 * VW;          // 92160
constexpr int SMEMV_BYTES = V_MISC + 704 * 4;    // 94976 -> 2 CTAs/SM

template<bool TR>
__device__ __forceinline__ void gemm64(float (&acc)[8][4], uint32_t aHi, uint32_t aLo,
                                       uint32_t wHi)
{
    #pragma unroll
    for (int kt = 0; kt < 4; kt++) {
        uint32_t ah[4], al[4];
        ldsm4(ah, aHi + kt * 32);
        ldsm4(al, aLo + kt * 32);
        #pragma unroll
        for (int p = 0; p < 4; p++) {
            uint32_t off = TR ? (uint32_t)(kt * 16 * SZB + p * 32)
                              : (uint32_t)(p * 16 * SZB + kt * 32);
            uint32_t bh[4];
            if (TR) ldsm4t(bh, wHi + off);
            else    ldsm4 (bh, wHi + off);
            float* c0 = acc[2 * p];
            float* c1 = acc[2 * p + 1];
            mma_hf(c0, ah[0], ah[1], ah[2], ah[3], bh[0], bh[1]);
            mma_hf(c0, al[0], al[1], al[2], al[3], bh[0], bh[1]);
            mma_hf(c1, ah[0], ah[1], ah[2], ah[3], bh[2], bh[3]);
            mma_hf(c1, al[0], al[1], al[2], al[3], bh[2], bh[3]);
        }
    }
}

__global__ __launch_bounds__(256, 2)
void vnet_mma(const float* __restrict__ X,   const float* __restrict__ Xs,
              const float* __restrict__ Vl1, const float* __restrict__ V2x,
              const float* __restrict__ V3x, const float* __restrict__ Vfx,
              const float* __restrict__ Vfz, int n)
{
    extern __shared__ __align__(16) char smb[];
    float* mf   = (float*)(smb + V_MISC);
    float* sd   = mf;
    float* sVfz = mf + 256;
    float* sV2x = mf + 320;
    float* sV3x = mf + 448;
    float* sVl1 = mf + 576;

    const int t    = threadIdx.x;
    const int wid  = t >> 5;
    const int lane = t & 31;
    const int gid  = lane >> 2;
    const int tig  = lane & 3;
    const int r0   = wid * 16;
    const int base = blockIdx.x * 128;
    const int rA = r0 + gid, rB = rA + 8;

    {   // sd write is warp-local (t in [32w,32w+31] -> rows 16w..16w+15)
        int p = t >> 1, c = t & 1;
        int gi = base + p; if (gi >= n) gi = n - 1;
        sd[t] = X[gi * 2 + c] - Xs[gi * 2 + c];
    }
    if (t < 64)  sVfz[t] = Vfz[t];
    if (t < 128) { sV2x[t] = V2x[t]; sV3x[t] = V3x[t]; sVl1[t] = Vl1[t]; }
    for (int i = t; i < 512; i += 256) {
        int row = i >> 3, ch = (i & 7) * 8;
        *(uint4*)(smb + V_W2H + row * SZB + ch * 2) = *(const uint4*)(g_vWh + row * 64 + ch);
        *(uint4*)(smb + V_W3H + row * SZB + ch * 2) = *(const uint4*)(g_vWh + 4096 + row * 64 + ch);
    }
    __syncthreads();   // the ONLY block-wide barrier

    // z1 = sr(d @ Vl1^T), warp-local rows
    for (int i = lane; i < 1024; i += 32) {
        int p = r0 + (i >> 6), j = i & 63;
        float v = sr(sd[2 * p] * sVl1[2 * j] + sd[2 * p + 1] * sVl1[2 * j + 1]);
        float h = hfrt(v);
        *(__half*)(smb + V_AHI + p * SZB + 2 * j) = __float2half_rn(v);
        *(__half*)(smb + V_ALO + p * SZB + 2 * j) = __float2half_rn(v - h);
    }
    __syncwarp();

    const uint32_t su   = smem_u32(smb);
    const uint32_t aoff = (uint32_t)((r0 + (lane & 7) + ((lane >> 3) & 1) * 8) * SZB
                                     + ((lane >> 4) & 1) * 16);
    const uint32_t wf   = (uint32_t)(((lane & 7) + ((lane >> 4) & 1) * 8) * SZB
                                     + ((lane >> 3) & 1) * 16);
    const uint32_t wt   = (uint32_t)(((lane & 7) + ((lane >> 3) & 1) * 8) * SZB
                                     + ((lane >> 4) & 1) * 16);

    const float dA0 = sd[2 * rA], dA1 = sd[2 * rA + 1];
    const float dB0 = sd[2 * rB], dB1 = sd[2 * rB + 1];
    float acc[8][4];

    // ---- z2 = sr(d@V2x^T + z1@V2z^T) -> B tile ----
    #pragma unroll
    for (int q = 0; q < 8; q++) { acc[q][0] = acc[q][1] = acc[q][2] = acc[q][3] = 0.f; }
    gemm64<false>(acc, su + V_AHI + aoff, su + V_ALO + aoff, su + V_W2H + wf);
    #pragma unroll
    for (int q = 0; q < 8; q++) {
        int c = q * 8 + 2 * tig;
        float v0 = sr(acc[q][0] + dA0 * sV2x[2 * c]     + dA1 * sV2x[2 * c + 1]);
        float v1 = sr(acc[q][1] + dA0 * sV2x[2 * c + 2] + dA1 * sV2x[2 * c + 3]);
        float v2 = sr(acc[q][2] + dB0 * sV2x[2 * c]     + dB1 * sV2x[2 * c + 1]);
        float v3 = sr(acc[q][3] + dB0 * sV2x[2 * c + 2] + dB1 * sV2x[2 * c + 3]);
        uint32_t hA = packhf(v0, v1), hB = packhf(v2, v3);
        float2 ha = unpackhf(hA), hb = unpackhf(hB);
        *(uint32_t*)(smb + V_BHI + rA * SZB + 2 * c) = hA;
        *(uint32_t*)(smb + V_BLO + rA * SZB + 2 * c) = packhf(v0 - ha.x, v1 - ha.y);
        *(uint32_t*)(smb + V_BHI + rB * SZB + 2 * c) = hB;
        *(uint32_t*)(smb + V_BLO + rB * SZB + 2 * c) = packhf(v2 - hb.x, v3 - hb.y);
    }
    __syncwarp();

    // ---- z3 (regs) + zf/gf/V + g3 -> A tile ----
    #pragma unroll
    for (int q = 0; q < 8; q++) { acc[q][0] = acc[q][1] = acc[q][2] = acc[q][3] = 0.f; }
    gemm64<false>(acc, su + V_BHI + aoff, su + V_BLO + aoff, su + V_W3H + wf);
    float zfA = 0.f, zfB = 0.f;
    #pragma unroll
    for (int q = 0; q < 8; q++) {
        int c = q * 8 + 2 * tig;
        acc[q][0] = sr(acc[q][0] + dA0 * sV3x[2 * c]     + dA1 * sV3x[2 * c + 1]);
        acc[q][1] = sr(acc[q][1] + dA0 * sV3x[2 * c + 2] + dA1 * sV3x[2 * c + 3]);
        acc[q][2] = sr(acc[q][2] + dB0 * sV3x[2 * c]     + dB1 * sV3x[2 * c + 1]);
        acc[q][3] = sr(acc[q][3] + dB0 * sV3x[2 * c + 2] + dB1 * sV3x[2 * c + 3]);
        zfA += sVfz[c] * acc[q][0] + sVfz[c + 1] * acc[q][1];
        zfB += sVfz[c] * acc[q][2] + sVfz[c + 1] * acc[q][3];
    }
    zfA += __shfl_xor_sync(0xFFFFFFFFu, zfA, 1);
    zfA += __shfl_xor_sync(0xFFFFFFFFu, zfA, 2);
    zfB += __shfl_xor_sync(0xFFFFFFFFu, zfB, 1);
    zfB += __shfl_xor_sync(0xFFFFFFFFu, zfB, 2);
    const float vfx0 = Vfx[0], vfx1 = Vfx[1];
    float afA = zfA + dA0 * vfx0 + dA1 * vfx1;
    float afB = zfB + dB0 * vfx0 + dB1 * vfx1;
    float zA = sr(afA), zB = sr(afB);
    float gfA = srp(zA) * srp(afA);
    float gfB = srp(zB) * srp(afB);
    if (tig == 0) {
        int gA = base + rA, gB = base + rB;
        if (gA < n) g_V[gA] = sr(zA) + TOLC * (dA0 * dA0 + dA1 * dA1);
        if (gB < n) g_V[gB] = sr(zB) + TOLC * (dB0 * dB0 + dB1 * dB1);
    }
    float gvA0 = 0.f, gvA1 = 0.f, gvB0 = 0.f, gvB1 = 0.f;
    #pragma unroll
    for (int q = 0; q < 8; q++) {
        int c = q * 8 + 2 * tig;
        float g0 = gfA * sVfz[c]     * srp_out(acc[q][0]);
        float g1 = gfA * sVfz[c + 1] * srp_out(acc[q][1]);
        float g2 = gfB * sVfz[c]     * srp_out(acc[q][2]);
        float g3 = gfB * sVfz[c + 1] * srp_out(acc[q][3]);
        gvA0 += g0 * sV3x[2 * c]     + g1 * sV3x[2 * c + 2];
        gvA1 += g0 * sV3x[2 * c + 1] + g1 * sV3x[2 * c + 3];
        gvB0 += g2 * sV3x[2 * c]     + g3 * sV3x[2 * c + 2];
        gvB1 += g2 * sV3x[2 * c + 1] + g3 * sV3x[2 * c + 3];
        uint32_t hA = packhf(g0, g1), hB = packhf(g2, g3);
        float2 ha = unpackhf(hA), hb = unpackhf(hB);
        *(uint32_t*)(smb + V_AHI + rA * SZB + 2 * c) = hA;
        *(uint32_t*)(smb + V_ALO + rA * SZB + 2 * c) = packhf(g0 - ha.x, g1 - ha.y);
        *(uint32_t*)(smb + V_AHI + rB * SZB + 2 * c) = hB;
        *(uint32_t*)(smb + V_ALO + rB * SZB + 2 * c) = packhf(g2 - hb.x, g3 - hb.y);
    }
    __syncwarp();

    // ---- g2 = (g3 @ V3z) * srp(z2) ----
    #pragma unroll
    for (int q = 0; q < 8; q++) { acc[q][0] = acc[q][1] = acc[q][2] = acc[q][3] = 0.f; }
    gemm64<true>(acc, su + V_AHI + aoff, su + V_ALO + aoff, su + V_W3H + wt);
    #pragma unroll
    for (int q = 0; q < 8; q++) {
        int c = q * 8 + 2 * tig;
        float2 hA = unpackhf(*(uint32_t*)(smb + V_BHI + rA * SZB + 2 * c));
        float2 lA = unpackhf(*(uint32_t*)(smb + V_BLO + rA * SZB + 2 * c));
        float2 hB = unpackhf(*(uint32_t*)(smb + V_BHI + rB * SZB + 2 * c));
        float2 lB = unpackhf(*(uint32_t*)(smb + V_BLO + rB * SZB + 2 * c));
        float v0 = acc[q][0] * srp_out(hA.x + lA.x);
        float v1 = acc[q][1] * srp_out(hA.y + lA.y);
        float v2 = acc[q][2] * srp_out(hB.x + lB.x);
        float v3 = acc[q][3] * srp_out(hB.y + lB.y);
        gvA0 += v0 * sV2x[2 * c]     + v1 * sV2x[2 * c + 2];
        gvA1 += v0 * sV2x[2 * c + 1] + v1 * sV2x[2 * c + 3];
        gvB0 += v2 * sV2x[2 * c]     + v3 * sV2x[2 * c + 2];
        gvB1 += v2 * sV2x[2 * c + 1] + v3 * sV2x[2 * c + 3];
        uint32_t nhA = packhf(v0, v1), nhB = packhf(v2, v3);
        float2 na = unpackhf(nhA), nb = unpackhf(nhB);
        *(uint32_t*)(smb + V_BHI + rA * SZB + 2 * c) = nhA;
        *(uint32_t*)(smb + V_BLO + rA * SZB + 2 * c) = packhf(v0 - na.x, v1 - na.y);
        *(uint32_t*)(smb + V_BHI + rB * SZB + 2 * c) = nhB;
        *(uint32_t*)(smb + V_BLO + rB * SZB + 2 * c) = packhf(v2 - nb.x, v3 - nb.y);
    }
    __syncwarp();

    // ---- g1 = (g2 @ V2z) * srp(a1); fold into gradV ----
    #pragma unroll
    for (int q = 0; q < 8; q++) { acc[q][0] = acc[q][1] = acc[q][2] = acc[q][3] = 0.f; }
    gemm64<true>(acc, su + V_BHI + aoff, su + V_BLO + aoff, su + V_W2H + wt);
    #pragma unroll
    for (int q = 0; q < 8; q++) {
        int c = q * 8 + 2 * tig;
        float w00 = sVl1[2 * c],     w01 = sVl1[2 * c + 1];
        float w10 = sVl1[2 * c + 2], w11 = sVl1[2 * c + 3];
        float v0 = acc[q][0] * srp(dA0 * w00 + dA1 * w01);
        float v1 = acc[q][1] * srp(dA0 * w10 + dA1 * w11);
        float v2 = acc[q][2] * srp(dB0 * w00 + dB1 * w01);
        float v3 = acc[q][3] * srp(dB0 * w10 + dB1 * w11);
        gvA0 += v0 * w00 + v1 * w10;
        gvA1 += v0 * w01 + v1 * w11;
        gvB0 += v2 * w00 + v3 * w10;
        gvB1 += v2 * w01 + v3 * w11;
    }
    gvA0 += __shfl_xor_sync(0xFFFFFFFFu, gvA0, 1);
    gvA0 += __shfl_xor_sync(0xFFFFFFFFu, gvA0, 2);
    gvA1 += __shfl_xor_sync(0xFFFFFFFFu, gvA1, 1);
    gvA1 += __shfl_xor_sync(0xFFFFFFFFu, gvA1, 2);
    gvB0 += __shfl_xor_sync(0xFFFFFFFFu, gvB0, 1);
    gvB0 += __shfl_xor_sync(0xFFFFFFFFu, gvB0, 2);
    gvB1 += __shfl_xor_sync(0xFFFFFFFFu, gvB1, 1);
    gvB1 += __shfl_xor_sync(0xFFFFFFFFu, gvB1, 2);
    if (tig == 0) {
        int gA = base + rA, gB = base + rB;
        if (gA < n) {
            g_gradV[2 * gA]     = gvA0 + gfA * vfx0 + 2.f * TOLC * dA0;
            g_gradV[2 * gA + 1] = gvA1 + gfA * vfx1 + 2.f * TOLC * dA1;
        }
        if (gB < n) {
            g_gradV[2 * gB]     = gvB0 + gfB * vfx0 + 2.f * TOLC * dB0;
            g_gradV[2 * gB + 1] = gvB1 + gfB * vfx1 + 2.f * TOLC * dB1;
        }
    }
}

// ============================================================================
// Kernel B: f_hat MLP — double-buffered W prefetch, 1 barrier/layer
// ============================================================================
constexpr int TB = 256;
constexpr int ST = 136;                       // fp16 row stride (272 B)
constexpr int ALO_OFF = 0;                    // 34816
constexpr int WHI0    = 34816;                // W buffer 0 (34816)
constexpr int WHI1    = 69632;                // W buffer 1
constexpr int B_MISC  = 104448;
constexpr int SMEMB_BYTES = B_MISC + (256 + 512 + 258 + 384) * 4;   // 110088

__global__ __launch_bounds__(TB, 2)
void fhat_kernel(const float* __restrict__ X,
                 const float* __restrict__ f1w, const float* __restrict__ f1b,
                 const float* __restrict__ f2b, const float* __restrict__ f3b,
                 const float* __restrict__ f4b, const float* __restrict__ f5b,
                 const float* __restrict__ ffw, const float* __restrict__ ffb,
                 float* __restrict__ out, int n)
{
    extern __shared__ __align__(16) char smb[];
    float* mf  = (float*)(smb + B_MISC);
    float* sx  = mf;            // 256
    float* sb4 = mf + 256;      // 512
    float* sff = mf + 768;      // 258
    float* su_ = mf + 1026;     // 384: f1 staging, later sp0/sp1
    float* sp0 = su_;
    float* sp1 = su_ + 128;

    const int t    = threadIdx.x;
    const int wid  = t >> 5;
    const int lane = t & 31;
    const int gid  = lane >> 2;
    const int tig  = lane & 3;
    const int r0   = wid * 16;
    const int base = blockIdx.x * 128;
    const int rA = r0 + gid, rB = rA + 8;

    const uint32_t suB  = smem_u32(smb);
    const uint32_t aOff = (uint32_t)((r0 + (lane & 7) + ((lane >> 3) & 1) * 8) * ST
                                     + ((lane >> 4) & 1) * 8) * 2;
    const uint32_t bOff = (uint32_t)(((lane & 7) + ((lane >> 4) & 1) * 8) * ST
                                     + ((lane >> 3) & 1) * 8) * 2;
    const uint32_t aloB = suB + ALO_OFF + aOff;

    // ---- prologue: prefetch W0 FIRST (overlaps all staging + layer 1) ----
    for (int i = t; i < 2048; i += TB) {
        int j = i >> 4, ch = (i & 15) * 8;
        cpa16(suB + WHI0 + (uint32_t)(j * ST * 2 + ch * 2), g_fWh + j * 128 + ch);
    }
    asm volatile("cp.async.commit_group;" ::: "memory");

    {
        int p = t >> 1, c = t & 1;
        int gi = base + p; if (gi >= n) gi = n - 1;
        sx[t] = X[gi * 2 + c];
    }
    for (int i = t; i < 258; i += TB) sff[i] = (i < 256) ? ffw[i] : ffb[i - 256];
    for (int i = t; i < 384; i += TB) su_[i] = (i < 256) ? f1w[i] : f1b[i - 256];
    {
        const float* Bs[4] = { f2b, f3b, f4b, f5b };
        for (int i = t; i < 512; i += TB) sb4[i] = Bs[i >> 7][i & 127];
    }
    __syncthreads();

    const float xA0 = sx[2 * rA], xA1 = sx[2 * rA + 1];
    const float xB0 = sx[2 * rB], xB1 = sx[2 * rB + 1];

    uint32_t AH[8][4];

    // ---- layer 1 in registers -> AH + A-lo smem (warp-local) ----
    #pragma unroll
    for (int q = 0; q < 16; q++) {
        int c = 8 * q + 2 * tig;
        float w0 = su_[2 * c],     w1 = su_[2 * c + 1], b0 = su_[256 + c];
        float w2 = su_[2 * c + 2], w3 = su_[2 * c + 3], b1 = su_[256 + c + 1];
        float v0 = lrelu(xA0 * w0 + xA1 * w1 + b0);
        float v1 = lrelu(xA0 * w2 + xA1 * w3 + b1);
        float v2 = lrelu(xB0 * w0 + xB1 * w1 + b0);
        float v3 = lrelu(xB0 * w2 + xB1 * w3 + b1);
        int kt = q >> 1, s = (q & 1) * 2;
        uint32_t hA = packhf(v0, v1);
        uint32_t hB = packhf(v2, v3);
        AH[kt][s]     = hA;
        AH[kt][s + 1] = hB;
        float2 ha = unpackhf(hA), hb = unpackhf(hB);
        *(uint32_t*)(smb + ALO_OFF + rA * ST * 2 + 2 * c) = packhf(v0 - ha.x, v1 - ha.y);
        *(uint32_t*)(smb + ALO_OFF + rB * ST * 2 + 2 * c) = packhf(v2 - hb.x, v3 - hb.y);
    }
    __syncwarp();

    #pragma unroll 1
    for (int L = 0; L < 4; L++) {
        // W_L was prefetched earlier; complete it and make visible
        asm volatile("cp.async.wait_group 0;" ::: "memory");
        __syncthreads();   // W_L visible; all warps past mainloop L-1 (alt buffer free)

        // prefetch W_{L+1} into the other buffer (overlaps this layer's compute)
        if (L < 3) {
            const __half* WN = g_fWh + (L + 1) * 16384;
            const uint32_t dst = suB + ((L & 1) ? WHI0 : WHI1);
            for (int i = t; i < 2048; i += TB) {
                int j = i >> 4, ch = (i & 15) * 8;
                cpa16(dst + (uint32_t)(j * ST * 2 + ch * 2), WN + j * 128 + ch);
            }
            asm volatile("cp.async.commit_group;" ::: "memory");
        }

        const uint32_t wHiB = suB + ((L & 1) ? WHI1 : WHI0) + bOff;

        float acc[16][4];
        #pragma unroll
        for (int q = 0; q < 16; q++)
            #pragma unroll
            for (int c = 0; c < 4; c++) acc[q][c] = 0.f;

        #pragma unroll
        for (int kt = 0; kt < 8; kt++) {
            uint32_t al[4];
            ldsm4(al, aloB + kt * 32);
            #pragma unroll
            for (int p = 0; p < 8; p++) {
                uint32_t bh[4];
                ldsm4(bh, wHiB + (uint32_t)(p * 16 * ST * 2) + kt * 32);
                float* c0 = acc[2 * p];
                float* c1 = acc[2 * p + 1];
                mma_hf(c0, AH[kt][0], AH[kt][1], AH[kt][2], AH[kt][3], bh[0], bh[1]);
                mma_hf(c0, al[0], al[1], al[2], al[3], bh[0], bh[1]);
                mma_hf(c1, AH[kt][0], AH[kt][1], AH[kt][2], AH[kt][3], bh[2], bh[3]);
                mma_hf(c1, al[0], al[1], al[2], al[3], bh[2], bh[3]);
            }
        }

        const float* sb = sb4 + L * 128;
        if (L < 3) {
            // epilogue (warp-local A-lo)
            #pragma unroll
            for (int q = 0; q < 16; q++) {
                int c = 8 * q + 2 * tig;
                float v0 = lrelu(acc[q][0] + sb[c]);
                float v1 = lrelu(acc[q][1] + sb[c + 1]);
                float v2 = lrelu(acc[q][2] + sb[c]);
                float v3 = lrelu(acc[q][3] + sb[c + 1]);
                int kt = q >> 1, s = (q & 1) * 2;
                uint32_t hA = packhf(v0, v1);
                uint32_t hB = packhf(v2, v3);
                AH[kt][s]     = hA;
                AH[kt][s + 1] = hB;
                float2 ha = unpackhf(hA), hb = unpackhf(hB);
                *(uint32_t*)(smb + ALO_OFF + rA * ST * 2 + 2 * c) = packhf(v0 - ha.x, v1 - ha.y);
                *(uint32_t*)(smb + ALO_OFF + rB * ST * 2 + 2 * c) = packhf(v2 - hb.x, v3 - hb.y);
            }
            __syncwarp();
        } else {
            float p0 = 0.f, p1 = 0.f, q0 = 0.f, q1 = 0.f;
            #pragma unroll
            for (int q = 0; q < 16; q++) {
                int c = 8 * q + 2 * tig;
                float v0 = lrelu(acc[q][0] + sb[c]);
                float v1 = lrelu(acc[q][1] + sb[c + 1]);
                float v2 = lrelu(acc[q][2] + sb[c]);
                float v3 = lrelu(acc[q][3] + sb[c + 1]);
                p0 = fmaf(v0, sff[c], fmaf(v1, sff[c + 1], p0));
                p1 = fmaf(v0, sff[128 + c], fmaf(v1, sff[129 + c], p1));
                q0 = fmaf(v2, sff[c], fmaf(v3, sff[c + 1], q0));
                q1 = fmaf(v2, sff[128 + c], fmaf(v3, sff[129 + c], q1));
            }
            #pragma unroll
            for (int m = 1; m < 4; m <<= 1) {
                p0 += __shfl_xor_sync(0xFFFFFFFFu, p0, m);
                p1 += __shfl_xor_sync(0xFFFFFFFFu, p1, m);
                q0 += __shfl_xor_sync(0xFFFFFFFFu, q0, m);
                q1 += __shfl_xor_sync(0xFFFFFFFFu, q1, m);
            }
            __syncthreads();   // su_ region free -> sp0/sp1
            if (tig == 0) {
                sp0[rA] = p0;  sp1[rA] = p1;
                sp0[rB] = q0;  sp1[rB] = q1;
            }
            __syncthreads();
        }
    }

    // ---- final projection ----
    if (t < 128) {
        int gi = base + t;
        if (gi < n) {
            float fh0 = sff[256] + sp0[t];
            float fh1 = sff[257] + sp1[t];
            float g0 = g_gradV[2 * gi], g1 = g_gradV[2 * gi + 1];
            float V  = g_V[gi];
            float vn  = g0 * g0 + g1 * g1;
            float num = fh0 * g0 + fh1 * g1 + ALPHAC * V;
            float fm  = (num > 0.f ? num : 0.f) / (vn + EPSC);
            out[2 * gi]     = fh0 - g0 * fm;
            out[2 * gi + 1] = fh1 - g1 * fm;
        }
    }
}

// ============================================================================
extern "C" void kernel_launch(void* const* d_in, const int* in_sizes, int n_in,
                              void* d_out, int out_size)
{
    const float* X   = (const float*)d_in[0];
    const float* Xs  = (const float*)d_in[1];
    const float* Vl1 = (const float*)d_in[2];
    const float* V2x = (const float*)d_in[3];
    const float* V2z = (const float*)d_in[4];
    const float* V3x = (const float*)d_in[5];
    const float* V3z = (const float*)d_in[6];
    const float* Vfx = (const float*)d_in[7];
    const float* Vfz = (const float*)d_in[8];
    const float* f1w = (const float*)d_in[9];
    const float* f1b = (const float*)d_in[10];
    const float* f2w = (const float*)d_in[11];
    const float* f2b = (const float*)d_in[12];
    const float* f3w = (const float*)d_in[13];
    const float* f3b = (const float*)d_in[14];
    const float* f4w = (const float*)d_in[15];
    const float* f4b = (const float*)d_in[16];
    const float* f5w = (const float*)d_in[17];
    const float* f5b = (const float*)d_in[18];
    const float* ffw = (const float*)d_in[19];
    const float* ffb = (const float*)d_in[20];

    int n = in_sizes[0] / 2;
    int grid = (n + 127) / 128;

    cudaFuncSetAttribute(vnet_mma,    cudaFuncAttributeMaxDynamicSharedMemorySize, SMEMV_BYTES);
    cudaFuncSetAttribute(fhat_kernel, cudaFuncAttributeMaxDynamicSharedMemorySize, SMEMB_BYTES);

    setup_w<<<288, 256>>>(f2w, f3w, f4w, f5w, V2z, V3z);

    vnet_mma<<<grid, 256, SMEMV_BYTES>>>(X, Xs, Vl1, V2x, V3x, Vfx, Vfz, n);

    fhat_kernel<<<grid, TB, SMEMB_BYTES>>>(
        X, f1w, f1b, f2b, f3b, f4b, f5b, ffw, ffb, (float*)d_out, n);
}

// round 15
// speedup vs baseline: 3.8995x; 1.3277x over previous
#include <cuda_runtime.h>
#include <cuda_fp16.h>
#include <math.h>
#include <stdint.h>

#define TOLC   0.01f
#define ALPHAC 0.1f
#define SLOPEC 0.01f
#define EPSC   1e-10f

#define NMAX 500096
__device__ float g_gradV[2 * NMAX];
__device__ float g_V[NMAX];
__device__ __half g_fWh[4 * 16384];   // f2..f5 fp16
__device__ __half g_vWh[8192];        // V2z,V3z fp16

__device__ __forceinline__ float sr(float x)  { return x < 0.f ? 0.f : (x < 1.f ? 0.5f * x * x : x - 0.5f); }
__device__ __forceinline__ float srp(float x) { return x < 0.f ? 0.f : (x < 1.f ? x : 1.f); }
__device__ __forceinline__ float srp_out(float z) { return z <= 0.f ? 0.f : (z < 0.5f ? sqrtf(2.f * z) : 1.f); }
__device__ __forceinline__ float lrelu(float x) { return x >= 0.f ? x : SLOPEC * x; }

__device__ __forceinline__ uint32_t packhf(float v0, float v1) {
    uint32_t r; asm("cvt.rn.f16x2.f32 %0, %1, %2;" : "=r"(r) : "f"(v1), "f"(v0)); return r;
}
__device__ __forceinline__ float hfrt(float v) { return __half2float(__float2half_rn(v)); }
__device__ __forceinline__ float2 unpackhf(uint32_t u) {
    __half2 h = *reinterpret_cast<__half2*>(&u);
    return __half22float2(h);
}
__device__ __forceinline__ uint32_t smem_u32(const void* p) {
    uint32_t a;
    asm("{ .reg .u64 t; cvta.to.shared.u64 t, %1; cvt.u32.u64 %0, t; }" : "=r"(a) : "l"(p));
    return a;
}
__device__ __forceinline__ void cpa16(uint32_t s, const void* g) {
    asm volatile("cp.async.cg.shared.global [%0], [%1], 16;" :: "r"(s), "l"(g));
}
__device__ __forceinline__ void ldsm4(uint32_t* r, uint32_t addr) {
    asm volatile("ldmatrix.sync.aligned.m8n8.x4.shared.b16 {%0,%1,%2,%3}, [%4];"
                 : "=r"(r[0]), "=r"(r[1]), "=r"(r[2]), "=r"(r[3]) : "r"(addr));
}
__device__ __forceinline__ void ldsm4t(uint32_t* r, uint32_t addr) {
    asm volatile("ldmatrix.sync.aligned.m8n8.x4.trans.shared.b16 {%0,%1,%2,%3}, [%4];"
                 : "=r"(r[0]), "=r"(r[1]), "=r"(r[2]), "=r"(r[3]) : "r"(addr));
}
__device__ __forceinline__ void mma_hf(float* c,
                                       uint32_t a0, uint32_t a1, uint32_t a2, uint32_t a3,
                                       uint32_t b0, uint32_t b1) {
    asm volatile("mma.sync.aligned.m16n8k16.row.col.f32.f16.f16.f32 "
                 "{%0,%1,%2,%3}, {%4,%5,%6,%7}, {%8,%9}, {%0,%1,%2,%3};"
                 : "+f"(c[0]), "+f"(c[1]), "+f"(c[2]), "+f"(c[3])
                 : "r"(a0), "r"(a1), "r"(a2), "r"(a3), "r"(b0), "r"(b1));
}

// ============================================================================
// Setup: convert weights to fp16 globals
// ============================================================================
__global__ void setup_w(const float* __restrict__ f2w, const float* __restrict__ f3w,
                        const float* __restrict__ f4w, const float* __restrict__ f5w,
                        const float* __restrict__ V2z, const float* __restrict__ V3z)
{
    int i = blockIdx.x * blockDim.x + threadIdx.x;
    if (i < 65536) {
        const float* W = (i < 32768) ? ((i < 16384) ? f2w : f3w)
                                     : ((i < 49152) ? f4w : f5w);
        g_fWh[i] = __float2half_rn(W[i & 16383]);
    } else if (i < 73728) {
        int j = i - 65536;
        g_vWh[j] = __float2half_rn((j < 4096) ? V2z[j] : V3z[j - 4096]);
    }
}

// ============================================================================
// Kernel A: ICNN V + VJP — exact-A fp16 split x fp16 W (proven round-14)
// ============================================================================
constexpr int SZB = 144;
constexpr int VT  = 128 * SZB;
constexpr int VW  = 64 * SZB;
constexpr int V_AHI = 0, V_ALO = VT, V_BHI = 2 * VT, V_BLO = 3 * VT;
constexpr int V_W2H = 4 * VT, V_W3H = 4 * VT + VW;
constexpr int V_MISC = 4 * VT + 2 * VW;
constexpr int SMEMV_BYTES = V_MISC + 704 * 4;

template<bool TR>
__device__ __forceinline__ void gemm64(float (&acc)[8][4], uint32_t aHi, uint32_t aLo,
                                       uint32_t wHi)
{
    #pragma unroll
    for (int kt = 0; kt < 4; kt++) {
        uint32_t ah[4], al[4];
        ldsm4(ah, aHi + kt * 32);
        ldsm4(al, aLo + kt * 32);
        #pragma unroll
        for (int p = 0; p < 4; p++) {
            uint32_t off = TR ? (uint32_t)(kt * 16 * SZB + p * 32)
                              : (uint32_t)(p * 16 * SZB + kt * 32);
            uint32_t bh[4];
            if (TR) ldsm4t(bh, wHi + off);
            else    ldsm4 (bh, wHi + off);
            float* c0 = acc[2 * p];
            float* c1 = acc[2 * p + 1];
            mma_hf(c0, ah[0], ah[1], ah[2], ah[3], bh[0], bh[1]);
            mma_hf(c0, al[0], al[1], al[2], al[3], bh[0], bh[1]);
            mma_hf(c1, ah[0], ah[1], ah[2], ah[3], bh[2], bh[3]);
            mma_hf(c1, al[0], al[1], al[2], al[3], bh[2], bh[3]);
        }
    }
}

__global__ __launch_bounds__(256, 2)
void vnet_mma(const float* __restrict__ X,   const float* __restrict__ Xs,
              const float* __restrict__ Vl1, const float* __restrict__ V2x,
              const float* __restrict__ V3x, const float* __restrict__ Vfx,
              const float* __restrict__ Vfz, int n)
{
    extern __shared__ __align__(16) char smb[];
    float* mf   = (float*)(smb + V_MISC);
    float* sd   = mf;
    float* sVfz = mf + 256;
    float* sV2x = mf + 320;
    float* sV3x = mf + 448;
    float* sVl1 = mf + 576;

    const int t    = threadIdx.x;
    const int wid  = t >> 5;
    const int lane = t & 31;
    const int gid  = lane >> 2;
    const int tig  = lane & 3;
    const int r0   = wid * 16;
    const int base = blockIdx.x * 128;
    const int rA = r0 + gid, rB = rA + 8;

    {
        int p = t >> 1, c = t & 1;
        int gi = base + p; if (gi >= n) gi = n - 1;
        sd[t] = X[gi * 2 + c] - Xs[gi * 2 + c];
    }
    if (t < 64)  sVfz[t] = Vfz[t];
    if (t < 128) { sV2x[t] = V2x[t]; sV3x[t] = V3x[t]; sVl1[t] = Vl1[t]; }
    for (int i = t; i < 512; i += 256) {
        int row = i >> 3, ch = (i & 7) * 8;
        *(uint4*)(smb + V_W2H + row * SZB + ch * 2) = *(const uint4*)(g_vWh + row * 64 + ch);
        *(uint4*)(smb + V_W3H + row * SZB + ch * 2) = *(const uint4*)(g_vWh + 4096 + row * 64 + ch);
    }
    __syncthreads();

    for (int i = lane; i < 1024; i += 32) {
        int p = r0 + (i >> 6), j = i & 63;
        float v = sr(sd[2 * p] * sVl1[2 * j] + sd[2 * p + 1] * sVl1[2 * j + 1]);
        float h = hfrt(v);
        *(__half*)(smb + V_AHI + p * SZB + 2 * j) = __float2half_rn(v);
        *(__half*)(smb + V_ALO + p * SZB + 2 * j) = __float2half_rn(v - h);
    }
    __syncwarp();

    const uint32_t su   = smem_u32(smb);
    const uint32_t aoff = (uint32_t)((r0 + (lane & 7) + ((lane >> 3) & 1) * 8) * SZB
                                     + ((lane >> 4) & 1) * 16);
    const uint32_t wf   = (uint32_t)(((lane & 7) + ((lane >> 4) & 1) * 8) * SZB
                                     + ((lane >> 3) & 1) * 16);
    const uint32_t wt   = (uint32_t)(((lane & 7) + ((lane >> 3) & 1) * 8) * SZB
                                     + ((lane >> 4) & 1) * 16);

    const float dA0 = sd[2 * rA], dA1 = sd[2 * rA + 1];
    const float dB0 = sd[2 * rB], dB1 = sd[2 * rB + 1];
    float acc[8][4];

    #pragma unroll
    for (int q = 0; q < 8; q++) { acc[q][0] = acc[q][1] = acc[q][2] = acc[q][3] = 0.f; }
    gemm64<false>(acc, su + V_AHI + aoff, su + V_ALO + aoff, su + V_W2H + wf);
    #pragma unroll
    for (int q = 0; q < 8; q++) {
        int c = q * 8 + 2 * tig;
        float v0 = sr(acc[q][0] + dA0 * sV2x[2 * c]     + dA1 * sV2x[2 * c + 1]);
        float v1 = sr(acc[q][1] + dA0 * sV2x[2 * c + 2] + dA1 * sV2x[2 * c + 3]);
        float v2 = sr(acc[q][2] + dB0 * sV2x[2 * c]     + dB1 * sV2x[2 * c + 1]);
        float v3 = sr(acc[q][3] + dB0 * sV2x[2 * c + 2] + dB1 * sV2x[2 * c + 3]);
        uint32_t hA = packhf(v0, v1), hB = packhf(v2, v3);
        float2 ha = unpackhf(hA), hb = unpackhf(hB);
        *(uint32_t*)(smb + V_BHI + rA * SZB + 2 * c) = hA;
        *(uint32_t*)(smb + V_BLO + rA * SZB + 2 * c) = packhf(v0 - ha.x, v1 - ha.y);
        *(uint32_t*)(smb + V_BHI + rB * SZB + 2 * c) = hB;
        *(uint32_t*)(smb + V_BLO + rB * SZB + 2 * c) = packhf(v2 - hb.x, v3 - hb.y);
    }
    __syncwarp();

    #pragma unroll
    for (int q = 0; q < 8; q++) { acc[q][0] = acc[q][1] = acc[q][2] = acc[q][3] = 0.f; }
    gemm64<false>(acc, su + V_BHI + aoff, su + V_BLO + aoff, su + V_W3H + wf);
    float zfA = 0.f, zfB = 0.f;
    #pragma unroll
    for (int q = 0; q < 8; q++) {
        int c = q * 8 + 2 * tig;
        acc[q][0] = sr(acc[q][0] + dA0 * sV3x[2 * c]     + dA1 * sV3x[2 * c + 1]);
        acc[q][1] = sr(acc[q][1] + dA0 * sV3x[2 * c + 2] + dA1 * sV3x[2 * c + 3]);
        acc[q][2] = sr(acc[q][2] + dB0 * sV3x[2 * c]     + dB1 * sV3x[2 * c + 1]);
        acc[q][3] = sr(acc[q][3] + dB0 * sV3x[2 * c + 2] + dB1 * sV3x[2 * c + 3]);
        zfA += sVfz[c] * acc[q][0] + sVfz[c + 1] * acc[q][1];
        zfB += sVfz[c] * acc[q][2] + sVfz[c + 1] * acc[q][3];
    }
    zfA += __shfl_xor_sync(0xFFFFFFFFu, zfA, 1);
    zfA += __shfl_xor_sync(0xFFFFFFFFu, zfA, 2);
    zfB += __shfl_xor_sync(0xFFFFFFFFu, zfB, 1);
    zfB += __shfl_xor_sync(0xFFFFFFFFu, zfB, 2);
    const float vfx0 = Vfx[0], vfx1 = Vfx[1];
    float afA = zfA + dA0 * vfx0 + dA1 * vfx1;
    float afB = zfB + dB0 * vfx0 + dB1 * vfx1;
    float zA = sr(afA), zB = sr(afB);
    float gfA = srp(zA) * srp(afA);
    float gfB = srp(zB) * srp(afB);
    if (tig == 0) {
        int gA = base + rA, gB = base + rB;
        if (gA < n) g_V[gA] = sr(zA) + TOLC * (dA0 * dA0 + dA1 * dA1);
        if (gB < n) g_V[gB] = sr(zB) + TOLC * (dB0 * dB0 + dB1 * dB1);
    }
    float gvA0 = 0.f, gvA1 = 0.f, gvB0 = 0.f, gvB1 = 0.f;
    #pragma unroll
    for (int q = 0; q < 8; q++) {
        int c = q * 8 + 2 * tig;
        float g0 = gfA * sVfz[c]     * srp_out(acc[q][0]);
        float g1 = gfA * sVfz[c + 1] * srp_out(acc[q][1]);
        float g2 = gfB * sVfz[c]     * srp_out(acc[q][2]);
        float g3 = gfB * sVfz[c + 1] * srp_out(acc[q][3]);
        gvA0 += g0 * sV3x[2 * c]     + g1 * sV3x[2 * c + 2];
        gvA1 += g0 * sV3x[2 * c + 1] + g1 * sV3x[2 * c + 3];
        gvB0 += g2 * sV3x[2 * c]     + g3 * sV3x[2 * c + 2];
        gvB1 += g2 * sV3x[2 * c + 1] + g3 * sV3x[2 * c + 3];
        uint32_t hA = packhf(g0, g1), hB = packhf(g2, g3);
        float2 ha = unpackhf(hA), hb = unpackhf(hB);
        *(uint32_t*)(smb + V_AHI + rA * SZB + 2 * c) = hA;
        *(uint32_t*)(smb + V_ALO + rA * SZB + 2 * c) = packhf(g0 - ha.x, g1 - ha.y);
        *(uint32_t*)(smb + V_AHI + rB * SZB + 2 * c) = hB;
        *(uint32_t*)(smb + V_ALO + rB * SZB + 2 * c) = packhf(g2 - hb.x, g3 - hb.y);
    }
    __syncwarp();

    #pragma unroll
    for (int q = 0; q < 8; q++) { acc[q][0] = acc[q][1] = acc[q][2] = acc[q][3] = 0.f; }
    gemm64<true>(acc, su + V_AHI + aoff, su + V_ALO + aoff, su + V_W3H + wt);
    #pragma unroll
    for (int q = 0; q < 8; q++) {
        int c = q * 8 + 2 * tig;
        float2 hA = unpackhf(*(uint32_t*)(smb + V_BHI + rA * SZB + 2 * c));
        float2 lA = unpackhf(*(uint32_t*)(smb + V_BLO + rA * SZB + 2 * c));
        float2 hB = unpackhf(*(uint32_t*)(smb + V_BHI + rB * SZB + 2 * c));
        float2 lB = unpackhf(*(uint32_t*)(smb + V_BLO + rB * SZB + 2 * c));
        float v0 = acc[q][0] * srp_out(hA.x + lA.x);
        float v1 = acc[q][1] * srp_out(hA.y + lA.y);
        float v2 = acc[q][2] * srp_out(hB.x + lB.x);
        float v3 = acc[q][3] * srp_out(hB.y + lB.y);
        gvA0 += v0 * sV2x[2 * c]     + v1 * sV2x[2 * c + 2];
        gvA1 += v0 * sV2x[2 * c + 1] + v1 * sV2x[2 * c + 3];
        gvB0 += v2 * sV2x[2 * c]     + v3 * sV2x[2 * c + 2];
        gvB1 += v2 * sV2x[2 * c + 1] + v3 * sV2x[2 * c + 3];
        uint32_t nhA = packhf(v0, v1), nhB = packhf(v2, v3);
        float2 na = unpackhf(nhA), nb = unpackhf(nhB);
        *(uint32_t*)(smb + V_BHI + rA * SZB + 2 * c) = nhA;
        *(uint32_t*)(smb + V_BLO + rA * SZB + 2 * c) = packhf(v0 - na.x, v1 - na.y);
        *(uint32_t*)(smb + V_BHI + rB * SZB + 2 * c) = nhB;
        *(uint32_t*)(smb + V_BLO + rB * SZB + 2 * c) = packhf(v2 - nb.x, v3 - nb.y);
    }
    __syncwarp();

    #pragma unroll
    for (int q = 0; q < 8; q++) { acc[q][0] = acc[q][1] = acc[q][2] = acc[q][3] = 0.f; }
    gemm64<true>(acc, su + V_BHI + aoff, su + V_BLO + aoff, su + V_W2H + wt);
    #pragma unroll
    for (int q = 0; q < 8; q++) {
        int c = q * 8 + 2 * tig;
        float w00 = sVl1[2 * c],     w01 = sVl1[2 * c + 1];
        float w10 = sVl1[2 * c + 2], w11 = sVl1[2 * c + 3];
        float v0 = acc[q][0] * srp(dA0 * w00 + dA1 * w01);
        float v1 = acc[q][1] * srp(dA0 * w10 + dA1 * w11);
        float v2 = acc[q][2] * srp(dB0 * w00 + dB1 * w01);
        float v3 = acc[q][3] * srp(dB0 * w10 + dB1 * w11);
        gvA0 += v0 * w00 + v1 * w10;
        gvA1 += v0 * w01 + v1 * w11;
        gvB0 += v2 * w00 + v3 * w10;
        gvB1 += v2 * w01 + v3 * w11;
    }
    gvA0 += __shfl_xor_sync(0xFFFFFFFFu, gvA0, 1);
    gvA0 += __shfl_xor_sync(0xFFFFFFFFu, gvA0, 2);
    gvA1 += __shfl_xor_sync(0xFFFFFFFFu, gvA1, 1);
    gvA1 += __shfl_xor_sync(0xFFFFFFFFu, gvA1, 2);
    gvB0 += __shfl_xor_sync(0xFFFFFFFFu, gvB0, 1);
    gvB0 += __shfl_xor_sync(0xFFFFFFFFu, gvB0, 2);
    gvB1 += __shfl_xor_sync(0xFFFFFFFFu, gvB1, 1);
    gvB1 += __shfl_xor_sync(0xFFFFFFFFu, gvB1, 2);
    if (tig == 0) {
        int gA = base + rA, gB = base + rB;
        if (gA < n) {
            g_gradV[2 * gA]     = gvA0 + gfA * vfx0 + 2.f * TOLC * dA0;
            g_gradV[2 * gA + 1] = gvA1 + gfA * vfx1 + 2.f * TOLC * dA1;
        }
        if (gB < n) {
            g_gradV[2 * gB]     = gvB0 + gfB * vfx0 + 2.f * TOLC * dB0;
            g_gradV[2 * gB + 1] = gvB1 + gfB * vfx1 + 2.f * TOLC * dB1;
        }
    }
}

// ============================================================================
// Kernel B: f_hat MLP — A entirely fp16 in registers (no A smem at all),
// double-buffered fp16 W. 2 MMA + 8 B-LDSM per kt.
// ============================================================================
constexpr int TB = 256;
constexpr int ST = 136;                       // fp16 row stride (272 B)
constexpr int WHI0    = 0;                    // 34816
constexpr int WHI1    = 34816;
constexpr int B_MISC  = 69632;
constexpr int SMEMB_BYTES = B_MISC + (256 + 512 + 258 + 384) * 4;   // 75272

__global__ __launch_bounds__(TB, 2)
void fhat_kernel(const float* __restrict__ X,
                 const float* __restrict__ f1w, const float* __restrict__ f1b,
                 const float* __restrict__ f2b, const float* __restrict__ f3b,
                 const float* __restrict__ f4b, const float* __restrict__ f5b,
                 const float* __restrict__ ffw, const float* __restrict__ ffb,
                 float* __restrict__ out, int n)
{
    extern __shared__ __align__(16) char smb[];
    float* mf  = (float*)(smb + B_MISC);
    float* sx  = mf;            // 256
    float* sb4 = mf + 256;      // 512
    float* sff = mf + 768;      // 258
    float* su_ = mf + 1026;     // 384: f1 staging, later sp0/sp1
    float* sp0 = su_;
    float* sp1 = su_ + 128;

    const int t    = threadIdx.x;
    const int lane = t & 31;
    const int gid  = lane >> 2;
    const int tig  = lane & 3;
    const int r0   = (t >> 5) * 16;
    const int base = blockIdx.x * 128;
    const int rA = r0 + gid, rB = rA + 8;

    const uint32_t suB  = smem_u32(smb);
    const uint32_t bOff = (uint32_t)(((lane & 7) + ((lane >> 4) & 1) * 8) * ST
                                     + ((lane >> 3) & 1) * 8) * 2;

    // prefetch W0 first
    for (int i = t; i < 2048; i += TB) {
        int j = i >> 4, ch = (i & 15) * 8;
        cpa16(suB + WHI0 + (uint32_t)(j * ST * 2 + ch * 2), g_fWh + j * 128 + ch);
    }
    asm volatile("cp.async.commit_group;" ::: "memory");

    {
        int p = t >> 1, c = t & 1;
        int gi = base + p; if (gi >= n) gi = n - 1;
        sx[t] = X[gi * 2 + c];
    }
    for (int i = t; i < 258; i += TB) sff[i] = (i < 256) ? ffw[i] : ffb[i - 256];
    for (int i = t; i < 384; i += TB) su_[i] = (i < 256) ? f1w[i] : f1b[i - 256];
    {
        const float* Bs[4] = { f2b, f3b, f4b, f5b };
        for (int i = t; i < 512; i += TB) sb4[i] = Bs[i >> 7][i & 127];
    }
    __syncthreads();

    const float xA0 = sx[2 * rA], xA1 = sx[2 * rA + 1];
    const float xB0 = sx[2 * rB], xB1 = sx[2 * rB + 1];

    uint32_t AH[8][4];   // full A (fp16) in registers

    // ---- layer 1 -> AH only ----
    #pragma unroll
    for (int q = 0; q < 16; q++) {
        int c = 8 * q + 2 * tig;
        float w0 = su_[2 * c],     w1 = su_[2 * c + 1], b0 = su_[256 + c];
        float w2 = su_[2 * c + 2], w3 = su_[2 * c + 3], b1 = su_[256 + c + 1];
        float v0 = lrelu(xA0 * w0 + xA1 * w1 + b0);
        float v1 = lrelu(xA0 * w2 + xA1 * w3 + b1);
        float v2 = lrelu(xB0 * w0 + xB1 * w1 + b0);
        float v3 = lrelu(xB0 * w2 + xB1 * w3 + b1);
        int kt = q >> 1, s = (q & 1) * 2;
        AH[kt][s]     = packhf(v0, v1);
        AH[kt][s + 1] = packhf(v2, v3);
    }

    #pragma unroll 1
    for (int L = 0; L < 4; L++) {
        asm volatile("cp.async.wait_group 0;" ::: "memory");
        __syncthreads();   // W_L visible; alt buffer free

        if (L < 3) {
            const __half* WN = g_fWh + (L + 1) * 16384;
            const uint32_t dst = suB + ((L & 1) ? WHI0 : WHI1);
            for (int i = t; i < 2048; i += TB) {
                int j = i >> 4, ch = (i & 15) * 8;
                cpa16(dst + (uint32_t)(j * ST * 2 + ch * 2), WN + j * 128 + ch);
            }
            asm volatile("cp.async.commit_group;" ::: "memory");
        }

        const uint32_t wHiB = suB + ((L & 1) ? WHI1 : WHI0) + bOff;

        float acc[16][4];
        #pragma unroll
        for (int q = 0; q < 16; q++)
            #pragma unroll
            for (int c = 0; c < 4; c++) acc[q][c] = 0.f;

        #pragma unroll
        for (int kt = 0; kt < 8; kt++) {
            #pragma unroll
            for (int p = 0; p < 8; p++) {
                uint32_t bh[4];
                ldsm4(bh, wHiB + (uint32_t)(p * 16 * ST * 2) + kt * 32);
                mma_hf(acc[2 * p],     AH[kt][0], AH[kt][1], AH[kt][2], AH[kt][3], bh[0], bh[1]);
                mma_hf(acc[2 * p + 1], AH[kt][0], AH[kt][1], AH[kt][2], AH[kt][3], bh[2], bh[3]);
            }
        }

        const float* sb = sb4 + L * 128;
        if (L < 3) {
            #pragma unroll
            for (int q = 0; q < 16; q++) {
                int c = 8 * q + 2 * tig;
                float v0 = lrelu(acc[q][0] + sb[c]);
                float v1 = lrelu(acc[q][1] + sb[c + 1]);
                float v2 = lrelu(acc[q][2] + sb[c]);
                float v3 = lrelu(acc[q][3] + sb[c + 1]);
                int kt = q >> 1, s = (q & 1) * 2;
                AH[kt][s]     = packhf(v0, v1);
                AH[kt][s + 1] = packhf(v2, v3);
            }
        } else {
            float p0 = 0.f, p1 = 0.f, q0 = 0.f, q1 = 0.f;
            #pragma unroll
            for (int q = 0; q < 16; q++) {
                int c = 8 * q + 2 * tig;
                float v0 = lrelu(acc[q][0] + sb[c]);
                float v1 = lrelu(acc[q][1] + sb[c + 1]);
                float v2 = lrelu(acc[q][2] + sb[c]);
                float v3 = lrelu(acc[q][3] + sb[c + 1]);
                p0 = fmaf(v0, sff[c], fmaf(v1, sff[c + 1], p0));
                p1 = fmaf(v0, sff[128 + c], fmaf(v1, sff[129 + c], p1));
                q0 = fmaf(v2, sff[c], fmaf(v3, sff[c + 1], q0));
                q1 = fmaf(v2, sff[128 + c], fmaf(v3, sff[129 + c], q1));
            }
            #pragma unroll
            for (int m = 1; m < 4; m <<= 1) {
                p0 += __shfl_xor_sync(0xFFFFFFFFu, p0, m);
                p1 += __shfl_xor_sync(0xFFFFFFFFu, p1, m);
                q0 += __shfl_xor_sync(0xFFFFFFFFu, q0, m);
                q1 += __shfl_xor_sync(0xFFFFFFFFu, q1, m);
            }
            __syncthreads();   // su_ region free -> sp0/sp1
            if (tig == 0) {
                sp0[rA] = p0;  sp1[rA] = p1;
                sp0[rB] = q0;  sp1[rB] = q1;
            }
            __syncthreads();
        }
    }

    // ---- final projection ----
    if (t < 128) {
        int gi = base + t;
        if (gi < n) {
            float fh0 = sff[256] + sp0[t];
            float fh1 = sff[257] + sp1[t];
            float g0 = g_gradV[2 * gi], g1 = g_gradV[2 * gi + 1];
            float V  = g_V[gi];
            float vn  = g0 * g0 + g1 * g1;
            float num = fh0 * g0 + fh1 * g1 + ALPHAC * V;
            float fm  = (num > 0.f ? num : 0.f) / (vn + EPSC);
            out[2 * gi]     = fh0 - g0 * fm;
            out[2 * gi + 1] = fh1 - g1 * fm;
        }
    }
}

// ============================================================================
extern "C" void kernel_launch(void* const* d_in, const int* in_sizes, int n_in,
                              void* d_out, int out_size)
{
    const float* X   = (const float*)d_in[0];
    const float* Xs  = (const float*)d_in[1];
    const float* Vl1 = (const float*)d_in[2];
    const float* V2x = (const float*)d_in[3];
    const float* V2z = (const float*)d_in[4];
    const float* V3x = (const float*)d_in[5];
    const float* V3z = (const float*)d_in[6];
    const float* Vfx = (const float*)d_in[7];
    const float* Vfz = (const float*)d_in[8];
    const float* f1w = (const float*)d_in[9];
    const float* f1b = (const float*)d_in[10];
    const float* f2w = (const float*)d_in[11];
    const float* f2b = (const float*)d_in[12];
    const float* f3w = (const float*)d_in[13];
    const float* f3b = (const float*)d_in[14];
    const float* f4w = (const float*)d_in[15];
    const float* f4b = (const float*)d_in[16];
    const float* f5w = (const float*)d_in[17];
    const float* f5b = (const float*)d_in[18];
    const float* ffw = (const float*)d_in[19];
    const float* ffb = (const float*)d_in[20];

    int n = in_sizes[0] / 2;
    int grid = (n + 127) / 128;

    cudaFuncSetAttribute(vnet_mma,    cudaFuncAttributeMaxDynamicSharedMemorySize, SMEMV_BYTES);
    cudaFuncSetAttribute(fhat_kernel, cudaFuncAttributeMaxDynamicSharedMemorySize, SMEMB_BYTES);

    setup_w<<<288, 256>>>(f2w, f3w, f4w, f5w, V2z, V3z);

    vnet_mma<<<grid, 256, SMEMV_BYTES>>>(X, Xs, Vl1, V2x, V3x, Vfx, Vfz, n);

    fhat_kernel<<<grid, TB, SMEMB_BYTES>>>(
        X, f1w, f1b, f2b, f3b, f4b, f5b, ffw, ffb, (float*)d_out, n);
}

// round 16
// speedup vs baseline: 4.5514x; 1.1672x over previous
#include <cuda_runtime.h>
#include <cuda_fp16.h>
#include <math.h>
#include <stdint.h>

#define TOLC   0.01f
#define ALPHAC 0.1f
#define SLOPEC 0.01f
#define EPSC   1e-10f

#define NMAX 500096
__device__ float g_gradV[2 * NMAX];
__device__ float g_V[NMAX];
__device__ __half g_fWh[4 * 16384];   // f2..f5 fp16
__device__ __half g_vWh[8192];        // V2z,V3z fp16

__device__ __forceinline__ float sr(float x)  { return x < 0.f ? 0.f : (x < 1.f ? 0.5f * x * x : x - 0.5f); }
__device__ __forceinline__ float srp(float x) { return x < 0.f ? 0.f : (x < 1.f ? x : 1.f); }
__device__ __forceinline__ float srp_out(float z) { return z <= 0.f ? 0.f : (z < 0.5f ? sqrtf(2.f * z) : 1.f); }
__device__ __forceinline__ float lrelu(float x) { return x >= 0.f ? x : SLOPEC * x; }

__device__ __forceinline__ uint32_t packhf(float v0, float v1) {
    uint32_t r; asm("cvt.rn.f16x2.f32 %0, %1, %2;" : "=r"(r) : "f"(v1), "f"(v0)); return r;
}
__device__ __forceinline__ float2 unpackhf(uint32_t u) {
    __half2 h = *reinterpret_cast<__half2*>(&u);
    return __half22float2(h);
}
__device__ __forceinline__ uint32_t smem_u32(const void* p) {
    uint32_t a;
    asm("{ .reg .u64 t; cvta.to.shared.u64 t, %1; cvt.u32.u64 %0, t; }" : "=r"(a) : "l"(p));
    return a;
}
__device__ __forceinline__ void cpa16(uint32_t s, const void* g) {
    asm volatile("cp.async.cg.shared.global [%0], [%1], 16;" :: "r"(s), "l"(g));
}
__device__ __forceinline__ void ldsm4(uint32_t* r, uint32_t addr) {
    asm volatile("ldmatrix.sync.aligned.m8n8.x4.shared.b16 {%0,%1,%2,%3}, [%4];"
                 : "=r"(r[0]), "=r"(r[1]), "=r"(r[2]), "=r"(r[3]) : "r"(addr));
}
__device__ __forceinline__ void ldsm4t(uint32_t* r, uint32_t addr) {
    asm volatile("ldmatrix.sync.aligned.m8n8.x4.trans.shared.b16 {%0,%1,%2,%3}, [%4];"
                 : "=r"(r[0]), "=r"(r[1]), "=r"(r[2]), "=r"(r[3]) : "r"(addr));
}
__device__ __forceinline__ void mma_hf(float* c,
                                       uint32_t a0, uint32_t a1, uint32_t a2, uint32_t a3,
                                       uint32_t b0, uint32_t b1) {
    asm volatile("mma.sync.aligned.m16n8k16.row.col.f32.f16.f16.f32 "
                 "{%0,%1,%2,%3}, {%4,%5,%6,%7}, {%8,%9}, {%0,%1,%2,%3};"
                 : "+f"(c[0]), "+f"(c[1]), "+f"(c[2]), "+f"(c[3])
                 : "r"(a0), "r"(a1), "r"(a2), "r"(a3), "r"(b0), "r"(b1));
}

// ============================================================================
// Setup: convert weights to fp16 globals
// ============================================================================
__global__ void setup_w(const float* __restrict__ f2w, const float* __restrict__ f3w,
                        const float* __restrict__ f4w, const float* __restrict__ f5w,
                        const float* __restrict__ V2z, const float* __restrict__ V3z)
{
    int i = blockIdx.x * blockDim.x + threadIdx.x;
    if (i < 65536) {
        const float* W = (i < 32768) ? ((i < 16384) ? f2w : f3w)
                                     : ((i < 49152) ? f4w : f5w);
        g_fWh[i] = __float2half_rn(W[i & 16383]);
    } else if (i < 73728) {
        int j = i - 65536;
        g_vWh[j] = __float2half_rn((j < 4096) ? V2z[j] : V3z[j - 4096]);
    }
}

// ============================================================================
// Kernel A: ICNN V + VJP — ALL activations/gradients in registers (fp16),
// smem holds only the two 64x64 W tiles. 8 MMA + 4 LDSM per kt.
// ============================================================================
constexpr int SZB = 144;
constexpr int VW  = 64 * SZB;                 // 9216
constexpr int V_W2H = 0, V_W3H = VW;
constexpr int V_MISC = 2 * VW;                // 18432
constexpr int SMEMV_BYTES = V_MISC + 704 * 4; // 21248

template<bool TR>
__device__ __forceinline__ void gemm64r(float (&acc)[8][4], const uint32_t (&AH)[4][4],
                                        uint32_t wHi)
{
    #pragma unroll
    for (int kt = 0; kt < 4; kt++) {
        #pragma unroll
        for (int p = 0; p < 4; p++) {
            uint32_t off = TR ? (uint32_t)(kt * 16 * SZB + p * 32)
                              : (uint32_t)(p * 16 * SZB + kt * 32);
            uint32_t bh[4];
            if (TR) ldsm4t(bh, wHi + off);
            else    ldsm4 (bh, wHi + off);
            mma_hf(acc[2 * p],     AH[kt][0], AH[kt][1], AH[kt][2], AH[kt][3], bh[0], bh[1]);
            mma_hf(acc[2 * p + 1], AH[kt][0], AH[kt][1], AH[kt][2], AH[kt][3], bh[2], bh[3]);
        }
    }
}

__global__ __launch_bounds__(256, 2)
void vnet_mma(const float* __restrict__ X,   const float* __restrict__ Xs,
              const float* __restrict__ Vl1, const float* __restrict__ V2x,
              const float* __restrict__ V3x, const float* __restrict__ Vfx,
              const float* __restrict__ Vfz, int n)
{
    extern __shared__ __align__(16) char smb[];
    float* mf   = (float*)(smb + V_MISC);
    float* sd   = mf;
    float* sVfz = mf + 256;
    float* sV2x = mf + 320;
    float* sV3x = mf + 448;
    float* sVl1 = mf + 576;

    const int t    = threadIdx.x;
    const int lane = t & 31;
    const int gid  = lane >> 2;
    const int tig  = lane & 3;
    const int r0   = (t >> 5) * 16;
    const int base = blockIdx.x * 128;
    const int rA = r0 + gid, rB = rA + 8;

    {
        int p = t >> 1, c = t & 1;
        int gi = base + p; if (gi >= n) gi = n - 1;
        sd[t] = X[gi * 2 + c] - Xs[gi * 2 + c];
    }
    if (t < 64)  sVfz[t] = Vfz[t];
    if (t < 128) { sV2x[t] = V2x[t]; sV3x[t] = V3x[t]; sVl1[t] = Vl1[t]; }
    for (int i = t; i < 512; i += 256) {
        int row = i >> 3, ch = (i & 7) * 8;
        *(uint4*)(smb + V_W2H + row * SZB + ch * 2) = *(const uint4*)(g_vWh + row * 64 + ch);
        *(uint4*)(smb + V_W3H + row * SZB + ch * 2) = *(const uint4*)(g_vWh + 4096 + row * 64 + ch);
    }
    __syncthreads();   // the only barrier

    const uint32_t su = smem_u32(smb);
    const uint32_t wf = (uint32_t)(((lane & 7) + ((lane >> 4) & 1) * 8) * SZB
                                   + ((lane >> 3) & 1) * 16);
    const uint32_t wt = (uint32_t)(((lane & 7) + ((lane >> 3) & 1) * 8) * SZB
                                   + ((lane >> 4) & 1) * 16);

    const float dA0 = sd[2 * rA], dA1 = sd[2 * rA + 1];
    const float dB0 = sd[2 * rB], dB1 = sd[2 * rB + 1];

    uint32_t AH[4][4];
    uint32_t Z2A[8], Z2B[8];
    float acc[8][4];

    // ---- z1 = sr(d @ Vl1^T) directly into fragments ----
    #pragma unroll
    for (int q = 0; q < 8; q++) {
        int c = 8 * q + 2 * tig;
        float v0 = sr(dA0 * sVl1[2 * c]     + dA1 * sVl1[2 * c + 1]);
        float v1 = sr(dA0 * sVl1[2 * c + 2] + dA1 * sVl1[2 * c + 3]);
        float v2 = sr(dB0 * sVl1[2 * c]     + dB1 * sVl1[2 * c + 1]);
        float v3 = sr(dB0 * sVl1[2 * c + 2] + dB1 * sVl1[2 * c + 3]);
        int kt = q >> 1, s = (q & 1) * 2;
        AH[kt][s]     = packhf(v0, v1);
        AH[kt][s + 1] = packhf(v2, v3);
    }

    // ---- z2 = sr(d@V2x^T + z1@V2z^T) ----
    #pragma unroll
    for (int q = 0; q < 8; q++) { acc[q][0] = acc[q][1] = acc[q][2] = acc[q][3] = 0.f; }
    gemm64r<false>(acc, AH, su + V_W2H + wf);
    #pragma unroll
    for (int q = 0; q < 8; q++) {
        int c = 8 * q + 2 * tig;
        float v0 = sr(acc[q][0] + dA0 * sV2x[2 * c]     + dA1 * sV2x[2 * c + 1]);
        float v1 = sr(acc[q][1] + dA0 * sV2x[2 * c + 2] + dA1 * sV2x[2 * c + 3]);
        float v2 = sr(acc[q][2] + dB0 * sV2x[2 * c]     + dB1 * sV2x[2 * c + 1]);
        float v3 = sr(acc[q][3] + dB0 * sV2x[2 * c + 2] + dB1 * sV2x[2 * c + 3]);
        int kt = q >> 1, s = (q & 1) * 2;
        Z2A[q] = packhf(v0, v1);
        Z2B[q] = packhf(v2, v3);
        AH[kt][s]     = Z2A[q];
        AH[kt][s + 1] = Z2B[q];
    }

    // ---- z3 = sr(d@V3x^T + z2@V3z^T); zf/gf/V; g3 -> fragments ----
    #pragma unroll
    for (int q = 0; q < 8; q++) { acc[q][0] = acc[q][1] = acc[q][2] = acc[q][3] = 0.f; }
    gemm64r<false>(acc, AH, su + V_W3H + wf);
    float zfA = 0.f, zfB = 0.f;
    #pragma unroll
    for (int q = 0; q < 8; q++) {
        int c = 8 * q + 2 * tig;
        acc[q][0] = sr(acc[q][0] + dA0 * sV3x[2 * c]     + dA1 * sV3x[2 * c + 1]);
        acc[q][1] = sr(acc[q][1] + dA0 * sV3x[2 * c + 2] + dA1 * sV3x[2 * c + 3]);
        acc[q][2] = sr(acc[q][2] + dB0 * sV3x[2 * c]     + dB1 * sV3x[2 * c + 1]);
        acc[q][3] = sr(acc[q][3] + dB0 * sV3x[2 * c + 2] + dB1 * sV3x[2 * c + 3]);
        zfA += sVfz[c] * acc[q][0] + sVfz[c + 1] * acc[q][1];
        zfB += sVfz[c] * acc[q][2] + sVfz[c + 1] * acc[q][3];
    }
    zfA += __shfl_xor_sync(0xFFFFFFFFu, zfA, 1);
    zfA += __shfl_xor_sync(0xFFFFFFFFu, zfA, 2);
    zfB += __shfl_xor_sync(0xFFFFFFFFu, zfB, 1);
    zfB += __shfl_xor_sync(0xFFFFFFFFu, zfB, 2);
    const float vfx0 = Vfx[0], vfx1 = Vfx[1];
    float afA = zfA + dA0 * vfx0 + dA1 * vfx1;
    float afB = zfB + dB0 * vfx0 + dB1 * vfx1;
    float zA = sr(afA), zB = sr(afB);
    float gfA = srp(zA) * srp(afA);
    float gfB = srp(zB) * srp(afB);
    if (tig == 0) {
        int gA = base + rA, gB = base + rB;
        if (gA < n) g_V[gA] = sr(zA) + TOLC * (dA0 * dA0 + dA1 * dA1);
        if (gB < n) g_V[gB] = sr(zB) + TOLC * (dB0 * dB0 + dB1 * dB1);
    }
    float gvA0 = 0.f, gvA1 = 0.f, gvB0 = 0.f, gvB1 = 0.f;
    #pragma unroll
    for (int q = 0; q < 8; q++) {
        int c = 8 * q + 2 * tig;
        float g0 = gfA * sVfz[c]     * srp_out(acc[q][0]);
        float g1 = gfA * sVfz[c + 1] * srp_out(acc[q][1]);
        float g2 = gfB * sVfz[c]     * srp_out(acc[q][2]);
        float g3 = gfB * sVfz[c + 1] * srp_out(acc[q][3]);
        gvA0 += g0 * sV3x[2 * c]     + g1 * sV3x[2 * c + 2];
        gvA1 += g0 * sV3x[2 * c + 1] + g1 * sV3x[2 * c + 3];
        gvB0 += g2 * sV3x[2 * c]     + g3 * sV3x[2 * c + 2];
        gvB1 += g2 * sV3x[2 * c + 1] + g3 * sV3x[2 * c + 3];
        int kt = q >> 1, s = (q & 1) * 2;
        AH[kt][s]     = packhf(g0, g1);
        AH[kt][s + 1] = packhf(g2, g3);
    }

    // ---- g2 = (g3 @ V3z) * srp_out(z2) ----
    #pragma unroll
    for (int q = 0; q < 8; q++) { acc[q][0] = acc[q][1] = acc[q][2] = acc[q][3] = 0.f; }
    gemm64r<true>(acc, AH, su + V_W3H + wt);
    #pragma unroll
    for (int q = 0; q < 8; q++) {
        int c = 8 * q + 2 * tig;
        float2 zAv = unpackhf(Z2A[q]);
        float2 zBv = unpackhf(Z2B[q]);
        float v0 = acc[q][0] * srp_out(zAv.x);
        float v1 = acc[q][1] * srp_out(zAv.y);
        float v2 = acc[q][2] * srp_out(zBv.x);
        float v3 = acc[q][3] * srp_out(zBv.y);
        gvA0 += v0 * sV2x[2 * c]     + v1 * sV2x[2 * c + 2];
        gvA1 += v0 * sV2x[2 * c + 1] + v1 * sV2x[2 * c + 3];
        gvB0 += v2 * sV2x[2 * c]     + v3 * sV2x[2 * c + 2];
        gvB1 += v2 * sV2x[2 * c + 1] + v3 * sV2x[2 * c + 3];
        int kt = q >> 1, s = (q & 1) * 2;
        AH[kt][s]     = packhf(v0, v1);
        AH[kt][s + 1] = packhf(v2, v3);
    }

    // ---- g1 = (g2 @ V2z) * srp(a1); fold into gradV ----
    #pragma unroll
    for (int q = 0; q < 8; q++) { acc[q][0] = acc[q][1] = acc[q][2] = acc[q][3] = 0.f; }
    gemm64r<true>(acc, AH, su + V_W2H + wt);
    #pragma unroll
    for (int q = 0; q < 8; q++) {
        int c = 8 * q + 2 * tig;
        float w00 = sVl1[2 * c],     w01 = sVl1[2 * c + 1];
        float w10 = sVl1[2 * c + 2], w11 = sVl1[2 * c + 3];
        float v0 = acc[q][0] * srp(dA0 * w00 + dA1 * w01);
        float v1 = acc[q][1] * srp(dA0 * w10 + dA1 * w11);
        float v2 = acc[q][2] * srp(dB0 * w00 + dB1 * w01);
        float v3 = acc[q][3] * srp(dB0 * w10 + dB1 * w11);
        gvA0 += v0 * w00 + v1 * w10;
        gvA1 += v0 * w01 + v1 * w11;
        gvB0 += v2 * w00 + v3 * w10;
        gvB1 += v2 * w01 + v3 * w11;
    }
    gvA0 += __shfl_xor_sync(0xFFFFFFFFu, gvA0, 1);
    gvA0 += __shfl_xor_sync(0xFFFFFFFFu, gvA0, 2);
    gvA1 += __shfl_xor_sync(0xFFFFFFFFu, gvA1, 1);
    gvA1 += __shfl_xor_sync(0xFFFFFFFFu, gvA1, 2);
    gvB0 += __shfl_xor_sync(0xFFFFFFFFu, gvB0, 1);
    gvB0 += __shfl_xor_sync(0xFFFFFFFFu, gvB0, 2);
    gvB1 += __shfl_xor_sync(0xFFFFFFFFu, gvB1, 1);
    gvB1 += __shfl_xor_sync(0xFFFFFFFFu, gvB1, 2);
    if (tig == 0) {
        int gA = base + rA, gB = base + rB;
        if (gA < n) {
            g_gradV[2 * gA]     = gvA0 + gfA * vfx0 + 2.f * TOLC * dA0;
            g_gradV[2 * gA + 1] = gvA1 + gfA * vfx1 + 2.f * TOLC * dA1;
        }
        if (gB < n) {
            g_gradV[2 * gB]     = gvB0 + gfB * vfx0 + 2.f * TOLC * dB0;
            g_gradV[2 * gB + 1] = gvB1 + gfB * vfx1 + 2.f * TOLC * dB1;
        }
    }
}

// ============================================================================
// Kernel B: f_hat MLP — A fp16 in registers, double-buffered fp16 W (round 15)
// ============================================================================
constexpr int TB = 256;
constexpr int ST = 136;
constexpr int WHI0    = 0;
constexpr int WHI1    = 34816;
constexpr int B_MISC  = 69632;
constexpr int SMEMB_BYTES = B_MISC + (256 + 512 + 258 + 384) * 4;   // 75272

__global__ __launch_bounds__(TB, 2)
void fhat_kernel(const float* __restrict__ X,
                 const float* __restrict__ f1w, const float* __restrict__ f1b,
                 const float* __restrict__ f2b, const float* __restrict__ f3b,
                 const float* __restrict__ f4b, const float* __restrict__ f5b,
                 const float* __restrict__ ffw, const float* __restrict__ ffb,
                 float* __restrict__ out, int n)
{
    extern __shared__ __align__(16) char smb[];
    float* mf  = (float*)(smb + B_MISC);
    float* sx  = mf;            // 256
    float* sb4 = mf + 256;      // 512
    float* sff = mf + 768;      // 258
    float* su_ = mf + 1026;     // 384: f1 staging, later sp0/sp1
    float* sp0 = su_;
    float* sp1 = su_ + 128;

    const int t    = threadIdx.x;
    const int lane = t & 31;
    const int gid  = lane >> 2;
    const int tig  = lane & 3;
    const int r0   = (t >> 5) * 16;
    const int base = blockIdx.x * 128;
    const int rA = r0 + gid, rB = rA + 8;

    const uint32_t suB  = smem_u32(smb);
    const uint32_t bOff = (uint32_t)(((lane & 7) + ((lane >> 4) & 1) * 8) * ST
                                     + ((lane >> 3) & 1) * 8) * 2;

    for (int i = t; i < 2048; i += TB) {
        int j = i >> 4, ch = (i & 15) * 8;
        cpa16(suB + WHI0 + (uint32_t)(j * ST * 2 + ch * 2), g_fWh + j * 128 + ch);
    }
    asm volatile("cp.async.commit_group;" ::: "memory");

    {
        int p = t >> 1, c = t & 1;
        int gi = base + p; if (gi >= n) gi = n - 1;
        sx[t] = X[gi * 2 + c];
    }
    for (int i = t; i < 258; i += TB) sff[i] = (i < 256) ? ffw[i] : ffb[i - 256];
    for (int i = t; i < 384; i += TB) su_[i] = (i < 256) ? f1w[i] : f1b[i - 256];
    {
        const float* Bs[4] = { f2b, f3b, f4b, f5b };
        for (int i = t; i < 512; i += TB) sb4[i] = Bs[i >> 7][i & 127];
    }
    __syncthreads();

    const float xA0 = sx[2 * rA], xA1 = sx[2 * rA + 1];
    const float xB0 = sx[2 * rB], xB1 = sx[2 * rB + 1];

    uint32_t AH[8][4];

    #pragma unroll
    for (int q = 0; q < 16; q++) {
        int c = 8 * q + 2 * tig;
        float w0 = su_[2 * c],     w1 = su_[2 * c + 1], b0 = su_[256 + c];
        float w2 = su_[2 * c + 2], w3 = su_[2 * c + 3], b1 = su_[256 + c + 1];
        float v0 = lrelu(xA0 * w0 + xA1 * w1 + b0);
        float v1 = lrelu(xA0 * w2 + xA1 * w3 + b1);
        float v2 = lrelu(xB0 * w0 + xB1 * w1 + b0);
        float v3 = lrelu(xB0 * w2 + xB1 * w3 + b1);
        int kt = q >> 1, s = (q & 1) * 2;
        AH[kt][s]     = packhf(v0, v1);
        AH[kt][s + 1] = packhf(v2, v3);
    }

    #pragma unroll 1
    for (int L = 0; L < 4; L++) {
        asm volatile("cp.async.wait_group 0;" ::: "memory");
        __syncthreads();

        if (L < 3) {
            const __half* WN = g_fWh + (L + 1) * 16384;
            const uint32_t dst = suB + ((L & 1) ? WHI0 : WHI1);
            for (int i = t; i < 2048; i += TB) {
                int j = i >> 4, ch = (i & 15) * 8;
                cpa16(dst + (uint32_t)(j * ST * 2 + ch * 2), WN + j * 128 + ch);
            }
            asm volatile("cp.async.commit_group;" ::: "memory");
        }

        const uint32_t wHiB = suB + ((L & 1) ? WHI1 : WHI0) + bOff;

        float acc[16][4];
        #pragma unroll
        for (int q = 0; q < 16; q++)
            #pragma unroll
            for (int c = 0; c < 4; c++) acc[q][c] = 0.f;

        #pragma unroll
        for (int kt = 0; kt < 8; kt++) {
            #pragma unroll
            for (int p = 0; p < 8; p++) {
                uint32_t bh[4];
                ldsm4(bh, wHiB + (uint32_t)(p * 16 * ST * 2) + kt * 32);
                mma_hf(acc[2 * p],     AH[kt][0], AH[kt][1], AH[kt][2], AH[kt][3], bh[0], bh[1]);
                mma_hf(acc[2 * p + 1], AH[kt][0], AH[kt][1], AH[kt][2], AH[kt][3], bh[2], bh[3]);
            }
        }

        const float* sb = sb4 + L * 128;
        if (L < 3) {
            #pragma unroll
            for (int q = 0; q < 16; q++) {
                int c = 8 * q + 2 * tig;
                float v0 = lrelu(acc[q][0] + sb[c]);
                float v1 = lrelu(acc[q][1] + sb[c + 1]);
                float v2 = lrelu(acc[q][2] + sb[c]);
                float v3 = lrelu(acc[q][3] + sb[c + 1]);
                int kt = q >> 1, s = (q & 1) * 2;
                AH[kt][s]     = packhf(v0, v1);
                AH[kt][s + 1] = packhf(v2, v3);
            }
        } else {
            float p0 = 0.f, p1 = 0.f, q0 = 0.f, q1 = 0.f;
            #pragma unroll
            for (int q = 0; q < 16; q++) {
                int c = 8 * q + 2 * tig;
                float v0 = lrelu(acc[q][0] + sb[c]);
                float v1 = lrelu(acc[q][1] + sb[c + 1]);
                float v2 = lrelu(acc[q][2] + sb[c]);
                float v3 = lrelu(acc[q][3] + sb[c + 1]);
                p0 = fmaf(v0, sff[c], fmaf(v1, sff[c + 1], p0));
                p1 = fmaf(v0, sff[128 + c], fmaf(v1, sff[129 + c], p1));
                q0 = fmaf(v2, sff[c], fmaf(v3, sff[c + 1], q0));
                q1 = fmaf(v2, sff[128 + c], fmaf(v3, sff[129 + c], q1));
            }
            #pragma unroll
            for (int m = 1; m < 4; m <<= 1) {
                p0 += __shfl_xor_sync(0xFFFFFFFFu, p0, m);
                p1 += __shfl_xor_sync(0xFFFFFFFFu, p1, m);
                q0 += __shfl_xor_sync(0xFFFFFFFFu, q0, m);
                q1 += __shfl_xor_sync(0xFFFFFFFFu, q1, m);
            }
            __syncthreads();
            if (tig == 0) {
                sp0[rA] = p0;  sp1[rA] = p1;
                sp0[rB] = q0;  sp1[rB] = q1;
            }
            __syncthreads();
        }
    }

    if (t < 128) {
        int gi = base + t;
        if (gi < n) {
            float fh0 = sff[256] + sp0[t];
            float fh1 = sff[257] + sp1[t];
            float g0 = g_gradV[2 * gi], g1 = g_gradV[2 * gi + 1];
            float V  = g_V[gi];
            float vn  = g0 * g0 + g1 * g1;
            float num = fh0 * g0 + fh1 * g1 + ALPHAC * V;
            float fm  = (num > 0.f ? num : 0.f) / (vn + EPSC);
            out[2 * gi]     = fh0 - g0 * fm;
            out[2 * gi + 1] = fh1 - g1 * fm;
        }
    }
}

// ============================================================================
extern "C" void kernel_launch(void* const* d_in, const int* in_sizes, int n_in,
                              void* d_out, int out_size)
{
    const float* X   = (const float*)d_in[0];
    const float* Xs  = (const float*)d_in[1];
    const float* Vl1 = (const float*)d_in[2];
    const float* V2x = (const float*)d_in[3];
    const float* V2z = (const float*)d_in[4];
    const float* V3x = (const float*)d_in[5];
    const float* V3z = (const float*)d_in[6];
    const float* Vfx = (const float*)d_in[7];
    const float* Vfz = (const float*)d_in[8];
    const float* f1w = (const float*)d_in[9];
    const float* f1b = (const float*)d_in[10];
    const float* f2w = (const float*)d_in[11];
    const float* f2b = (const float*)d_in[12];
    const float* f3w = (const float*)d_in[13];
    const float* f3b = (const float*)d_in[14];
    const float* f4w = (const float*)d_in[15];
    const float* f4b = (const float*)d_in[16];
    const float* f5w = (const float*)d_in[17];
    const float* f5b = (const float*)d_in[18];
    const float* ffw = (const float*)d_in[19];
    const float* ffb = (const float*)d_in[20];

    int n = in_sizes[0] / 2;
    int grid = (n + 127) / 128;

    cudaFuncSetAttribute(vnet_mma,    cudaFuncAttributeMaxDynamicSharedMemorySize, SMEMV_BYTES);
    cudaFuncSetAttribute(fhat_kernel, cudaFuncAttributeMaxDynamicSharedMemorySize, SMEMB_BYTES);

    setup_w<<<288, 256>>>(f2w, f3w, f4w, f5w, V2z, V3z);

    vnet_mma<<<grid, 256, SMEMV_BYTES>>>(X, Xs, Vl1, V2x, V3x, Vfx, Vfz, n);

    fhat_kernel<<<grid, TB, SMEMB_BYTES>>>(
        X, f1w, f1b, f2b, f3b, f4b, f5b, ffw, ffb, (float*)d_out, n);
}

// round 17
// speedup vs baseline: 4.6844x; 1.0292x over previous
#include <cuda_runtime.h>
#include <cuda_fp16.h>
#include <math.h>
#include <stdint.h>

#define TOLC   0.01f
#define ALPHAC 0.1f
#define SLOPEC 0.01f
#define EPSC   1e-10f

__device__ __half g_fWh[4 * 16384];   // f2..f5 fp16
__device__ __half g_vWh[8192];        // V2z,V3z fp16

__device__ __forceinline__ float sr(float x)  { return x < 0.f ? 0.f : (x < 1.f ? 0.5f * x * x : x - 0.5f); }
__device__ __forceinline__ float srp(float x) { return x < 0.f ? 0.f : (x < 1.f ? x : 1.f); }
__device__ __forceinline__ float srp_out(float z) { return z <= 0.f ? 0.f : (z < 0.5f ? sqrtf(2.f * z) : 1.f); }
__device__ __forceinline__ float lrelu(float x) { return x >= 0.f ? x : SLOPEC * x; }

__device__ __forceinline__ uint32_t packhf(float v0, float v1) {
    uint32_t r; asm("cvt.rn.f16x2.f32 %0, %1, %2;" : "=r"(r) : "f"(v1), "f"(v0)); return r;
}
__device__ __forceinline__ float2 unpackhf(uint32_t u) {
    __half2 h = *reinterpret_cast<__half2*>(&u);
    return __half22float2(h);
}
__device__ __forceinline__ uint32_t smem_u32(const void* p) {
    uint32_t a;
    asm("{ .reg .u64 t; cvta.to.shared.u64 t, %1; cvt.u32.u64 %0, t; }" : "=r"(a) : "l"(p));
    return a;
}
__device__ __forceinline__ void cpa16(uint32_t s, const void* g) {
    asm volatile("cp.async.cg.shared.global [%0], [%1], 16;" :: "r"(s), "l"(g));
}
__device__ __forceinline__ void ldsm4(uint32_t* r, uint32_t addr) {
    asm volatile("ldmatrix.sync.aligned.m8n8.x4.shared.b16 {%0,%1,%2,%3}, [%4];"
                 : "=r"(r[0]), "=r"(r[1]), "=r"(r[2]), "=r"(r[3]) : "r"(addr));
}
__device__ __forceinline__ void ldsm4t(uint32_t* r, uint32_t addr) {
    asm volatile("ldmatrix.sync.aligned.m8n8.x4.trans.shared.b16 {%0,%1,%2,%3}, [%4];"
                 : "=r"(r[0]), "=r"(r[1]), "=r"(r[2]), "=r"(r[3]) : "r"(addr));
}
__device__ __forceinline__ void mma_hf(float* c,
                                       uint32_t a0, uint32_t a1, uint32_t a2, uint32_t a3,
                                       uint32_t b0, uint32_t b1) {
    asm volatile("mma.sync.aligned.m16n8k16.row.col.f32.f16.f16.f32 "
                 "{%0,%1,%2,%3}, {%4,%5,%6,%7}, {%8,%9}, {%0,%1,%2,%3};"
                 : "+f"(c[0]), "+f"(c[1]), "+f"(c[2]), "+f"(c[3])
                 : "r"(a0), "r"(a1), "r"(a2), "r"(a3), "r"(b0), "r"(b1));
}

// ============================================================================
// Setup: convert weights to fp16 globals
// ============================================================================
__global__ void setup_w(const float* __restrict__ f2w, const float* __restrict__ f3w,
                        const float* __restrict__ f4w, const float* __restrict__ f5w,
                        const float* __restrict__ V2z, const float* __restrict__ V3z)
{
    int i = blockIdx.x * blockDim.x + threadIdx.x;
    if (i < 65536) {
        const float* W = (i < 32768) ? ((i < 16384) ? f2w : f3w)
                                     : ((i < 49152) ? f4w : f5w);
        g_fWh[i] = __float2half_rn(W[i & 16383]);
    } else if (i < 73728) {
        int j = i - 65536;
        g_vWh[j] = __float2half_rn((j < 4096) ? V2z[j] : V3z[j - 4096]);
    }
}

// ============================================================================
// Fused kernel: vnet (all-register, fp16 MMA) then fhat MLP (register A,
// double-buffered W), gradV/V handed over in smem. One CTA = 128 points.
// ============================================================================
constexpr int TB  = 256;
constexpr int ST  = 136;                      // fhat fp16 row stride (272 B)
constexpr int SZB = 144;                      // vnet W row stride bytes
constexpr int VW  = 64 * SZB;                 // 9216
constexpr int WHI0   = 0;                     // fhat W buf 0 (34816 B)
constexpr int WHI1   = 34816;                 // fhat W buf 1 / vnet W tiles
constexpr int V_W2H  = WHI1;                  // vnet W2 (9216)
constexpr int V_W3H  = WHI1 + VW;             // vnet W3 (9216)
constexpr int B_MISC = 69632;
// misc floats: sx[256] sd[256] sgv[256] sVv[128] sVfz[64] sV2x[128] sV3x[128]
//              sVl1[128] sb4[512] sff[258] su_[384]
constexpr int MF_SX  = 0,    MF_SD  = 256,  MF_SGV = 512,  MF_SVV = 768;
constexpr int MF_VFZ = 896,  MF_V2X = 960,  MF_V3X = 1088, MF_VL1 = 1216;
constexpr int MF_SB4 = 1344, MF_SFF = 1856, MF_SU  = 2114;
constexpr int MF_TOT = 2498;
constexpr int SMEM_BYTES = B_MISC + MF_TOT * 4;   // 79624 -> 2 CTAs/SM

__global__ __launch_bounds__(TB, 2)
void icnn_fused(const float* __restrict__ X,   const float* __restrict__ Xs,
                const float* __restrict__ Vl1, const float* __restrict__ V2x,
                const float* __restrict__ V3x, const float* __restrict__ Vfx,
                const float* __restrict__ Vfz,
                const float* __restrict__ f1w, const float* __restrict__ f1b,
                const float* __restrict__ f2b, const float* __restrict__ f3b,
                const float* __restrict__ f4b, const float* __restrict__ f5b,
                const float* __restrict__ ffw, const float* __restrict__ ffb,
                float* __restrict__ out, int n)
{
    extern __shared__ __align__(16) char smb[];
    float* mf   = (float*)(smb + B_MISC);
    float* sx   = mf + MF_SX;
    float* sd   = mf + MF_SD;
    float* sgv  = mf + MF_SGV;
    float* sVv  = mf + MF_SVV;
    float* sVfz = mf + MF_VFZ;
    float* sV2x = mf + MF_V2X;
    float* sV3x = mf + MF_V3X;
    float* sVl1 = mf + MF_VL1;
    float* sb4  = mf + MF_SB4;
    float* sff  = mf + MF_SFF;
    float* su_  = mf + MF_SU;
    float* sp0  = su_;
    float* sp1  = su_ + 128;

    const int t    = threadIdx.x;
    const int lane = t & 31;
    const int gid  = lane >> 2;
    const int tig  = lane & 3;
    const int r0   = (t >> 5) * 16;
    const int base = blockIdx.x * 128;
    const int rA = r0 + gid, rB = rA + 8;

    const uint32_t su = smem_u32(smb);

    // ---- prefetch fhat W0 FIRST: hides behind the whole vnet phase ----
    for (int i = t; i < 2048; i += TB) {
        int j = i >> 4, ch = (i & 15) * 8;
        cpa16(su + WHI0 + (uint32_t)(j * ST * 2 + ch * 2), g_fWh + j * 128 + ch);
    }
    asm volatile("cp.async.commit_group;" ::: "memory");

    // ---- stage everything ----
    {
        int p = t >> 1, c = t & 1;
        int gi = base + p; if (gi >= n) gi = n - 1;
        float xv = X[gi * 2 + c];
        sx[t] = xv;
        sd[t] = xv - Xs[gi * 2 + c];
    }
    if (t < 64)  sVfz[t] = Vfz[t];
    if (t < 128) { sV2x[t] = V2x[t]; sV3x[t] = V3x[t]; sVl1[t] = Vl1[t]; }
    for (int i = t; i < 512; i += TB) {
        int row = i >> 3, ch = (i & 7) * 8;
        *(uint4*)(smb + V_W2H + row * SZB + ch * 2) = *(const uint4*)(g_vWh + row * 64 + ch);
        *(uint4*)(smb + V_W3H + row * SZB + ch * 2) = *(const uint4*)(g_vWh + 4096 + row * 64 + ch);
    }
    for (int i = t; i < 258; i += TB) sff[i] = (i < 256) ? ffw[i] : ffb[i - 256];
    for (int i = t; i < 384; i += TB) su_[i] = (i < 256) ? f1w[i] : f1b[i - 256];
    {
        const float* Bs[4] = { f2b, f3b, f4b, f5b };
        for (int i = t; i < 512; i += TB) sb4[i] = Bs[i >> 7][i & 127];
    }
    __syncthreads();

    // ========================================================================
    // Phase 1: vnet (all-register fp16 MMA; warp-local)
    // ========================================================================
    {
        const uint32_t wf = (uint32_t)(((lane & 7) + ((lane >> 4) & 1) * 8) * SZB
                                       + ((lane >> 3) & 1) * 16);
        const uint32_t wt = (uint32_t)(((lane & 7) + ((lane >> 3) & 1) * 8) * SZB
                                       + ((lane >> 4) & 1) * 16);

        const float dA0 = sd[2 * rA], dA1 = sd[2 * rA + 1];
        const float dB0 = sd[2 * rB], dB1 = sd[2 * rB + 1];

        uint32_t AH[4][4];
        uint32_t Z2A[8], Z2B[8];
        float acc[8][4];

        #pragma unroll
        for (int q = 0; q < 8; q++) {
            int c = 8 * q + 2 * tig;
            float v0 = sr(dA0 * sVl1[2 * c]     + dA1 * sVl1[2 * c + 1]);
            float v1 = sr(dA0 * sVl1[2 * c + 2] + dA1 * sVl1[2 * c + 3]);
            float v2 = sr(dB0 * sVl1[2 * c]     + dB1 * sVl1[2 * c + 1]);
            float v3 = sr(dB0 * sVl1[2 * c + 2] + dB1 * sVl1[2 * c + 3]);
            int kt = q >> 1, s = (q & 1) * 2;
            AH[kt][s]     = packhf(v0, v1);
            AH[kt][s + 1] = packhf(v2, v3);
        }

        // z2
        #pragma unroll
        for (int q = 0; q < 8; q++) { acc[q][0] = acc[q][1] = acc[q][2] = acc[q][3] = 0.f; }
        #pragma unroll
        for (int kt = 0; kt < 4; kt++)
            #pragma unroll
            for (int p = 0; p < 4; p++) {
                uint32_t bh[4];
                ldsm4(bh, su + V_W2H + wf + (uint32_t)(p * 16 * SZB + kt * 32));
                mma_hf(acc[2 * p],     AH[kt][0], AH[kt][1], AH[kt][2], AH[kt][3], bh[0], bh[1]);
                mma_hf(acc[2 * p + 1], AH[kt][0], AH[kt][1], AH[kt][2], AH[kt][3], bh[2], bh[3]);
            }
        #pragma unroll
        for (int q = 0; q < 8; q++) {
            int c = 8 * q + 2 * tig;
            float v0 = sr(acc[q][0] + dA0 * sV2x[2 * c]     + dA1 * sV2x[2 * c + 1]);
            float v1 = sr(acc[q][1] + dA0 * sV2x[2 * c + 2] + dA1 * sV2x[2 * c + 3]);
            float v2 = sr(acc[q][2] + dB0 * sV2x[2 * c]     + dB1 * sV2x[2 * c + 1]);
            float v3 = sr(acc[q][3] + dB0 * sV2x[2 * c + 2] + dB1 * sV2x[2 * c + 3]);
            int kt = q >> 1, s = (q & 1) * 2;
            Z2A[q] = packhf(v0, v1);
            Z2B[q] = packhf(v2, v3);
            AH[kt][s]     = Z2A[q];
            AH[kt][s + 1] = Z2B[q];
        }

        // z3 + head
        #pragma unroll
        for (int q = 0; q < 8; q++) { acc[q][0] = acc[q][1] = acc[q][2] = acc[q][3] = 0.f; }
        #pragma unroll
        for (int kt = 0; kt < 4; kt++)
            #pragma unroll
            for (int p = 0; p < 4; p++) {
                uint32_t bh[4];
                ldsm4(bh, su + V_W3H + wf + (uint32_t)(p * 16 * SZB + kt * 32));
                mma_hf(acc[2 * p],     AH[kt][0], AH[kt][1], AH[kt][2], AH[kt][3], bh[0], bh[1]);
                mma_hf(acc[2 * p + 1], AH[kt][0], AH[kt][1], AH[kt][2], AH[kt][3], bh[2], bh[3]);
            }
        float zfA = 0.f, zfB = 0.f;
        #pragma unroll
        for (int q = 0; q < 8; q++) {
            int c = 8 * q + 2 * tig;
            acc[q][0] = sr(acc[q][0] + dA0 * sV3x[2 * c]     + dA1 * sV3x[2 * c + 1]);
            acc[q][1] = sr(acc[q][1] + dA0 * sV3x[2 * c + 2] + dA1 * sV3x[2 * c + 3]);
            acc[q][2] = sr(acc[q][2] + dB0 * sV3x[2 * c]     + dB1 * sV3x[2 * c + 1]);
            acc[q][3] = sr(acc[q][3] + dB0 * sV3x[2 * c + 2] + dB1 * sV3x[2 * c + 3]);
            zfA += sVfz[c] * acc[q][0] + sVfz[c + 1] * acc[q][1];
            zfB += sVfz[c] * acc[q][2] + sVfz[c + 1] * acc[q][3];
        }
        zfA += __shfl_xor_sync(0xFFFFFFFFu, zfA, 1);
        zfA += __shfl_xor_sync(0xFFFFFFFFu, zfA, 2);
        zfB += __shfl_xor_sync(0xFFFFFFFFu, zfB, 1);
        zfB += __shfl_xor_sync(0xFFFFFFFFu, zfB, 2);
        const float vfx0 = Vfx[0], vfx1 = Vfx[1];
        float afA = zfA + dA0 * vfx0 + dA1 * vfx1;
        float afB = zfB + dB0 * vfx0 + dB1 * vfx1;
        float zA = sr(afA), zB = sr(afB);
        float gfA = srp(zA) * srp(afA);
        float gfB = srp(zB) * srp(afB);
        if (tig == 0) {
            sVv[rA] = sr(zA) + TOLC * (dA0 * dA0 + dA1 * dA1);
            sVv[rB] = sr(zB) + TOLC * (dB0 * dB0 + dB1 * dB1);
        }
        float gvA0 = 0.f, gvA1 = 0.f, gvB0 = 0.f, gvB1 = 0.f;
        #pragma unroll
        for (int q = 0; q < 8; q++) {
            int c = 8 * q + 2 * tig;
            float g0 = gfA * sVfz[c]     * srp_out(acc[q][0]);
            float g1 = gfA * sVfz[c + 1] * srp_out(acc[q][1]);
            float g2 = gfB * sVfz[c]     * srp_out(acc[q][2]);
            float g3 = gfB * sVfz[c + 1] * srp_out(acc[q][3]);
            gvA0 += g0 * sV3x[2 * c]     + g1 * sV3x[2 * c + 2];
            gvA1 += g0 * sV3x[2 * c + 1] + g1 * sV3x[2 * c + 3];
            gvB0 += g2 * sV3x[2 * c]     + g3 * sV3x[2 * c + 2];
            gvB1 += g2 * sV3x[2 * c + 1] + g3 * sV3x[2 * c + 3];
            int kt = q >> 1, s = (q & 1) * 2;
            AH[kt][s]     = packhf(g0, g1);
            AH[kt][s + 1] = packhf(g2, g3);
        }

        // g2
        #pragma unroll
        for (int q = 0; q < 8; q++) { acc[q][0] = acc[q][1] = acc[q][2] = acc[q][3] = 0.f; }
        #pragma unroll
        for (int kt = 0; kt < 4; kt++)
            #pragma unroll
            for (int p = 0; p < 4; p++) {
                uint32_t bh[4];
                ldsm4t(bh, su + V_W3H + wt + (uint32_t)(kt * 16 * SZB + p * 32));
                mma_hf(acc[2 * p],     AH[kt][0], AH[kt][1], AH[kt][2], AH[kt][3], bh[0], bh[1]);
                mma_hf(acc[2 * p + 1], AH[kt][0], AH[kt][1], AH[kt][2], AH[kt][3], bh[2], bh[3]);
            }
        #pragma unroll
        for (int q = 0; q < 8; q++) {
            int c = 8 * q + 2 * tig;
            float2 zAv = unpackhf(Z2A[q]);
            float2 zBv = unpackhf(Z2B[q]);
            float v0 = acc[q][0] * srp_out(zAv.x);
            float v1 = acc[q][1] * srp_out(zAv.y);
            float v2 = acc[q][2] * srp_out(zBv.x);
            float v3 = acc[q][3] * srp_out(zBv.y);
            gvA0 += v0 * sV2x[2 * c]     + v1 * sV2x[2 * c + 2];
            gvA1 += v0 * sV2x[2 * c + 1] + v1 * sV2x[2 * c + 3];
            gvB0 += v2 * sV2x[2 * c]     + v3 * sV2x[2 * c + 2];
            gvB1 += v2 * sV2x[2 * c + 1] + v3 * sV2x[2 * c + 3];
            int kt = q >> 1, s = (q & 1) * 2;
            AH[kt][s]     = packhf(v0, v1);
            AH[kt][s + 1] = packhf(v2, v3);
        }

        // g1
        #pragma unroll
        for (int q = 0; q < 8; q++) { acc[q][0] = acc[q][1] = acc[q][2] = acc[q][3] = 0.f; }
        #pragma unroll
        for (int kt = 0; kt < 4; kt++)
            #pragma unroll
            for (int p = 0; p < 4; p++) {
                uint32_t bh[4];
                ldsm4t(bh, su + V_W2H + wt + (uint32_t)(kt * 16 * SZB + p * 32));
                mma_hf(acc[2 * p],     AH[kt][0], AH[kt][1], AH[kt][2], AH[kt][3], bh[0], bh[1]);
                mma_hf(acc[2 * p + 1], AH[kt][0], AH[kt][1], AH[kt][2], AH[kt][3], bh[2], bh[3]);
            }
        #pragma unroll
        for (int q = 0; q < 8; q++) {
            int c = 8 * q + 2 * tig;
            float w00 = sVl1[2 * c],     w01 = sVl1[2 * c + 1];
            float w10 = sVl1[2 * c + 2], w11 = sVl1[2 * c + 3];
            float v0 = acc[q][0] * srp(dA0 * w00 + dA1 * w01);
            float v1 = acc[q][1] * srp(dA0 * w10 + dA1 * w11);
            float v2 = acc[q][2] * srp(dB0 * w00 + dB1 * w01);
            float v3 = acc[q][3] * srp(dB0 * w10 + dB1 * w11);
            gvA0 += v0 * w00 + v1 * w10;
            gvA1 += v0 * w01 + v1 * w11;
            gvB0 += v2 * w00 + v3 * w10;
            gvB1 += v2 * w01 + v3 * w11;
        }
        gvA0 += __shfl_xor_sync(0xFFFFFFFFu, gvA0, 1);
        gvA0 += __shfl_xor_sync(0xFFFFFFFFu, gvA0, 2);
        gvA1 += __shfl_xor_sync(0xFFFFFFFFu, gvA1, 1);
        gvA1 += __shfl_xor_sync(0xFFFFFFFFu, gvA1, 2);
        gvB0 += __shfl_xor_sync(0xFFFFFFFFu, gvB0, 1);
        gvB0 += __shfl_xor_sync(0xFFFFFFFFu, gvB0, 2);
        gvB1 += __shfl_xor_sync(0xFFFFFFFFu, gvB1, 1);
        gvB1 += __shfl_xor_sync(0xFFFFFFFFu, gvB1, 2);
        if (tig == 0) {
            sgv[2 * rA] = gvA0 + gfA * vfx0 + 2.f * TOLC * dA0;
            sgv[2 * rA + 1] = gvA1 + gfA * vfx1 + 2.f * TOLC * dA1;
            sgv[2 * rB] = gvB0 + gfB * vfx0 + 2.f * TOLC * dB0;
            sgv[2 * rB + 1] = gvB1 + gfB * vfx1 + 2.f * TOLC * dB1;
        }
    }

    // ========================================================================
    // Phase 2: fhat MLP (register A, double-buffered W) + projection
    // ========================================================================
    const uint32_t bOff = (uint32_t)(((lane & 7) + ((lane >> 4) & 1) * 8) * ST
                                     + ((lane >> 3) & 1) * 8) * 2;

    const float xA0 = sx[2 * rA], xA1 = sx[2 * rA + 1];
    const float xB0 = sx[2 * rB], xB1 = sx[2 * rB + 1];

    uint32_t AH[8][4];

    #pragma unroll
    for (int q = 0; q < 16; q++) {
        int c = 8 * q + 2 * tig;
        float w0 = su_[2 * c],     w1 = su_[2 * c + 1], b0 = su_[256 + c];
        float w2 = su_[2 * c + 2], w3 = su_[2 * c + 3], b1 = su_[256 + c + 1];
        float v0 = lrelu(xA0 * w0 + xA1 * w1 + b0);
        float v1 = lrelu(xA0 * w2 + xA1 * w3 + b1);
        float v2 = lrelu(xB0 * w0 + xB1 * w1 + b0);
        float v3 = lrelu(xB0 * w2 + xB1 * w3 + b1);
        int kt = q >> 1, s = (q & 1) * 2;
        AH[kt][s]     = packhf(v0, v1);
        AH[kt][s + 1] = packhf(v2, v3);
    }

    #pragma unroll 1
    for (int L = 0; L < 4; L++) {
        asm volatile("cp.async.wait_group 0;" ::: "memory");
        __syncthreads();   // W_L visible; vnet W reads (L=0) / prior mainloop done

        if (L < 3) {
            const __half* WN = g_fWh + (L + 1) * 16384;
            const uint32_t dst = su + ((L & 1) ? WHI0 : WHI1);
            for (int i = t; i < 2048; i += TB) {
                int j = i >> 4, ch = (i & 15) * 8;
                cpa16(dst + (uint32_t)(j * ST * 2 + ch * 2), WN + j * 128 + ch);
            }
            asm volatile("cp.async.commit_group;" ::: "memory");
        }

        const uint32_t wHiB = su + ((L & 1) ? WHI1 : WHI0) + bOff;

        float acc[16][4];
        #pragma unroll
        for (int q = 0; q < 16; q++)
            #pragma unroll
            for (int c = 0; c < 4; c++) acc[q][c] = 0.f;

        #pragma unroll
        for (int kt = 0; kt < 8; kt++) {
            #pragma unroll
            for (int p = 0; p < 8; p++) {
                uint32_t bh[4];
                ldsm4(bh, wHiB + (uint32_t)(p * 16 * ST * 2) + kt * 32);
                mma_hf(acc[2 * p],     AH[kt][0], AH[kt][1], AH[kt][2], AH[kt][3], bh[0], bh[1]);
                mma_hf(acc[2 * p + 1], AH[kt][0], AH[kt][1], AH[kt][2], AH[kt][3], bh[2], bh[3]);
            }
        }

        const float* sb = sb4 + L * 128;
        if (L < 3) {
            #pragma unroll
            for (int q = 0; q < 16; q++) {
                int c = 8 * q + 2 * tig;
                float v0 = lrelu(acc[q][0] + sb[c]);
                float v1 = lrelu(acc[q][1] + sb[c + 1]);
                float v2 = lrelu(acc[q][2] + sb[c]);
                float v3 = lrelu(acc[q][3] + sb[c + 1]);
                int kt = q >> 1, s = (q & 1) * 2;
                AH[kt][s]     = packhf(v0, v1);
                AH[kt][s + 1] = packhf(v2, v3);
            }
        } else {
            float p0 = 0.f, p1 = 0.f, q0 = 0.f, q1 = 0.f;
            #pragma unroll
            for (int q = 0; q < 16; q++) {
                int c = 8 * q + 2 * tig;
                float v0 = lrelu(acc[q][0] + sb[c]);
                float v1 = lrelu(acc[q][1] + sb[c + 1]);
                float v2 = lrelu(acc[q][2] + sb[c]);
                float v3 = lrelu(acc[q][3] + sb[c + 1]);
                p0 = fmaf(v0, sff[c], fmaf(v1, sff[c + 1], p0));
                p1 = fmaf(v0, sff[128 + c], fmaf(v1, sff[129 + c], p1));
                q0 = fmaf(v2, sff[c], fmaf(v3, sff[c + 1], q0));
                q1 = fmaf(v2, sff[128 + c], fmaf(v3, sff[129 + c], q1));
            }
            #pragma unroll
            for (int m = 1; m < 4; m <<= 1) {
                p0 += __shfl_xor_sync(0xFFFFFFFFu, p0, m);
                p1 += __shfl_xor_sync(0xFFFFFFFFu, p1, m);
                q0 += __shfl_xor_sync(0xFFFFFFFFu, q0, m);
                q1 += __shfl_xor_sync(0xFFFFFFFFu, q1, m);
            }
            __syncthreads();   // f1 staging in su_ long dead -> sp0/sp1
            if (tig == 0) {
                sp0[rA] = p0;  sp1[rA] = p1;
                sp0[rB] = q0;  sp1[rB] = q1;
            }
            __syncthreads();
        }
    }

    // ---- projection (gradV/V from smem) ----
    if (t < 128) {
        int gi = base + t;
        if (gi < n) {
            float fh0 = sff[256] + sp0[t];
            float fh1 = sff[257] + sp1[t];
            float g0 = sgv[2 * t], g1 = sgv[2 * t + 1];
            float V  = sVv[t];
            float vn  = g0 * g0 + g1 * g1;
            float num = fh0 * g0 + fh1 * g1 + ALPHAC * V;
            float fm  = (num > 0.f ? num : 0.f) / (vn + EPSC);
            out[2 * gi]     = fh0 - g0 * fm;
            out[2 * gi + 1] = fh1 - g1 * fm;
        }
    }
}

// ============================================================================
extern "C" void kernel_launch(void* const* d_in, const int* in_sizes, int n_in,
                              void* d_out, int out_size)
{
    const float* X   = (const float*)d_in[0];
    const float* Xs  = (const float*)d_in[1];
    const float* Vl1 = (const float*)d_in[2];
    const float* V2x = (const float*)d_in[3];
    const float* V2z = (const float*)d_in[4];
    const float* V3x = (const float*)d_in[5];
    const float* V3z = (const float*)d_in[6];
    const float* Vfx = (const float*)d_in[7];
    const float* Vfz = (const float*)d_in[8];
    const float* f1w = (const float*)d_in[9];
    const float* f1b = (const float*)d_in[10];
    const float* f2w = (const float*)d_in[11];
    const float* f2b = (const float*)d_in[12];
    const float* f3w = (const float*)d_in[13];
    const float* f3b = (const float*)d_in[14];
    const float* f4w = (const float*)d_in[15];
    const float* f4b = (const float*)d_in[16];
    const float* f5w = (const float*)d_in[17];
    const float* f5b = (const float*)d_in[18];
    const float* ffw = (const float*)d_in[19];
    const float* ffb = (const float*)d_in[20];

    int n = in_sizes[0] / 2;
    int grid = (n + 127) / 128;

    cudaFuncSetAttribute(icnn_fused, cudaFuncAttributeMaxDynamicSharedMemorySize, SMEM_BYTES);

    setup_w<<<288, 256>>>(f2w, f3w, f4w, f5w, V2z, V3z);

    icnn_fused<<<grid, TB, SMEM_BYTES>>>(
        X, Xs, Vl1, V2x, V3x, Vfx, Vfz,
        f1w, f1b, f2b, f3b, f4b, f5b, ffw, ffb, (float*)d_out, n);
}